// round 2
// baseline (speedup 1.0000x reference)
#include <cuda_runtime.h>
#include <math.h>

#define NDIM 384
#define C 128
#define NN (NDIM*NDIM)
#define EPS 1e-5f

// Scratch (allocation-free rule: __device__ globals)
__device__ float g_at[(size_t)C * NN];   // a transposed: [c][k][j]
__device__ float g_bt[(size_t)C * NN];   // b transposed: [c][k][i]
__device__ float g_ct[(size_t)C * NN];   // contracted:   [c][i][j]
__device__ float g_gate[(size_t)NN * C]; // sigmoid(gate_o): [r][c]

__device__ __forceinline__ float sigmf(float x) { return 1.f / (1.f + __expf(-x)); }

// Load 128x128 row-major W into smem with row stride 132 (conflict-free, float4-aligned)
__device__ __forceinline__ void load_w(const float* __restrict__ W, float* w_s, int tid) {
#pragma unroll
    for (int it = 0; it < 16; it++) {
        int idx = (tid + it * 256) * 4;      // 0..65532
        int cc = idx >> 7, kk = idx & 127;
        *(float4*)(w_s + cc * 132 + kk) = *(const float4*)(W + idx);
    }
}

// 64x128 tile GEMM: acc[i][jj] = sum_k zn_s[row][k] * W[col][k]
// rows: ty*4+i, cols: tx + 16*jj
template <int ZS>
__device__ __forceinline__ void gemm_tile(const float* __restrict__ zn_s,
                                          const float* __restrict__ w_s,
                                          int tx, int ty, float (&acc)[4][8]) {
#pragma unroll
    for (int i = 0; i < 4; i++)
#pragma unroll
        for (int j = 0; j < 8; j++) acc[i][j] = 0.f;

#pragma unroll 4
    for (int k = 0; k < 128; k += 4) {
        float4 zv[4];
#pragma unroll
        for (int i = 0; i < 4; i++)
            zv[i] = *(const float4*)(zn_s + (ty * 4 + i) * ZS + k);
#pragma unroll
        for (int jj = 0; jj < 8; jj++) {
            float4 wv = *(const float4*)(w_s + (tx + 16 * jj) * 132 + k);
#pragma unroll
            for (int i = 0; i < 4; i++) {
                acc[i][jj] += zv[i].x * wv.x;
                acc[i][jj] += zv[i].y * wv.y;
                acc[i][jj] += zv[i].z * wv.z;
                acc[i][jj] += zv[i].w * wv.w;
            }
        }
    }
}

// combine proj*sigmoid(gate)*mask, transpose via smem, write channel-major
__device__ __forceinline__ void combine_store(
    float (&accP)[4][8], float (&accG)[4][8],
    const float* __restrict__ bp, const float* __restrict__ bg,
    const float* __restrict__ mask, float* tr, float* __restrict__ gout,
    int r0, int tx, int ty, int tid)
{
#pragma unroll
    for (int i = 0; i < 4; i++) {
        int rl = ty * 4 + i;
        float mv = mask[r0 + rl];
#pragma unroll
        for (int jj = 0; jj < 8; jj++) {
            int cc = tx + 16 * jj;
            float p = accP[i][jj] + bp[cc];
            float g = accG[i][jj] + bg[cc];
            tr[cc * 65 + rl] = p * sigmf(g) * mv;
        }
    }
    __syncthreads();
#pragma unroll
    for (int it = 0; it < 32; it++) {
        int idx = tid + it * 256;
        int cc = idx >> 6, rr = idx & 63;
        gout[cc * NN + r0 + rr] = tr[cc * 65 + rr];
    }
}

// Stage 2: fused LayerNorm + 5 linears (proj_a,gate_a,proj_b,gate_b,gate_o)
__global__ void __launch_bounds__(256) k_linear5(
    const float* __restrict__ z, const float* __restrict__ mask,
    const float* __restrict__ lnw, const float* __restrict__ lnb,
    const float* __restrict__ Wpa, const float* __restrict__ bpa,
    const float* __restrict__ Wga, const float* __restrict__ bga,
    const float* __restrict__ Wpb, const float* __restrict__ bpb,
    const float* __restrict__ Wgb, const float* __restrict__ bgb,
    const float* __restrict__ Wgo, const float* __restrict__ bgo)
{
    extern __shared__ float sm[];
    float* zn_s = sm;           // 64*128 = 8192 floats
    float* w_s = sm + 8192;     // 128*132 = 16896 floats (also reused as transpose buffer)
    int tid = threadIdx.x;
    int r0 = blockIdx.x * 64;

    { // load z tile
        const float4* zg = (const float4*)(z + (size_t)r0 * C);
        float4* zs = (float4*)zn_s;
#pragma unroll
        for (int it = 0; it < 8; it++) zs[tid + it * 256] = zg[tid + it * 256];
    }
    __syncthreads();

    { // layernorm in-place: warp per row
        int lane = tid & 31, wid = tid >> 5;
        float4 wv = ((const float4*)lnw)[lane];
        float4 bv = ((const float4*)lnb)[lane];
#pragma unroll
        for (int rr = 0; rr < 8; rr++) {
            int row = wid * 8 + rr;
            float4 v = *(float4*)(zn_s + row * C + lane * 4);
            float s1 = v.x + v.y + v.z + v.w;
            float s2 = v.x * v.x + v.y * v.y + v.z * v.z + v.w * v.w;
#pragma unroll
            for (int o = 16; o; o >>= 1) {
                s1 += __shfl_xor_sync(0xffffffffu, s1, o);
                s2 += __shfl_xor_sync(0xffffffffu, s2, o);
            }
            float m = s1 * (1.f / 128.f);
            float var = fmaxf(s2 * (1.f / 128.f) - m * m, 0.f);
            float rs = rsqrtf(var + EPS);
            v.x = (v.x - m) * rs * wv.x + bv.x;
            v.y = (v.y - m) * rs * wv.y + bv.y;
            v.z = (v.z - m) * rs * wv.z + bv.z;
            v.w = (v.w - m) * rs * wv.w + bv.w;
            *(float4*)(zn_s + row * C + lane * 4) = v;
        }
    }
    __syncthreads();

    int tx = tid & 15, ty = tid >> 4;
    float acc0[4][8], acc1[4][8];

    // a = proj_a * sigmoid(gate_a) * mask  -> g_at [c][r]
    load_w(Wpa, w_s, tid); __syncthreads();
    gemm_tile<128>(zn_s, w_s, tx, ty, acc0); __syncthreads();
    load_w(Wga, w_s, tid); __syncthreads();
    gemm_tile<128>(zn_s, w_s, tx, ty, acc1); __syncthreads();
    combine_store(acc0, acc1, bpa, bga, mask, w_s, g_at, r0, tx, ty, tid);
    __syncthreads();

    // b = proj_b * sigmoid(gate_b) * mask  -> g_bt [c][r]
    load_w(Wpb, w_s, tid); __syncthreads();
    gemm_tile<128>(zn_s, w_s, tx, ty, acc0); __syncthreads();
    load_w(Wgb, w_s, tid); __syncthreads();
    gemm_tile<128>(zn_s, w_s, tx, ty, acc1); __syncthreads();
    combine_store(acc0, acc1, bpb, bgb, mask, w_s, g_bt, r0, tx, ty, tid);
    __syncthreads();

    // gate = sigmoid(gate_o) -> g_gate [r][c]
    load_w(Wgo, w_s, tid); __syncthreads();
    gemm_tile<128>(zn_s, w_s, tx, ty, acc0);
#pragma unroll
    for (int i = 0; i < 4; i++) {
        int r = r0 + ty * 4 + i;
#pragma unroll
        for (int jj = 0; jj < 8; jj++) {
            int cc = tx + 16 * jj;
            g_gate[(size_t)r * C + cc] = sigmf(acc0[i][jj] + bgo[cc]);
        }
    }
}

// Stage 3: per-channel contraction ct[c] = bt[c]^T @ at[c]  (128x128 tile per block)
__global__ void __launch_bounds__(256) k_contract(const float* __restrict__ mask) {
    int tid = threadIdx.x;
    int b = blockIdx.x;
    int bj = b % 3, bi = (b / 3) % 3, c = b / 9;
    const float* __restrict__ A = g_at + c * NN;   // [k][j]
    const float* __restrict__ Bm = g_bt + c * NN;  // [k][i]
    __shared__ float as_[8 * 128];
    __shared__ float bs_[8 * 128];
    int tx = tid & 15, ty = tid >> 4;
    float acc[8][8];
#pragma unroll
    for (int i = 0; i < 8; i++)
#pragma unroll
        for (int j = 0; j < 8; j++) acc[i][j] = 0.f;

    int lrow = tid >> 5;            // 0..7
    int lcol = (tid & 31) * 4;      // 0..124
    int jbase = bj * 128, ibase = bi * 128;

    for (int k0 = 0; k0 < NDIM; k0 += 8) {
        float4 av = *(const float4*)(A + (k0 + lrow) * NDIM + jbase + lcol);
        float4 bv = *(const float4*)(Bm + (k0 + lrow) * NDIM + ibase + lcol);
        __syncthreads();
        *(float4*)(as_ + lrow * 128 + lcol) = av;
        *(float4*)(bs_ + lrow * 128 + lcol) = bv;
        __syncthreads();
#pragma unroll
        for (int kk = 0; kk < 8; kk++) {
            float4 a0 = *(const float4*)(as_ + kk * 128 + tx * 8);
            float4 a1 = *(const float4*)(as_ + kk * 128 + tx * 8 + 4);
            float4 b0 = *(const float4*)(bs_ + kk * 128 + ty * 8);
            float4 b1 = *(const float4*)(bs_ + kk * 128 + ty * 8 + 4);
            float aa[8] = {a0.x, a0.y, a0.z, a0.w, a1.x, a1.y, a1.z, a1.w};
            float bb[8] = {b0.x, b0.y, b0.z, b0.w, b1.x, b1.y, b1.z, b1.w};
#pragma unroll
            for (int ii = 0; ii < 8; ii++)
#pragma unroll
                for (int jj = 0; jj < 8; jj++) acc[ii][jj] += bb[ii] * aa[jj];
        }
    }

    float* __restrict__ O = g_ct + c * NN;
#pragma unroll
    for (int ii = 0; ii < 8; ii++) {
        int ig = ibase + ty * 8 + ii;
        const float* mrow = mask + ig * NDIM + jbase + tx * 8;
        float4 m0 = *(const float4*)(mrow);
        float4 m1 = *(const float4*)(mrow + 4);
        float4 o0 = make_float4(acc[ii][0] * m0.x, acc[ii][1] * m0.y,
                                acc[ii][2] * m0.z, acc[ii][3] * m0.w);
        float4 o1 = make_float4(acc[ii][4] * m1.x, acc[ii][5] * m1.y,
                                acc[ii][6] * m1.z, acc[ii][7] * m1.w);
        *(float4*)(O + ig * NDIM + jbase + tx * 8) = o0;
        *(float4*)(O + ig * NDIM + jbase + tx * 8 + 4) = o1;
    }
}

// Stage 4: transpose ct tile, LayerNorm, proj_o linear, multiply by gate
__global__ void __launch_bounds__(256) k_out(
    const float* __restrict__ lnw, const float* __restrict__ lnb,
    const float* __restrict__ Wo, const float* __restrict__ bo,
    float* __restrict__ out)
{
    extern __shared__ float sm[];
    float* cs = sm;             // 64*132 = 8448 floats
    float* w_s = sm + 8448;     // 128*132 = 16896 floats
    int tid = threadIdx.x;
    int r0 = blockIdx.x * 64;

    // transposed load: ct[c][r0+rr] -> cs[rr][c] (stride 132)
#pragma unroll
    for (int it = 0; it < 8; it++) {
        int idx = (tid + it * 256) * 4;
        int cc = idx >> 6, rr = idx & 63;
        float4 v = *(const float4*)(g_ct + cc * NN + r0 + rr);
        cs[(rr + 0) * 132 + cc] = v.x;
        cs[(rr + 1) * 132 + cc] = v.y;
        cs[(rr + 2) * 132 + cc] = v.z;
        cs[(rr + 3) * 132 + cc] = v.w;
    }
    __syncthreads();

    { // layernorm (ln_out)
        int lane = tid & 31, wid = tid >> 5;
        float4 wv = ((const float4*)lnw)[lane];
        float4 bv = ((const float4*)lnb)[lane];
#pragma unroll
        for (int rr = 0; rr < 8; rr++) {
            int row = wid * 8 + rr;
            float4 v = *(float4*)(cs + row * 132 + lane * 4);
            float s1 = v.x + v.y + v.z + v.w;
            float s2 = v.x * v.x + v.y * v.y + v.z * v.z + v.w * v.w;
#pragma unroll
            for (int o = 16; o; o >>= 1) {
                s1 += __shfl_xor_sync(0xffffffffu, s1, o);
                s2 += __shfl_xor_sync(0xffffffffu, s2, o);
            }
            float m = s1 * (1.f / 128.f);
            float var = fmaxf(s2 * (1.f / 128.f) - m * m, 0.f);
            float rs = rsqrtf(var + EPS);
            v.x = (v.x - m) * rs * wv.x + bv.x;
            v.y = (v.y - m) * rs * wv.y + bv.y;
            v.z = (v.z - m) * rs * wv.z + bv.z;
            v.w = (v.w - m) * rs * wv.w + bv.w;
            *(float4*)(cs + row * 132 + lane * 4) = v;
        }
    }
    __syncthreads();

    int tx = tid & 15, ty = tid >> 4;
    float acc[4][8];
    load_w(Wo, w_s, tid); __syncthreads();
    gemm_tile<132>(cs, w_s, tx, ty, acc);
#pragma unroll
    for (int i = 0; i < 4; i++) {
        int r = r0 + ty * 4 + i;
#pragma unroll
        for (int jj = 0; jj < 8; jj++) {
            int cc = tx + 16 * jj;
            out[(size_t)r * C + cc] = (acc[i][jj] + bo[cc]) * g_gate[(size_t)r * C + cc];
        }
    }
}

extern "C" void kernel_launch(void* const* d_in, const int* in_sizes, int n_in,
                              void* d_out, int out_size) {
    const float* z    = (const float*)d_in[0];
    const float* mask = (const float*)d_in[1];
    const float* lniw = (const float*)d_in[2];
    const float* lnib = (const float*)d_in[3];
    const float* lnow = (const float*)d_in[4];
    const float* lnob = (const float*)d_in[5];
    const float* Wpa  = (const float*)d_in[6];
    const float* bpa  = (const float*)d_in[7];
    const float* Wga  = (const float*)d_in[8];
    const float* bga  = (const float*)d_in[9];
    const float* Wpb  = (const float*)d_in[10];
    const float* bpb  = (const float*)d_in[11];
    const float* Wgb  = (const float*)d_in[12];
    const float* bgb  = (const float*)d_in[13];
    const float* Wgo  = (const float*)d_in[14];
    const float* bgo  = (const float*)d_in[15];
    const float* Wpo  = (const float*)d_in[16];
    const float* bpo  = (const float*)d_in[17];
    float* out = (float*)d_out;

    const int SMEM2 = (8192 + 16896) * 4;   // 100352 B
    const int SMEM4 = (8448 + 16896) * 4;   // 101376 B
    cudaFuncSetAttribute(k_linear5, cudaFuncAttributeMaxDynamicSharedMemorySize, SMEM2);
    cudaFuncSetAttribute(k_out, cudaFuncAttributeMaxDynamicSharedMemorySize, SMEM4);

    k_linear5<<<NN / 64, 256, SMEM2>>>(z, mask, lniw, lnib,
                                       Wpa, bpa, Wga, bga, Wpb, bpb, Wgb, bgb, Wgo, bgo);
    k_contract<<<9 * C, 256>>>(mask);
    k_out<<<NN / 64, 256, SMEM4>>>(lnow, lnob, Wpo, bpo, out);
}

// round 4
// speedup vs baseline: 1.4836x; 1.4836x over previous
#include <cuda_runtime.h>
#include <cuda_bf16.h>
#include <math.h>
#include <stdint.h>

#define NDIM 384
#define C 128
#define NN (NDIM*NDIM)
#define EPS 1e-5f

// Scratch (allocation-free rule: __device__ globals)
__device__ uint32_t g_a[(size_t)C * NN];   // a packed bf16 (hi|lo<<16): [c][k][j]
__device__ uint32_t g_b[(size_t)C * NN];   // b packed bf16: [c][k][i]
__device__ float    g_ct[(size_t)C * NN];  // contracted fp32: [c][i][j]
__device__ float    g_gate[(size_t)NN * C];// sigmoid(gate_o): [r][c]

__device__ __forceinline__ float sigmf(float x) { return 1.f / (1.f + __expf(-x)); }

__device__ __forceinline__ uint32_t smem_u32(const void* p) {
    uint32_t a;
    asm("{ .reg .u64 t; cvta.to.shared.u64 t, %1; cvt.u32.u64 %0, t; }" : "=r"(a) : "l"(p));
    return a;
}
__device__ __forceinline__ void ldsm4(uint32_t (&r)[4], uint32_t a) {
    asm volatile("ldmatrix.sync.aligned.m8n8.x4.shared.b16 {%0,%1,%2,%3}, [%4];"
                 : "=r"(r[0]), "=r"(r[1]), "=r"(r[2]), "=r"(r[3]) : "r"(a));
}
__device__ __forceinline__ void ldsm4t(uint32_t (&r)[4], uint32_t a) {
    asm volatile("ldmatrix.sync.aligned.m8n8.x4.trans.shared.b16 {%0,%1,%2,%3}, [%4];"
                 : "=r"(r[0]), "=r"(r[1]), "=r"(r[2]), "=r"(r[3]) : "r"(a));
}
__device__ __forceinline__ void mma16816(float (&c)[4], const uint32_t (&a)[4],
                                         uint32_t b0, uint32_t b1) {
    asm volatile("mma.sync.aligned.m16n8k16.row.col.f32.bf16.bf16.f32 "
                 "{%0,%1,%2,%3}, {%4,%5,%6,%7}, {%8,%9}, {%0,%1,%2,%3};"
                 : "+f"(c[0]), "+f"(c[1]), "+f"(c[2]), "+f"(c[3])
                 : "r"(a[0]), "r"(a[1]), "r"(a[2]), "r"(a[3]), "r"(b0), "r"(b1));
}

__device__ __forceinline__ uint32_t bfbits(float x) {
    __nv_bfloat16 h = __float2bfloat16(x);
    return (uint32_t)*(unsigned short*)&h;
}
__device__ __forceinline__ float bff(uint32_t b) {
    unsigned short s = (unsigned short)b;
    __nv_bfloat16 h = *(__nv_bfloat16*)&s;
    return __bfloat162float(h);
}
__device__ __forceinline__ float lopart(float x) { return x - bff(bfbits(x)); }
__device__ __forceinline__ uint32_t pack2h(float a, float b) {
    return bfbits(a) | (bfbits(b) << 16);
}
__device__ __forceinline__ uint32_t pack_hl(float v) {
    uint32_t hb = bfbits(v);
    return hb | (bfbits(v - bff(hb)) << 16);
}

// ===================== Stage 2: LN + 5 linears via mma.sync bf16x3 =====================
// smem byte offsets (half stride 136 per 128-wide row -> 272 B/row)
#define SMB_ZH  0
#define SMB_ZL  34816
#define SMB_WH0 69632
#define SMB_WL0 104448
#define SMB_WH1 139264
#define SMB_WL1 174080
#define SMB_TOT 208896

__device__ __forceinline__ void load_wpair(const float* __restrict__ W,
                                           char* hi, char* lo, int tid) {
#pragma unroll
    for (int it = 0; it < 16; it++) {
        int idx = (tid + it * 256) * 4;
        int n = idx >> 7, k = idx & 127;
        float4 v = *(const float4*)(W + idx);
        uint2 h = make_uint2(pack2h(v.x, v.y), pack2h(v.z, v.w));
        uint2 l = make_uint2(pack2h(lopart(v.x), lopart(v.y)),
                             pack2h(lopart(v.z), lopart(v.w)));
        *(uint2*)(hi + n * 272 + k * 2) = h;
        *(uint2*)(lo + n * 272 + k * 2) = l;
    }
}

// warp GEMM: rows w*16..+16 x cols 0..128, K=128, 3-pass bf16x3
__device__ __forceinline__ void wgemm(uint32_t Ah, uint32_t Al, uint32_t Bh, uint32_t Bl,
                                      uint32_t aoff, uint32_t boff, float (&acc)[16][4]) {
#pragma unroll
    for (int t = 0; t < 16; t++)
#pragma unroll
        for (int e = 0; e < 4; e++) acc[t][e] = 0.f;

    for (int pass = 0; pass < 3; pass++) {
        uint32_t Ab = ((pass == 2) ? Al : Ah) + aoff;
        uint32_t Bb = ((pass == 1) ? Bl : Bh) + boff;
#pragma unroll 2
        for (int ks = 0; ks < 8; ks++) {
            uint32_t a[4];
            ldsm4(a, Ab + ks * 32);
#pragma unroll
            for (int g = 0; g < 8; g++) {
                uint32_t b[4];
                ldsm4(b, Bb + g * 4352 + ks * 32);
                mma16816(acc[2 * g], a, b[0], b[2]);
                mma16816(acc[2 * g + 1], a, b[1], b[3]);
            }
        }
    }
}

__device__ __forceinline__ void store_ab(float (&P)[16][4], float (&G)[16][4],
                                         const float* __restrict__ bp,
                                         const float* __restrict__ bg,
                                         const float* __restrict__ mask,
                                         uint32_t* __restrict__ gout,
                                         int r0, int w, int lane) {
    int q = lane >> 2, m = lane & 3;
    int r1 = r0 + w * 16 + q, r2 = r1 + 8;
    float m1 = __ldg(mask + r1), m2 = __ldg(mask + r2);
#pragma unroll
    for (int t = 0; t < 16; t++) {
        int cc = t * 8 + 2 * m;
        float p0b = __ldg(bp + cc), p1b = __ldg(bp + cc + 1);
        float g0b = __ldg(bg + cc), g1b = __ldg(bg + cc + 1);
        gout[(size_t)cc * NN + r1]       = pack_hl((P[t][0] + p0b) * sigmf(G[t][0] + g0b) * m1);
        gout[(size_t)(cc + 1) * NN + r1] = pack_hl((P[t][1] + p1b) * sigmf(G[t][1] + g1b) * m1);
        gout[(size_t)cc * NN + r2]       = pack_hl((P[t][2] + p0b) * sigmf(G[t][2] + g0b) * m2);
        gout[(size_t)(cc + 1) * NN + r2] = pack_hl((P[t][3] + p1b) * sigmf(G[t][3] + g1b) * m2);
    }
}

__global__ void __launch_bounds__(256) k_lin5(
    const float* __restrict__ z, const float* __restrict__ mask,
    const float* __restrict__ lnw, const float* __restrict__ lnb,
    const float* __restrict__ Wpa, const float* __restrict__ bpa,
    const float* __restrict__ Wga, const float* __restrict__ bga,
    const float* __restrict__ Wpb, const float* __restrict__ bpb,
    const float* __restrict__ Wgb, const float* __restrict__ bgb,
    const float* __restrict__ Wgo, const float* __restrict__ bgo)
{
    extern __shared__ char sm[];
    uint32_t sb = smem_u32(sm);
    int tid = threadIdx.x, w = tid >> 5, lane = tid & 31;
    int r0 = blockIdx.x * 128;

    // LayerNorm -> bf16 hi/lo planes in smem
    {
        float4 wv = ((const float4*)lnw)[lane];
        float4 bv = ((const float4*)lnb)[lane];
#pragma unroll
        for (int rr = 0; rr < 16; rr++) {
            int row = w * 16 + rr;
            float4 v = *(const float4*)(z + (size_t)(r0 + row) * C + lane * 4);
            float s1 = v.x + v.y + v.z + v.w;
            float s2 = v.x * v.x + v.y * v.y + v.z * v.z + v.w * v.w;
#pragma unroll
            for (int o = 16; o; o >>= 1) {
                s1 += __shfl_xor_sync(0xffffffffu, s1, o);
                s2 += __shfl_xor_sync(0xffffffffu, s2, o);
            }
            float mn = s1 * (1.f / 128.f);
            float var = fmaxf(s2 * (1.f / 128.f) - mn * mn, 0.f);
            float rs = rsqrtf(var + EPS);
            v.x = (v.x - mn) * rs * wv.x + bv.x;
            v.y = (v.y - mn) * rs * wv.y + bv.y;
            v.z = (v.z - mn) * rs * wv.z + bv.z;
            v.w = (v.w - mn) * rs * wv.w + bv.w;
            *(uint2*)(sm + SMB_ZH + row * 272 + lane * 8) =
                make_uint2(pack2h(v.x, v.y), pack2h(v.z, v.w));
            *(uint2*)(sm + SMB_ZL + row * 272 + lane * 8) =
                make_uint2(pack2h(lopart(v.x), lopart(v.y)),
                           pack2h(lopart(v.z), lopart(v.w)));
        }
    }
    __syncthreads();

    uint32_t aoff = (uint32_t)(((w * 16 + (lane & 15)) * 136 + (lane >> 4) * 8) * 2);
    uint32_t boff = (uint32_t)(((lane & 15) * 136 + (lane >> 4) * 8) * 2);
    float accP[16][4], accG[16][4];

    // branch a
    load_wpair(Wpa, sm + SMB_WH0, sm + SMB_WL0, tid);
    load_wpair(Wga, sm + SMB_WH1, sm + SMB_WL1, tid);
    __syncthreads();
    wgemm(sb + SMB_ZH, sb + SMB_ZL, sb + SMB_WH0, sb + SMB_WL0, aoff, boff, accP);
    wgemm(sb + SMB_ZH, sb + SMB_ZL, sb + SMB_WH1, sb + SMB_WL1, aoff, boff, accG);
    store_ab(accP, accG, bpa, bga, mask, g_a, r0, w, lane);
    __syncthreads();

    // branch b
    load_wpair(Wpb, sm + SMB_WH0, sm + SMB_WL0, tid);
    load_wpair(Wgb, sm + SMB_WH1, sm + SMB_WL1, tid);
    __syncthreads();
    wgemm(sb + SMB_ZH, sb + SMB_ZL, sb + SMB_WH0, sb + SMB_WL0, aoff, boff, accP);
    wgemm(sb + SMB_ZH, sb + SMB_ZL, sb + SMB_WH1, sb + SMB_WL1, aoff, boff, accG);
    store_ab(accP, accG, bpb, bgb, mask, g_b, r0, w, lane);
    __syncthreads();

    // gate_o
    load_wpair(Wgo, sm + SMB_WH0, sm + SMB_WL0, tid);
    __syncthreads();
    wgemm(sb + SMB_ZH, sb + SMB_ZL, sb + SMB_WH0, sb + SMB_WL0, aoff, boff, accP);
    __syncthreads();                       // zn no longer needed
    {
        float* stg = (float*)sm;           // 128 x 132 staging in zn area
        int q = lane >> 2, m = lane & 3;
#pragma unroll
        for (int t = 0; t < 16; t++) {
            int cc = t * 8 + 2 * m;
            float b0 = __ldg(bgo + cc), b1 = __ldg(bgo + cc + 1);
            stg[(w * 16 + q) * 132 + cc]         = sigmf(accP[t][0] + b0);
            stg[(w * 16 + q) * 132 + cc + 1]     = sigmf(accP[t][1] + b1);
            stg[(w * 16 + q + 8) * 132 + cc]     = sigmf(accP[t][2] + b0);
            stg[(w * 16 + q + 8) * 132 + cc + 1] = sigmf(accP[t][3] + b1);
        }
        __syncthreads();
#pragma unroll
        for (int it = 0; it < 16; it++) {
            int idx = (tid + it * 256) * 4;
            int row = idx >> 7, cc = idx & 127;
            float4 v = *(float4*)(stg + row * 132 + cc);
            *(float4*)(g_gate + (size_t)(r0 + row) * C + cc) = v;
        }
    }
}

// ===================== Stage 3: contraction via mma.sync bf16x3 =====================
// smem planes (half stride 136): bh=0, bl=17408, ah=34816, al=52224; total 69632 B
#define CSM_TOT 69632

__global__ void __launch_bounds__(256) k_contract(const float* __restrict__ mask) {
    extern __shared__ char sm[];
    uint32_t sb = smem_u32(sm);
    int tid = threadIdx.x, w = tid >> 5, lane = tid & 31;
    int blk = blockIdx.x;
    int bj = blk % 3, bi = (blk / 3) % 3, ch = blk / 9;
    const uint32_t* __restrict__ Ag = g_b + (size_t)ch * NN;  // A operand (b): [k][i]
    const uint32_t* __restrict__ Bg = g_a + (size_t)ch * NN;  // B operand (a): [k][j]
    int ibase = bi * 128, jbase = bj * 128;

    float acc[16][4];
#pragma unroll
    for (int t = 0; t < 16; t++)
#pragma unroll
        for (int e = 0; e < 4; e++) acc[t][e] = 0.f;

    int kl = (lane & 7) + (lane >> 4) * 8;
    int cbit = ((lane >> 3) & 1) * 8;
    uint32_t aoff = (uint32_t)((kl * 136 + w * 16 + cbit) * 2);
    uint32_t boff = (uint32_t)((kl * 136 + cbit) * 2);

    for (int k0 = 0; k0 < NDIM; k0 += 64) {
        __syncthreads();
#pragma unroll
        for (int it = 0; it < 16; it++) {
            int t2 = tid + it * 256;        // 0..4095
            int row = t2 >> 6;              // 0..63
            int col2 = (t2 & 63) * 2;       // 0..126
            uint2 ua = *(const uint2*)(Ag + (size_t)(k0 + row) * NDIM + ibase + col2);
            uint2 ub = *(const uint2*)(Bg + (size_t)(k0 + row) * NDIM + jbase + col2);
            uint32_t off = row * 272 + col2 * 2;
            *(uint32_t*)(sm + 0     + off) = __byte_perm(ua.x, ua.y, 0x5410);
            *(uint32_t*)(sm + 17408 + off) = __byte_perm(ua.x, ua.y, 0x7632);
            *(uint32_t*)(sm + 34816 + off) = __byte_perm(ub.x, ub.y, 0x5410);
            *(uint32_t*)(sm + 52224 + off) = __byte_perm(ub.x, ub.y, 0x7632);
        }
        __syncthreads();
#pragma unroll
        for (int ks = 0; ks < 4; ks++) {
            uint32_t aH[4], aL[4];
            ldsm4t(aH, sb + 0     + aoff + ks * 4352);
            ldsm4t(aL, sb + 17408 + aoff + ks * 4352);
#pragma unroll
            for (int g = 0; g < 8; g++) {
                uint32_t bH[4], bL[4];
                uint32_t bo = boff + g * 32 + ks * 4352;
                ldsm4t(bH, sb + 34816 + bo);
                ldsm4t(bL, sb + 52224 + bo);
                mma16816(acc[2 * g],     aH, bH[0], bH[2]);
                mma16816(acc[2 * g + 1], aH, bH[1], bH[3]);
                mma16816(acc[2 * g],     aH, bL[0], bL[2]);
                mma16816(acc[2 * g + 1], aH, bL[1], bL[3]);
                mma16816(acc[2 * g],     aL, bH[0], bH[2]);
                mma16816(acc[2 * g + 1], aL, bH[1], bH[3]);
            }
        }
    }

    // epilogue: stage acc -> smem, masked coalesced store
    __syncthreads();
    float* stg = (float*)sm;   // 128 x 132 floats = 67584 B
    {
        int q = lane >> 2, m = lane & 3;
#pragma unroll
        for (int t = 0; t < 16; t++) {
            int cc = t * 8 + 2 * m;
            stg[(w * 16 + q) * 132 + cc]         = acc[t][0];
            stg[(w * 16 + q) * 132 + cc + 1]     = acc[t][1];
            stg[(w * 16 + q + 8) * 132 + cc]     = acc[t][2];
            stg[(w * 16 + q + 8) * 132 + cc + 1] = acc[t][3];
        }
    }
    __syncthreads();
#pragma unroll
    for (int it = 0; it < 16; it++) {
        int idx = (tid + it * 256) * 4;
        int row = idx >> 7, col = idx & 127;
        float4 v = *(float4*)(stg + row * 132 + col);
        int ig = ibase + row, jg = jbase + col;
        float4 mk = *(const float4*)(mask + (size_t)ig * NDIM + jg);
        v.x *= mk.x; v.y *= mk.y; v.z *= mk.z; v.w *= mk.w;
        *(float4*)(g_ct + (size_t)ch * NN + (size_t)ig * NDIM + jg) = v;
    }
}

// ===================== Stage 4: SIMT (unchanged) =====================
__device__ __forceinline__ void load_w(const float* __restrict__ W, float* w_s, int tid) {
#pragma unroll
    for (int it = 0; it < 16; it++) {
        int idx = (tid + it * 256) * 4;
        int cc = idx >> 7, kk = idx & 127;
        *(float4*)(w_s + cc * 132 + kk) = *(const float4*)(W + idx);
    }
}

template <int ZS>
__device__ __forceinline__ void gemm_tile(const float* __restrict__ zn_s,
                                          const float* __restrict__ w_s,
                                          int tx, int ty, float (&acc)[4][8]) {
#pragma unroll
    for (int i = 0; i < 4; i++)
#pragma unroll
        for (int j = 0; j < 8; j++) acc[i][j] = 0.f;

#pragma unroll 4
    for (int k = 0; k < 128; k += 4) {
        float4 zv[4];
#pragma unroll
        for (int i = 0; i < 4; i++)
            zv[i] = *(const float4*)(zn_s + (ty * 4 + i) * ZS + k);
#pragma unroll
        for (int jj = 0; jj < 8; jj++) {
            float4 wv = *(const float4*)(w_s + (tx + 16 * jj) * 132 + k);
#pragma unroll
            for (int i = 0; i < 4; i++) {
                acc[i][jj] += zv[i].x * wv.x;
                acc[i][jj] += zv[i].y * wv.y;
                acc[i][jj] += zv[i].z * wv.z;
                acc[i][jj] += zv[i].w * wv.w;
            }
        }
    }
}

__global__ void __launch_bounds__(256) k_out(
    const float* __restrict__ lnw, const float* __restrict__ lnb,
    const float* __restrict__ Wo, const float* __restrict__ bo,
    float* __restrict__ out)
{
    extern __shared__ float smf[];
    float* cs = smf;             // 64*132
    float* w_s = smf + 8448;     // 128*132
    int tid = threadIdx.x;
    int r0 = blockIdx.x * 64;

#pragma unroll
    for (int it = 0; it < 8; it++) {
        int idx = (tid + it * 256) * 4;
        int cc = idx >> 6, rr = idx & 63;
        float4 v = *(const float4*)(g_ct + (size_t)cc * NN + r0 + rr);
        cs[(rr + 0) * 132 + cc] = v.x;
        cs[(rr + 1) * 132 + cc] = v.y;
        cs[(rr + 2) * 132 + cc] = v.z;
        cs[(rr + 3) * 132 + cc] = v.w;
    }
    __syncthreads();

    {
        int lane = tid & 31, wid = tid >> 5;
        float4 wv = ((const float4*)lnw)[lane];
        float4 bv = ((const float4*)lnb)[lane];
#pragma unroll
        for (int rr = 0; rr < 8; rr++) {
            int row = wid * 8 + rr;
            float4 v = *(float4*)(cs + row * 132 + lane * 4);
            float s1 = v.x + v.y + v.z + v.w;
            float s2 = v.x * v.x + v.y * v.y + v.z * v.z + v.w * v.w;
#pragma unroll
            for (int o = 16; o; o >>= 1) {
                s1 += __shfl_xor_sync(0xffffffffu, s1, o);
                s2 += __shfl_xor_sync(0xffffffffu, s2, o);
            }
            float m = s1 * (1.f / 128.f);
            float var = fmaxf(s2 * (1.f / 128.f) - m * m, 0.f);
            float rs = rsqrtf(var + EPS);
            v.x = (v.x - m) * rs * wv.x + bv.x;
            v.y = (v.y - m) * rs * wv.y + bv.y;
            v.z = (v.z - m) * rs * wv.z + bv.z;
            v.w = (v.w - m) * rs * wv.w + bv.w;
            *(float4*)(cs + row * 132 + lane * 4) = v;
        }
    }
    __syncthreads();

    int tx = tid & 15, ty = tid >> 4;
    float acc[4][8];
    load_w(Wo, w_s, tid); __syncthreads();
    gemm_tile<132>(cs, w_s, tx, ty, acc);
#pragma unroll
    for (int i = 0; i < 4; i++) {
        int r = r0 + ty * 4 + i;
#pragma unroll
        for (int jj = 0; jj < 8; jj++) {
            int cc = tx + 16 * jj;
            out[(size_t)r * C + cc] = (acc[i][jj] + bo[cc]) * g_gate[(size_t)r * C + cc];
        }
    }
}

extern "C" void kernel_launch(void* const* d_in, const int* in_sizes, int n_in,
                              void* d_out, int out_size) {
    const float* z    = (const float*)d_in[0];
    const float* mask = (const float*)d_in[1];
    const float* lniw = (const float*)d_in[2];
    const float* lnib = (const float*)d_in[3];
    const float* lnow = (const float*)d_in[4];
    const float* lnob = (const float*)d_in[5];
    const float* Wpa  = (const float*)d_in[6];
    const float* bpa  = (const float*)d_in[7];
    const float* Wga  = (const float*)d_in[8];
    const float* bga  = (const float*)d_in[9];
    const float* Wpb  = (const float*)d_in[10];
    const float* bpb  = (const float*)d_in[11];
    const float* Wgb  = (const float*)d_in[12];
    const float* bgb  = (const float*)d_in[13];
    const float* Wgo  = (const float*)d_in[14];
    const float* bgo  = (const float*)d_in[15];
    const float* Wpo  = (const float*)d_in[16];
    const float* bpo  = (const float*)d_in[17];
    float* out = (float*)d_out;

    const int SMEM4 = (8448 + 16896) * 4;
    cudaFuncSetAttribute(k_lin5, cudaFuncAttributeMaxDynamicSharedMemorySize, SMB_TOT);
    cudaFuncSetAttribute(k_contract, cudaFuncAttributeMaxDynamicSharedMemorySize, CSM_TOT);
    cudaFuncSetAttribute(k_out, cudaFuncAttributeMaxDynamicSharedMemorySize, SMEM4);

    k_lin5<<<NN / 128, 256, SMB_TOT>>>(z, mask, lniw, lnib,
                                       Wpa, bpa, Wga, bga, Wpb, bpb, Wgb, bgb, Wgo, bgo);
    k_contract<<<9 * C, 256, CSM_TOT>>>(mask);
    k_out<<<NN / 64, 256, SMEM4>>>(lnow, lnob, Wpo, bpo, out);
}

// round 5
// speedup vs baseline: 1.8101x; 1.2201x over previous
#include <cuda_runtime.h>
#include <cuda_bf16.h>
#include <math.h>
#include <stdint.h>

#define NDIM 384
#define C 128
#define NN (NDIM*NDIM)
#define EPS 1e-5f

// Scratch (allocation-free rule: __device__ globals)
__device__ uint32_t g_a[(size_t)C * NN];   // a packed bf16 (hi|lo<<16): [c][k][j]
__device__ uint32_t g_b[(size_t)C * NN];   // b packed bf16: [c][k][i]
__device__ float    g_ct[(size_t)C * NN];  // contracted fp32: [c][i][j]
__device__ float    g_gate[(size_t)NN * C];// sigmoid(gate_o): [r][c]
// Precomputed weight bf16 hi/lo planes, in exact smem byte layout (136-half row stride).
// 6 weights x 2 planes x 17408 halves. Order: Wpa,Wga,Wpb,Wgb,Wgo,Wpo
__device__ unsigned short g_wpl[6 * 34816];

__device__ __forceinline__ float sigmf(float x) { return 1.f / (1.f + __expf(-x)); }

__device__ __forceinline__ uint32_t smem_u32(const void* p) {
    uint32_t a;
    asm("{ .reg .u64 t; cvta.to.shared.u64 t, %1; cvt.u32.u64 %0, t; }" : "=r"(a) : "l"(p));
    return a;
}
__device__ __forceinline__ void ldsm4(uint32_t (&r)[4], uint32_t a) {
    asm volatile("ldmatrix.sync.aligned.m8n8.x4.shared.b16 {%0,%1,%2,%3}, [%4];"
                 : "=r"(r[0]), "=r"(r[1]), "=r"(r[2]), "=r"(r[3]) : "r"(a));
}
__device__ __forceinline__ void ldsm4t(uint32_t (&r)[4], uint32_t a) {
    asm volatile("ldmatrix.sync.aligned.m8n8.x4.trans.shared.b16 {%0,%1,%2,%3}, [%4];"
                 : "=r"(r[0]), "=r"(r[1]), "=r"(r[2]), "=r"(r[3]) : "r"(a));
}
__device__ __forceinline__ void mma16816(float (&c)[4], const uint32_t (&a)[4],
                                         uint32_t b0, uint32_t b1) {
    asm volatile("mma.sync.aligned.m16n8k16.row.col.f32.bf16.bf16.f32 "
                 "{%0,%1,%2,%3}, {%4,%5,%6,%7}, {%8,%9}, {%0,%1,%2,%3};"
                 : "+f"(c[0]), "+f"(c[1]), "+f"(c[2]), "+f"(c[3])
                 : "r"(a[0]), "r"(a[1]), "r"(a[2]), "r"(a[3]), "r"(b0), "r"(b1));
}

__device__ __forceinline__ uint32_t bfbits(float x) {
    __nv_bfloat16 h = __float2bfloat16(x);
    return (uint32_t)*(unsigned short*)&h;
}
__device__ __forceinline__ float bff(uint32_t b) {
    unsigned short s = (unsigned short)b;
    __nv_bfloat16 h = *(__nv_bfloat16*)&s;
    return __bfloat162float(h);
}
__device__ __forceinline__ float lopart(float x) { return x - bff(bfbits(x)); }
__device__ __forceinline__ uint32_t pack2h(float a, float b) {
    return bfbits(a) | (bfbits(b) << 16);
}
__device__ __forceinline__ uint32_t pack_hl(float v) {
    uint32_t hb = bfbits(v);
    return hb | (bfbits(v - bff(hb)) << 16);
}

// ===================== k_prep: weight fp32 -> bf16 hi/lo planes =====================
__global__ void __launch_bounds__(256) k_prep(
    const float* __restrict__ W0, const float* __restrict__ W1,
    const float* __restrict__ W2, const float* __restrict__ W3,
    const float* __restrict__ W4, const float* __restrict__ W5)
{
    int gid = blockIdx.x * 256 + threadIdx.x;      // 6*16384 total
    int wsel = gid >> 14;
    int rem = gid & 16383;
    int n = rem >> 7, k = rem & 127;
    const float* W;
    switch (wsel) {
        case 0: W = W0; break;
        case 1: W = W1; break;
        case 2: W = W2; break;
        case 3: W = W3; break;
        case 4: W = W4; break;
        default: W = W5; break;
    }
    float v = W[n * 128 + k];
    uint32_t hb = bfbits(v);
    uint32_t lb = bfbits(v - bff(hb));
    size_t base = (size_t)wsel * 34816 + n * 136 + k;
    g_wpl[base] = (unsigned short)hb;
    g_wpl[base + 17408] = (unsigned short)lb;
}

// ===================== Stage 2: LN + 5 linears via mma.sync bf16x3 =====================
// smem byte offsets (half stride 136 per 128-wide row -> 272 B/row)
#define SMB_ZH  0
#define SMB_ZL  34816
#define SMB_WH0 69632
#define SMB_WL0 104448
#define SMB_WH1 139264
#define SMB_WL1 174080
#define SMB_TOT 208896

// copy one weight (hi+lo = 69632 B = 4352 uint4) from global planes to smem
__device__ __forceinline__ void copy_w(int wsel, void* dst, int tid) {
    const uint4* src = (const uint4*)(g_wpl + (size_t)wsel * 34816);
    uint4* d = (uint4*)dst;
    for (int i = tid; i < 4352; i += 512) d[i] = src[i];
}

// warp GEMM: 16 rows (rg) x 64 cols (chalf), K=128, 3-pass bf16x3
__device__ __forceinline__ void wgemm2(uint32_t Ah, uint32_t Al, uint32_t Bh, uint32_t Bl,
                                       uint32_t aoff, uint32_t boff, float (&acc)[8][4]) {
#pragma unroll
    for (int t = 0; t < 8; t++)
#pragma unroll
        for (int e = 0; e < 4; e++) acc[t][e] = 0.f;

    for (int pass = 0; pass < 3; pass++) {
        uint32_t Ab = ((pass == 2) ? Al : Ah) + aoff;
        uint32_t Bb = ((pass == 1) ? Bl : Bh) + boff;
#pragma unroll 2
        for (int ks = 0; ks < 8; ks++) {
            uint32_t a[4];
            ldsm4(a, Ab + ks * 32);
#pragma unroll
            for (int g = 0; g < 4; g++) {
                uint32_t b[4];
                ldsm4(b, Bb + g * 4352 + ks * 32);
                mma16816(acc[2 * g], a, b[0], b[2]);
                mma16816(acc[2 * g + 1], a, b[1], b[3]);
            }
        }
    }
}

// combine + transpose-stage + coalesced channel-major store (packed hi/lo)
__device__ __forceinline__ void store_ab2(float (&P)[8][4], float (&G)[8][4],
                                          const float* __restrict__ bp,
                                          const float* __restrict__ bg,
                                          const float* __restrict__ mask,
                                          uint32_t* stg, uint32_t* __restrict__ gout,
                                          int r0, int rg, int chalf, int lane, int tid)
{
    int q = lane >> 2, m = lane & 3;
    int rl1 = rg * 16 + q, rl2 = rl1 + 8;
    float m1 = __ldg(mask + r0 + rl1), m2 = __ldg(mask + r0 + rl2);
#pragma unroll
    for (int t = 0; t < 8; t++) {
        int cc = chalf * 64 + t * 8 + 2 * m;
        float p0 = __ldg(bp + cc), p1 = __ldg(bp + cc + 1);
        float g0 = __ldg(bg + cc), g1 = __ldg(bg + cc + 1);
        stg[cc * 132 + rl1]       = pack_hl((P[t][0] + p0) * sigmf(G[t][0] + g0) * m1);
        stg[(cc + 1) * 132 + rl1] = pack_hl((P[t][1] + p1) * sigmf(G[t][1] + g1) * m1);
        stg[cc * 132 + rl2]       = pack_hl((P[t][2] + p0) * sigmf(G[t][2] + g0) * m2);
        stg[(cc + 1) * 132 + rl2] = pack_hl((P[t][3] + p1) * sigmf(G[t][3] + g1) * m2);
    }
    __syncthreads();
#pragma unroll
    for (int it = 0; it < 8; it++) {
        int idx = (tid + it * 512) * 4;
        int c = idx >> 7, r = idx & 127;
        uint4 v = *(uint4*)(stg + c * 132 + r);
        *(uint4*)(gout + (size_t)c * NN + r0 + r) = v;
    }
}

__global__ void __launch_bounds__(512) k_lin5(
    const float* __restrict__ z, const float* __restrict__ mask,
    const float* __restrict__ lnw, const float* __restrict__ lnb,
    const float* __restrict__ bpa, const float* __restrict__ bga,
    const float* __restrict__ bpb, const float* __restrict__ bgb,
    const float* __restrict__ bgo)
{
    extern __shared__ char sm[];
    uint32_t sb = smem_u32(sm);
    int tid = threadIdx.x, w = tid >> 5, lane = tid & 31;
    int rg = w & 7, chalf = w >> 3;
    int r0 = blockIdx.x * 128;

    // LayerNorm -> bf16 hi/lo planes (warp handles 8 rows)
    {
        float4 wv = ((const float4*)lnw)[lane];
        float4 bv = ((const float4*)lnb)[lane];
#pragma unroll
        for (int rr = 0; rr < 8; rr++) {
            int row = w * 8 + rr;
            float4 v = *(const float4*)(z + (size_t)(r0 + row) * C + lane * 4);
            float s1 = v.x + v.y + v.z + v.w;
            float s2 = v.x * v.x + v.y * v.y + v.z * v.z + v.w * v.w;
#pragma unroll
            for (int o = 16; o; o >>= 1) {
                s1 += __shfl_xor_sync(0xffffffffu, s1, o);
                s2 += __shfl_xor_sync(0xffffffffu, s2, o);
            }
            float mn = s1 * (1.f / 128.f);
            float var = fmaxf(s2 * (1.f / 128.f) - mn * mn, 0.f);
            float rs = rsqrtf(var + EPS);
            v.x = (v.x - mn) * rs * wv.x + bv.x;
            v.y = (v.y - mn) * rs * wv.y + bv.y;
            v.z = (v.z - mn) * rs * wv.z + bv.z;
            v.w = (v.w - mn) * rs * wv.w + bv.w;
            *(uint2*)(sm + SMB_ZH + row * 272 + lane * 8) =
                make_uint2(pack2h(v.x, v.y), pack2h(v.z, v.w));
            *(uint2*)(sm + SMB_ZL + row * 272 + lane * 8) =
                make_uint2(pack2h(lopart(v.x), lopart(v.y)),
                           pack2h(lopart(v.z), lopart(v.w)));
        }
    }

    uint32_t aoff = (uint32_t)(((rg * 16 + (lane & 15)) * 136 + (lane >> 4) * 8) * 2);
    uint32_t boff = (uint32_t)(((chalf * 64 + (lane & 15)) * 136 + (lane >> 4) * 8) * 2);
    float P[8][4], G[8][4];

    // branch a
    copy_w(0, sm + SMB_WH0, tid);
    copy_w(1, sm + SMB_WH1, tid);
    __syncthreads();
    wgemm2(sb + SMB_ZH, sb + SMB_ZL, sb + SMB_WH0, sb + SMB_WL0, aoff, boff, P);
    wgemm2(sb + SMB_ZH, sb + SMB_ZL, sb + SMB_WH1, sb + SMB_WL1, aoff, boff, G);
    __syncthreads();
    store_ab2(P, G, bpa, bga, mask, (uint32_t*)(sm + SMB_WH0), g_a, r0, rg, chalf, lane, tid);
    __syncthreads();

    // branch b
    copy_w(2, sm + SMB_WH0, tid);
    copy_w(3, sm + SMB_WH1, tid);
    __syncthreads();
    wgemm2(sb + SMB_ZH, sb + SMB_ZL, sb + SMB_WH0, sb + SMB_WL0, aoff, boff, P);
    wgemm2(sb + SMB_ZH, sb + SMB_ZL, sb + SMB_WH1, sb + SMB_WL1, aoff, boff, G);
    __syncthreads();
    store_ab2(P, G, bpb, bgb, mask, (uint32_t*)(sm + SMB_WH0), g_b, r0, rg, chalf, lane, tid);
    __syncthreads();

    // gate_o
    copy_w(4, sm + SMB_WH0, tid);
    __syncthreads();
    wgemm2(sb + SMB_ZH, sb + SMB_ZL, sb + SMB_WH0, sb + SMB_WL0, aoff, boff, P);
    __syncthreads();
    {
        float* stgf = (float*)(sm + SMB_WH0);
        int q = lane >> 2, m = lane & 3;
#pragma unroll
        for (int t = 0; t < 8; t++) {
            int cc = chalf * 64 + t * 8 + 2 * m;
            float b0 = __ldg(bgo + cc), b1 = __ldg(bgo + cc + 1);
            stgf[(rg * 16 + q) * 132 + cc]         = sigmf(P[t][0] + b0);
            stgf[(rg * 16 + q) * 132 + cc + 1]     = sigmf(P[t][1] + b1);
            stgf[(rg * 16 + q + 8) * 132 + cc]     = sigmf(P[t][2] + b0);
            stgf[(rg * 16 + q + 8) * 132 + cc + 1] = sigmf(P[t][3] + b1);
        }
        __syncthreads();
#pragma unroll
        for (int it = 0; it < 8; it++) {
            int idx = (tid + it * 512) * 4;
            int row = idx >> 7, cc = idx & 127;
            float4 v = *(float4*)(stgf + row * 132 + cc);
            *(float4*)(g_gate + (size_t)(r0 + row) * C + cc) = v;
        }
    }
}

// ===================== Stage 3: contraction via mma.sync bf16x3 (unchanged) ==========
#define CSM_TOT 69632

__global__ void __launch_bounds__(256) k_contract(const float* __restrict__ mask) {
    extern __shared__ char sm[];
    uint32_t sb = smem_u32(sm);
    int tid = threadIdx.x, w = tid >> 5, lane = tid & 31;
    int blk = blockIdx.x;
    int bj = blk % 3, bi = (blk / 3) % 3, ch = blk / 9;
    const uint32_t* __restrict__ Ag = g_b + (size_t)ch * NN;  // [k][i]
    const uint32_t* __restrict__ Bg = g_a + (size_t)ch * NN;  // [k][j]
    int ibase = bi * 128, jbase = bj * 128;

    float acc[16][4];
#pragma unroll
    for (int t = 0; t < 16; t++)
#pragma unroll
        for (int e = 0; e < 4; e++) acc[t][e] = 0.f;

    int kl = (lane & 7) + (lane >> 4) * 8;
    int cbit = ((lane >> 3) & 1) * 8;
    uint32_t aoff = (uint32_t)((kl * 136 + w * 16 + cbit) * 2);
    uint32_t boff = (uint32_t)((kl * 136 + cbit) * 2);

    for (int k0 = 0; k0 < NDIM; k0 += 64) {
        __syncthreads();
#pragma unroll
        for (int it = 0; it < 16; it++) {
            int t2 = tid + it * 256;
            int row = t2 >> 6;
            int col2 = (t2 & 63) * 2;
            uint2 ua = *(const uint2*)(Ag + (size_t)(k0 + row) * NDIM + ibase + col2);
            uint2 ub = *(const uint2*)(Bg + (size_t)(k0 + row) * NDIM + jbase + col2);
            uint32_t off = row * 272 + col2 * 2;
            *(uint32_t*)(sm + 0     + off) = __byte_perm(ua.x, ua.y, 0x5410);
            *(uint32_t*)(sm + 17408 + off) = __byte_perm(ua.x, ua.y, 0x7632);
            *(uint32_t*)(sm + 34816 + off) = __byte_perm(ub.x, ub.y, 0x5410);
            *(uint32_t*)(sm + 52224 + off) = __byte_perm(ub.x, ub.y, 0x7632);
        }
        __syncthreads();
#pragma unroll
        for (int ks = 0; ks < 4; ks++) {
            uint32_t aH[4], aL[4];
            ldsm4t(aH, sb + 0     + aoff + ks * 4352);
            ldsm4t(aL, sb + 17408 + aoff + ks * 4352);
#pragma unroll
            for (int g = 0; g < 8; g++) {
                uint32_t bH[4], bL[4];
                uint32_t bo = boff + g * 32 + ks * 4352;
                ldsm4t(bH, sb + 34816 + bo);
                ldsm4t(bL, sb + 52224 + bo);
                mma16816(acc[2 * g],     aH, bH[0], bH[2]);
                mma16816(acc[2 * g + 1], aH, bH[1], bH[3]);
                mma16816(acc[2 * g],     aH, bL[0], bL[2]);
                mma16816(acc[2 * g + 1], aH, bL[1], bL[3]);
                mma16816(acc[2 * g],     aL, bH[0], bH[2]);
                mma16816(acc[2 * g + 1], aL, bH[1], bH[3]);
            }
        }
    }

    __syncthreads();
    float* stg = (float*)sm;   // 128 x 132 floats
    {
        int q = lane >> 2, m = lane & 3;
#pragma unroll
        for (int t = 0; t < 16; t++) {
            int cc = t * 8 + 2 * m;
            stg[(w * 16 + q) * 132 + cc]         = acc[t][0];
            stg[(w * 16 + q) * 132 + cc + 1]     = acc[t][1];
            stg[(w * 16 + q + 8) * 132 + cc]     = acc[t][2];
            stg[(w * 16 + q + 8) * 132 + cc + 1] = acc[t][3];
        }
    }
    __syncthreads();
#pragma unroll
    for (int it = 0; it < 16; it++) {
        int idx = (tid + it * 256) * 4;
        int row = idx >> 7, col = idx & 127;
        float4 v = *(float4*)(stg + row * 132 + col);
        int ig = ibase + row, jg = jbase + col;
        float4 mk = *(const float4*)(mask + (size_t)ig * NDIM + jg);
        v.x *= mk.x; v.y *= mk.y; v.z *= mk.z; v.w *= mk.w;
        *(float4*)(g_ct + (size_t)ch * NN + (size_t)ig * NDIM + jg) = v;
    }
}

// ===================== Stage 4: transpose + LN + proj_o (mma) + gate =====================
#define KO_STG 0
#define KO_ZH  67584
#define KO_ZL  102400
#define KO_WH  137216
#define KO_WL  172032
#define KO_TOT 206848

__global__ void __launch_bounds__(512) k_out(
    const float* __restrict__ lnw, const float* __restrict__ lnb,
    const float* __restrict__ bo, float* __restrict__ out)
{
    extern __shared__ char sm[];
    uint32_t sb = smem_u32(sm);
    int tid = threadIdx.x, w = tid >> 5, lane = tid & 31;
    int rg = w & 7, chalf = w >> 3;
    int r0 = blockIdx.x * 128;
    float* stg = (float*)(sm + KO_STG);

    // weights (Wpo = plane 5)
    copy_w(5, sm + KO_WH, tid);

    // transposed load of g_ct with per-row channel rotation (rot = r & 124)
#pragma unroll
    for (int it = 0; it < 8; it++) {
        int linear = tid + it * 512;
        int c = linear >> 5;
        int r = (linear & 31) * 4;
        float4 v = *(const float4*)(g_ct + (size_t)c * NN + r0 + r);
        stg[(r + 0) * 132 + ((c + ((r + 0) & 124)) & 127)] = v.x;
        stg[(r + 1) * 132 + ((c + ((r + 1) & 124)) & 127)] = v.y;
        stg[(r + 2) * 132 + ((c + ((r + 2) & 124)) & 127)] = v.z;
        stg[(r + 3) * 132 + ((c + ((r + 3) & 124)) & 127)] = v.w;
    }
    __syncthreads();

    // LayerNorm rows (8 per warp) -> bf16 hi/lo planes
    {
        float4 wv = ((const float4*)lnw)[lane];
        float4 bv = ((const float4*)lnb)[lane];
#pragma unroll
        for (int rr = 0; rr < 8; rr++) {
            int row = w * 8 + rr;
            int pos = (lane * 4 + (row & 124)) & 127;
            float4 v = *(float4*)(stg + row * 132 + pos);
            float s1 = v.x + v.y + v.z + v.w;
            float s2 = v.x * v.x + v.y * v.y + v.z * v.z + v.w * v.w;
#pragma unroll
            for (int o = 16; o; o >>= 1) {
                s1 += __shfl_xor_sync(0xffffffffu, s1, o);
                s2 += __shfl_xor_sync(0xffffffffu, s2, o);
            }
            float mn = s1 * (1.f / 128.f);
            float var = fmaxf(s2 * (1.f / 128.f) - mn * mn, 0.f);
            float rs = rsqrtf(var + EPS);
            v.x = (v.x - mn) * rs * wv.x + bv.x;
            v.y = (v.y - mn) * rs * wv.y + bv.y;
            v.z = (v.z - mn) * rs * wv.z + bv.z;
            v.w = (v.w - mn) * rs * wv.w + bv.w;
            *(uint2*)(sm + KO_ZH + row * 272 + lane * 8) =
                make_uint2(pack2h(v.x, v.y), pack2h(v.z, v.w));
            *(uint2*)(sm + KO_ZL + row * 272 + lane * 8) =
                make_uint2(pack2h(lopart(v.x), lopart(v.y)),
                           pack2h(lopart(v.z), lopart(v.w)));
        }
    }
    __syncthreads();

    uint32_t aoff = (uint32_t)(((rg * 16 + (lane & 15)) * 136 + (lane >> 4) * 8) * 2);
    uint32_t boff = (uint32_t)(((chalf * 64 + (lane & 15)) * 136 + (lane >> 4) * 8) * 2);
    float P[8][4];
    wgemm2(sb + KO_ZH, sb + KO_ZL, sb + KO_WH, sb + KO_WL, aoff, boff, P);
    __syncthreads();

    // epilogue: bias + gate, stage, coalesced store
    {
        int q = lane >> 2, m = lane & 3;
        int rl1 = rg * 16 + q, rl2 = rl1 + 8;
#pragma unroll
        for (int t = 0; t < 8; t++) {
            int cc = chalf * 64 + t * 8 + 2 * m;
            float b0 = __ldg(bo + cc), b1 = __ldg(bo + cc + 1);
            stg[rl1 * 132 + cc]     = (P[t][0] + b0) * g_gate[(size_t)(r0 + rl1) * C + cc];
            stg[rl1 * 132 + cc + 1] = (P[t][1] + b1) * g_gate[(size_t)(r0 + rl1) * C + cc + 1];
            stg[rl2 * 132 + cc]     = (P[t][2] + b0) * g_gate[(size_t)(r0 + rl2) * C + cc];
            stg[rl2 * 132 + cc + 1] = (P[t][3] + b1) * g_gate[(size_t)(r0 + rl2) * C + cc + 1];
        }
    }
    __syncthreads();
#pragma unroll
    for (int it = 0; it < 8; it++) {
        int idx = (tid + it * 512) * 4;
        int row = idx >> 7, cc = idx & 127;
        float4 v = *(float4*)(stg + row * 132 + cc);
        *(float4*)(out + (size_t)(r0 + row) * C + cc) = v;
    }
}

extern "C" void kernel_launch(void* const* d_in, const int* in_sizes, int n_in,
                              void* d_out, int out_size) {
    const float* z    = (const float*)d_in[0];
    const float* mask = (const float*)d_in[1];
    const float* lniw = (const float*)d_in[2];
    const float* lnib = (const float*)d_in[3];
    const float* lnow = (const float*)d_in[4];
    const float* lnob = (const float*)d_in[5];
    const float* Wpa  = (const float*)d_in[6];
    const float* bpa  = (const float*)d_in[7];
    const float* Wga  = (const float*)d_in[8];
    const float* bga  = (const float*)d_in[9];
    const float* Wpb  = (const float*)d_in[10];
    const float* bpb  = (const float*)d_in[11];
    const float* Wgb  = (const float*)d_in[12];
    const float* bgb  = (const float*)d_in[13];
    const float* Wgo  = (const float*)d_in[14];
    const float* bgo  = (const float*)d_in[15];
    const float* Wpo  = (const float*)d_in[16];
    const float* bpo  = (const float*)d_in[17];
    float* out = (float*)d_out;

    cudaFuncSetAttribute(k_lin5, cudaFuncAttributeMaxDynamicSharedMemorySize, SMB_TOT);
    cudaFuncSetAttribute(k_contract, cudaFuncAttributeMaxDynamicSharedMemorySize, CSM_TOT);
    cudaFuncSetAttribute(k_out, cudaFuncAttributeMaxDynamicSharedMemorySize, KO_TOT);

    k_prep<<<384, 256>>>(Wpa, Wga, Wpb, Wgb, Wgo, Wpo);
    k_lin5<<<NN / 128, 512, SMB_TOT>>>(z, mask, lniw, lnib, bpa, bga, bpb, bgb, bgo);
    k_contract<<<9 * C, 256, CSM_TOT>>>(mask);
    k_out<<<NN / 128, 512, KO_TOT>>>(lnow, lnob, bpo, out);
}

// round 6
// speedup vs baseline: 1.8162x; 1.0033x over previous
#include <cuda_runtime.h>
#include <cuda_bf16.h>
#include <math.h>
#include <stdint.h>

#define NDIM 384
#define C 128
#define NN (NDIM*NDIM)
#define EPS 1e-5f

// Scratch (allocation-free rule: __device__ globals)
__device__ uint32_t g_a[(size_t)C * NN];   // a packed bf16 (hi|lo<<16): [c][k][j]
__device__ uint32_t g_b[(size_t)C * NN];   // b packed bf16: [c][k][i]
__device__ float    g_ct[(size_t)C * NN];  // contracted fp32: [c][i][j]
__device__ float    g_gate[(size_t)NN * C];// sigmoid(gate_o): [r][c]
// Precomputed weight bf16 hi/lo planes (136-half row stride). Order: Wpa,Wga,Wpb,Wgb,Wgo,Wpo
__device__ unsigned short g_wpl[6 * 34816];

__device__ __forceinline__ float sigmf(float x) { return 1.f / (1.f + __expf(-x)); }

__device__ __forceinline__ uint32_t smem_u32(const void* p) {
    uint32_t a;
    asm("{ .reg .u64 t; cvta.to.shared.u64 t, %1; cvt.u32.u64 %0, t; }" : "=r"(a) : "l"(p));
    return a;
}
__device__ __forceinline__ void ldsm4(uint32_t (&r)[4], uint32_t a) {
    asm volatile("ldmatrix.sync.aligned.m8n8.x4.shared.b16 {%0,%1,%2,%3}, [%4];"
                 : "=r"(r[0]), "=r"(r[1]), "=r"(r[2]), "=r"(r[3]) : "r"(a));
}
__device__ __forceinline__ void ldsm4t(uint32_t (&r)[4], uint32_t a) {
    asm volatile("ldmatrix.sync.aligned.m8n8.x4.trans.shared.b16 {%0,%1,%2,%3}, [%4];"
                 : "=r"(r[0]), "=r"(r[1]), "=r"(r[2]), "=r"(r[3]) : "r"(a));
}
__device__ __forceinline__ void mma16816(float (&c)[4], const uint32_t (&a)[4],
                                         uint32_t b0, uint32_t b1) {
    asm volatile("mma.sync.aligned.m16n8k16.row.col.f32.bf16.bf16.f32 "
                 "{%0,%1,%2,%3}, {%4,%5,%6,%7}, {%8,%9}, {%0,%1,%2,%3};"
                 : "+f"(c[0]), "+f"(c[1]), "+f"(c[2]), "+f"(c[3])
                 : "r"(a[0]), "r"(a[1]), "r"(a[2]), "r"(a[3]), "r"(b0), "r"(b1));
}

__device__ __forceinline__ uint32_t bfbits(float x) {
    __nv_bfloat16 h = __float2bfloat16(x);
    return (uint32_t)*(unsigned short*)&h;
}
__device__ __forceinline__ float bff(uint32_t b) {
    unsigned short s = (unsigned short)b;
    __nv_bfloat16 h = *(__nv_bfloat16*)&s;
    return __bfloat162float(h);
}
__device__ __forceinline__ float lopart(float x) { return x - bff(bfbits(x)); }
__device__ __forceinline__ uint32_t pack2h(float a, float b) {
    return bfbits(a) | (bfbits(b) << 16);
}
__device__ __forceinline__ uint32_t pack_hl(float v) {
    uint32_t hb = bfbits(v);
    return hb | (bfbits(v - bff(hb)) << 16);
}

// ===================== k_prep: weight fp32 -> bf16 hi/lo planes =====================
__global__ void __launch_bounds__(256) k_prep(
    const float* __restrict__ W0, const float* __restrict__ W1,
    const float* __restrict__ W2, const float* __restrict__ W3,
    const float* __restrict__ W4, const float* __restrict__ W5)
{
    int gid = blockIdx.x * 256 + threadIdx.x;
    int wsel = gid >> 14;
    int rem = gid & 16383;
    int n = rem >> 7, k = rem & 127;
    const float* W;
    switch (wsel) {
        case 0: W = W0; break;
        case 1: W = W1; break;
        case 2: W = W2; break;
        case 3: W = W3; break;
        case 4: W = W4; break;
        default: W = W5; break;
    }
    float v = W[n * 128 + k];
    uint32_t hb = bfbits(v);
    uint32_t lb = bfbits(v - bff(hb));
    size_t base = (size_t)wsel * 34816 + n * 136 + k;
    g_wpl[base] = (unsigned short)hb;
    g_wpl[base + 17408] = (unsigned short)lb;
}

// copy one weight (hi+lo = 69632 B = 4352 uint4) from global planes to smem
__device__ __forceinline__ void copy_w(int wsel, void* dst, int tid, int nthr) {
    const uint4* src = (const uint4*)(g_wpl + (size_t)wsel * 34816);
    uint4* d = (uint4*)dst;
    for (int i = tid; i < 4352; i += nthr) d[i] = src[i];
}

// merged 3-combo gemm, A-hi preloaded in regs; warp tile 16 rows x 64 cols
__device__ __forceinline__ void wg3(const uint32_t (&aH)[8][4], uint32_t Zl,
                                    uint32_t Bh, uint32_t Bl,
                                    uint32_t aoff, uint32_t boff, float (&acc)[8][4]) {
#pragma unroll
    for (int t = 0; t < 8; t++)
#pragma unroll
        for (int e = 0; e < 4; e++) acc[t][e] = 0.f;
#pragma unroll 2
    for (int ks = 0; ks < 8; ks++) {
        uint32_t aL[4];
        ldsm4(aL, Zl + aoff + ks * 32);
#pragma unroll
        for (int g = 0; g < 4; g++) {
            uint32_t bh[4], bl[4];
            ldsm4(bh, Bh + boff + g * 4352 + ks * 32);
            ldsm4(bl, Bl + boff + g * 4352 + ks * 32);
            mma16816(acc[2 * g],     aH[ks], bh[0], bh[2]);
            mma16816(acc[2 * g + 1], aH[ks], bh[1], bh[3]);
            mma16816(acc[2 * g],     aH[ks], bl[0], bl[2]);
            mma16816(acc[2 * g + 1], aH[ks], bl[1], bl[3]);
            mma16816(acc[2 * g],     aL, bh[0], bh[2]);
            mma16816(acc[2 * g + 1], aL, bh[1], bh[3]);
        }
    }
}

// merged 3-combo gemm, A from smem (single-use); warp tile 16 x 64
__device__ __forceinline__ void wg3s(uint32_t Zh, uint32_t Zl,
                                     uint32_t Bh, uint32_t Bl,
                                     uint32_t aoff, uint32_t boff, float (&acc)[8][4]) {
#pragma unroll
    for (int t = 0; t < 8; t++)
#pragma unroll
        for (int e = 0; e < 4; e++) acc[t][e] = 0.f;
#pragma unroll 2
    for (int ks = 0; ks < 8; ks++) {
        uint32_t aH[4], aL[4];
        ldsm4(aH, Zh + aoff + ks * 32);
        ldsm4(aL, Zl + aoff + ks * 32);
#pragma unroll
        for (int g = 0; g < 4; g++) {
            uint32_t bh[4], bl[4];
            ldsm4(bh, Bh + boff + g * 4352 + ks * 32);
            ldsm4(bl, Bl + boff + g * 4352 + ks * 32);
            mma16816(acc[2 * g],     aH, bh[0], bh[2]);
            mma16816(acc[2 * g + 1], aH, bh[1], bh[3]);
            mma16816(acc[2 * g],     aH, bl[0], bl[2]);
            mma16816(acc[2 * g + 1], aH, bl[1], bl[3]);
            mma16816(acc[2 * g],     aL, bh[0], bh[2]);
            mma16816(acc[2 * g + 1], aL, bh[1], bh[3]);
        }
    }
}

// ===================== Stage 2: LN + 5 linears =====================
#define SMB_ZH  0
#define SMB_ZL  34816
#define SMB_B0  69632
#define SMB_B1  139264
#define SMB_TOT 208896

// combine + transpose-stage + coalesced channel-major store (packed hi/lo)
__device__ __forceinline__ void store_ab2(float (&P)[8][4], float (&G)[8][4],
                                          const float* __restrict__ bp,
                                          const float* __restrict__ bg,
                                          const float* __restrict__ mask,
                                          uint32_t* stg, uint32_t* __restrict__ gout,
                                          int r0, int rg, int chalf, int lane, int tid)
{
    int q = lane >> 2, m = lane & 3;
    int rl1 = rg * 16 + q, rl2 = rl1 + 8;
    float m1 = __ldg(mask + r0 + rl1), m2 = __ldg(mask + r0 + rl2);
#pragma unroll
    for (int t = 0; t < 8; t++) {
        int cc = chalf * 64 + t * 8 + 2 * m;
        float p0 = __ldg(bp + cc), p1 = __ldg(bp + cc + 1);
        float g0 = __ldg(bg + cc), g1 = __ldg(bg + cc + 1);
        stg[cc * 132 + rl1]       = pack_hl((P[t][0] + p0) * sigmf(G[t][0] + g0) * m1);
        stg[(cc + 1) * 132 + rl1] = pack_hl((P[t][1] + p1) * sigmf(G[t][1] + g1) * m1);
        stg[cc * 132 + rl2]       = pack_hl((P[t][2] + p0) * sigmf(G[t][2] + g0) * m2);
        stg[(cc + 1) * 132 + rl2] = pack_hl((P[t][3] + p1) * sigmf(G[t][3] + g1) * m2);
    }
    __syncthreads();
#pragma unroll
    for (int it = 0; it < 8; it++) {
        int idx = (tid + it * 512) * 4;
        int c = idx >> 7, r = idx & 127;
        uint4 v = *(uint4*)(stg + c * 132 + r);
        *(uint4*)(gout + (size_t)c * NN + r0 + r) = v;
    }
}

__global__ void __launch_bounds__(512) k_lin5(
    const float* __restrict__ z, const float* __restrict__ mask,
    const float* __restrict__ lnw, const float* __restrict__ lnb,
    const float* __restrict__ bpa, const float* __restrict__ bga,
    const float* __restrict__ bpb, const float* __restrict__ bgb,
    const float* __restrict__ bgo)
{
    extern __shared__ char sm[];
    uint32_t sb = smem_u32(sm);
    int tid = threadIdx.x, w = tid >> 5, lane = tid & 31;
    int rg = w & 7, chalf = w >> 3;
    int r0 = blockIdx.x * 128;

    // LayerNorm -> bf16 hi/lo planes (warp handles 8 rows)
    {
        float4 wv = ((const float4*)lnw)[lane];
        float4 bv = ((const float4*)lnb)[lane];
#pragma unroll
        for (int rr = 0; rr < 8; rr++) {
            int row = w * 8 + rr;
            float4 v = *(const float4*)(z + (size_t)(r0 + row) * C + lane * 4);
            float s1 = v.x + v.y + v.z + v.w;
            float s2 = v.x * v.x + v.y * v.y + v.z * v.z + v.w * v.w;
#pragma unroll
            for (int o = 16; o; o >>= 1) {
                s1 += __shfl_xor_sync(0xffffffffu, s1, o);
                s2 += __shfl_xor_sync(0xffffffffu, s2, o);
            }
            float mn = s1 * (1.f / 128.f);
            float var = fmaxf(s2 * (1.f / 128.f) - mn * mn, 0.f);
            float rs = rsqrtf(var + EPS);
            v.x = (v.x - mn) * rs * wv.x + bv.x;
            v.y = (v.y - mn) * rs * wv.y + bv.y;
            v.z = (v.z - mn) * rs * wv.z + bv.z;
            v.w = (v.w - mn) * rs * wv.w + bv.w;
            *(uint2*)(sm + SMB_ZH + row * 272 + lane * 8) =
                make_uint2(pack2h(v.x, v.y), pack2h(v.z, v.w));
            *(uint2*)(sm + SMB_ZL + row * 272 + lane * 8) =
                make_uint2(pack2h(lopart(v.x), lopart(v.y)),
                           pack2h(lopart(v.z), lopart(v.w)));
        }
    }
    // weight copies for branch a
    copy_w(0, sm + SMB_B0, tid, 512);
    copy_w(1, sm + SMB_B1, tid, 512);
    __syncthreads();

    uint32_t aoff = (uint32_t)(((rg * 16 + (lane & 15)) * 136 + (lane >> 4) * 8) * 2);
    uint32_t boff = (uint32_t)(((chalf * 64 + (lane & 15)) * 136 + (lane >> 4) * 8) * 2);

    // preload A-hi fragments (reused across all 5 gemms)
    uint32_t aH[8][4];
#pragma unroll
    for (int ks = 0; ks < 8; ks++) ldsm4(aH[ks], sb + SMB_ZH + aoff + ks * 32);

    float P[8][4], G[8][4];

    // branch a
    wg3(aH, sb + SMB_ZL, sb + SMB_B0, sb + SMB_B0 + 34816, aoff, boff, P);
    wg3(aH, sb + SMB_ZL, sb + SMB_B1, sb + SMB_B1 + 34816, aoff, boff, G);
    __syncthreads();
    store_ab2(P, G, bpa, bga, mask, (uint32_t*)(sm + SMB_B0), g_a, r0, rg, chalf, lane, tid);
    __syncthreads();

    // branch b
    copy_w(2, sm + SMB_B0, tid, 512);
    copy_w(3, sm + SMB_B1, tid, 512);
    __syncthreads();
    wg3(aH, sb + SMB_ZL, sb + SMB_B0, sb + SMB_B0 + 34816, aoff, boff, P);
    wg3(aH, sb + SMB_ZL, sb + SMB_B1, sb + SMB_B1 + 34816, aoff, boff, G);
    __syncthreads();
    store_ab2(P, G, bpb, bgb, mask, (uint32_t*)(sm + SMB_B0), g_b, r0, rg, chalf, lane, tid);
    __syncthreads();

    // gate_o
    copy_w(4, sm + SMB_B0, tid, 512);
    __syncthreads();
    wg3(aH, sb + SMB_ZL, sb + SMB_B0, sb + SMB_B0 + 34816, aoff, boff, P);
    __syncthreads();
    {
        float* stgf = (float*)(sm + SMB_B1);
        int q = lane >> 2, m = lane & 3;
#pragma unroll
        for (int t = 0; t < 8; t++) {
            int cc = chalf * 64 + t * 8 + 2 * m;
            float b0 = __ldg(bgo + cc), b1 = __ldg(bgo + cc + 1);
            stgf[(rg * 16 + q) * 132 + cc]         = sigmf(P[t][0] + b0);
            stgf[(rg * 16 + q) * 132 + cc + 1]     = sigmf(P[t][1] + b1);
            stgf[(rg * 16 + q + 8) * 132 + cc]     = sigmf(P[t][2] + b0);
            stgf[(rg * 16 + q + 8) * 132 + cc + 1] = sigmf(P[t][3] + b1);
        }
        __syncthreads();
#pragma unroll
        for (int it = 0; it < 8; it++) {
            int idx = (tid + it * 512) * 4;
            int row = idx >> 7, cc = idx & 127;
            float4 v = *(float4*)(stgf + row * 132 + cc);
            *(float4*)(g_gate + (size_t)(r0 + row) * C + cc) = v;
        }
    }
}

// ===================== Stage 3: contraction (now 2 CTAs/SM) ==========
#define CSM_TOT 69632

__global__ void __launch_bounds__(256, 2) k_contract(const float* __restrict__ mask) {
    extern __shared__ char sm[];
    uint32_t sb = smem_u32(sm);
    int tid = threadIdx.x, w = tid >> 5, lane = tid & 31;
    int blk = blockIdx.x;
    int bj = blk % 3, bi = (blk / 3) % 3, ch = blk / 9;
    const uint32_t* __restrict__ Ag = g_b + (size_t)ch * NN;  // [k][i]
    const uint32_t* __restrict__ Bg = g_a + (size_t)ch * NN;  // [k][j]
    int ibase = bi * 128, jbase = bj * 128;

    float acc[16][4];
#pragma unroll
    for (int t = 0; t < 16; t++)
#pragma unroll
        for (int e = 0; e < 4; e++) acc[t][e] = 0.f;

    int kl = (lane & 7) + (lane >> 4) * 8;
    int cbit = ((lane >> 3) & 1) * 8;
    uint32_t aoff = (uint32_t)((kl * 136 + w * 16 + cbit) * 2);
    uint32_t boff = (uint32_t)((kl * 136 + cbit) * 2);

    for (int k0 = 0; k0 < NDIM; k0 += 64) {
        __syncthreads();
#pragma unroll
        for (int it = 0; it < 16; it++) {
            int t2 = tid + it * 256;
            int row = t2 >> 6;
            int col2 = (t2 & 63) * 2;
            uint2 ua = *(const uint2*)(Ag + (size_t)(k0 + row) * NDIM + ibase + col2);
            uint2 ub = *(const uint2*)(Bg + (size_t)(k0 + row) * NDIM + jbase + col2);
            uint32_t off = row * 272 + col2 * 2;
            *(uint32_t*)(sm + 0     + off) = __byte_perm(ua.x, ua.y, 0x5410);
            *(uint32_t*)(sm + 17408 + off) = __byte_perm(ua.x, ua.y, 0x7632);
            *(uint32_t*)(sm + 34816 + off) = __byte_perm(ub.x, ub.y, 0x5410);
            *(uint32_t*)(sm + 52224 + off) = __byte_perm(ub.x, ub.y, 0x7632);
        }
        __syncthreads();
#pragma unroll
        for (int ks = 0; ks < 4; ks++) {
            uint32_t aH[4], aL[4];
            ldsm4t(aH, sb + 0     + aoff + ks * 4352);
            ldsm4t(aL, sb + 17408 + aoff + ks * 4352);
#pragma unroll
            for (int g = 0; g < 8; g++) {
                uint32_t bH[4], bL[4];
                uint32_t bo = boff + g * 32 + ks * 4352;
                ldsm4t(bH, sb + 34816 + bo);
                ldsm4t(bL, sb + 52224 + bo);
                mma16816(acc[2 * g],     aH, bH[0], bH[2]);
                mma16816(acc[2 * g + 1], aH, bH[1], bH[3]);
                mma16816(acc[2 * g],     aH, bL[0], bL[2]);
                mma16816(acc[2 * g + 1], aH, bL[1], bL[3]);
                mma16816(acc[2 * g],     aL, bH[0], bH[2]);
                mma16816(acc[2 * g + 1], aL, bH[1], bH[3]);
            }
        }
    }

    __syncthreads();
    float* stg = (float*)sm;   // 128 x 132 floats
    {
        int q = lane >> 2, m = lane & 3;
#pragma unroll
        for (int t = 0; t < 16; t++) {
            int cc = t * 8 + 2 * m;
            stg[(w * 16 + q) * 132 + cc]         = acc[t][0];
            stg[(w * 16 + q) * 132 + cc + 1]     = acc[t][1];
            stg[(w * 16 + q + 8) * 132 + cc]     = acc[t][2];
            stg[(w * 16 + q + 8) * 132 + cc + 1] = acc[t][3];
        }
    }
    __syncthreads();
#pragma unroll
    for (int it = 0; it < 16; it++) {
        int idx = (tid + it * 256) * 4;
        int row = idx >> 7, col = idx & 127;
        float4 v = *(float4*)(stg + row * 132 + col);
        int ig = ibase + row, jg = jbase + col;
        float4 mk = *(const float4*)(mask + (size_t)ig * NDIM + jg);
        v.x *= mk.x; v.y *= mk.y; v.z *= mk.z; v.w *= mk.w;
        *(float4*)(g_ct + (size_t)ch * NN + (size_t)ig * NDIM + jg) = v;
    }
}

// ===================== Stage 4: 64-row blocks, 2 CTAs/SM =====================
#define KO_BUF 0
#define KO_ZH  69632
#define KO_ZL  87040
#define KO_TOT 104448

__global__ void __launch_bounds__(256, 2) k_out(
    const float* __restrict__ lnw, const float* __restrict__ lnb,
    const float* __restrict__ bo, float* __restrict__ out)
{
    extern __shared__ char sm[];
    uint32_t sb = smem_u32(sm);
    int tid = threadIdx.x, w = tid >> 5, lane = tid & 31;
    int rg = w & 3, chalf = w >> 2;
    int r0 = blockIdx.x * 64;
    float* stg = (float*)(sm + KO_BUF);   // 64 x 132 floats

    // transposed load of g_ct with per-row channel rotation (rot = r & 124)
#pragma unroll
    for (int it = 0; it < 8; it++) {
        int linear = tid + it * 256;
        int c = linear >> 4;
        int r = (linear & 15) * 4;
        float4 v = *(const float4*)(g_ct + (size_t)c * NN + r0 + r);
        stg[(r + 0) * 132 + ((c + ((r + 0) & 124)) & 127)] = v.x;
        stg[(r + 1) * 132 + ((c + ((r + 1) & 124)) & 127)] = v.y;
        stg[(r + 2) * 132 + ((c + ((r + 2) & 124)) & 127)] = v.z;
        stg[(r + 3) * 132 + ((c + ((r + 3) & 124)) & 127)] = v.w;
    }
    __syncthreads();

    // LayerNorm rows (8 per warp) -> bf16 hi/lo planes
    {
        float4 wv = ((const float4*)lnw)[lane];
        float4 bv = ((const float4*)lnb)[lane];
#pragma unroll
        for (int rr = 0; rr < 8; rr++) {
            int row = w * 8 + rr;
            int pos = (lane * 4 + (row & 124)) & 127;
            float4 v = *(float4*)(stg + row * 132 + pos);
            float s1 = v.x + v.y + v.z + v.w;
            float s2 = v.x * v.x + v.y * v.y + v.z * v.z + v.w * v.w;
#pragma unroll
            for (int o = 16; o; o >>= 1) {
                s1 += __shfl_xor_sync(0xffffffffu, s1, o);
                s2 += __shfl_xor_sync(0xffffffffu, s2, o);
            }
            float mn = s1 * (1.f / 128.f);
            float var = fmaxf(s2 * (1.f / 128.f) - mn * mn, 0.f);
            float rs = rsqrtf(var + EPS);
            v.x = (v.x - mn) * rs * wv.x + bv.x;
            v.y = (v.y - mn) * rs * wv.y + bv.y;
            v.z = (v.z - mn) * rs * wv.z + bv.z;
            v.w = (v.w - mn) * rs * wv.w + bv.w;
            *(uint2*)(sm + KO_ZH + row * 272 + lane * 8) =
                make_uint2(pack2h(v.x, v.y), pack2h(v.z, v.w));
            *(uint2*)(sm + KO_ZL + row * 272 + lane * 8) =
                make_uint2(pack2h(lopart(v.x), lopart(v.y)),
                           pack2h(lopart(v.z), lopart(v.w)));
        }
    }
    __syncthreads();

    // weights (Wpo = plane 5) -> buf (overwrites stg)
    copy_w(5, sm + KO_BUF, tid, 256);
    __syncthreads();

    uint32_t aoff = (uint32_t)(((rg * 16 + (lane & 15)) * 136 + (lane >> 4) * 8) * 2);
    uint32_t boff = (uint32_t)(((chalf * 64 + (lane & 15)) * 136 + (lane >> 4) * 8) * 2);
    float P[8][4];
    wg3s(sb + KO_ZH, sb + KO_ZL, sb + KO_BUF, sb + KO_BUF + 34816, aoff, boff, P);
    __syncthreads();

    // epilogue: bias + gate, stage (overwrites weights), coalesced store
    {
        int q = lane >> 2, m = lane & 3;
        int rl1 = rg * 16 + q, rl2 = rl1 + 8;
#pragma unroll
        for (int t = 0; t < 8; t++) {
            int cc = chalf * 64 + t * 8 + 2 * m;
            float b0 = __ldg(bo + cc), b1 = __ldg(bo + cc + 1);
            stg[rl1 * 132 + cc]     = (P[t][0] + b0) * g_gate[(size_t)(r0 + rl1) * C + cc];
            stg[rl1 * 132 + cc + 1] = (P[t][1] + b1) * g_gate[(size_t)(r0 + rl1) * C + cc + 1];
            stg[rl2 * 132 + cc]     = (P[t][2] + b0) * g_gate[(size_t)(r0 + rl2) * C + cc];
            stg[rl2 * 132 + cc + 1] = (P[t][3] + b1) * g_gate[(size_t)(r0 + rl2) * C + cc + 1];
        }
    }
    __syncthreads();
#pragma unroll
    for (int it = 0; it < 8; it++) {
        int idx = (tid + it * 256) * 4;
        int row = idx >> 7, cc = idx & 127;
        float4 v = *(float4*)(stg + row * 132 + cc);
        *(float4*)(out + (size_t)(r0 + row) * C + cc) = v;
    }
}

extern "C" void kernel_launch(void* const* d_in, const int* in_sizes, int n_in,
                              void* d_out, int out_size) {
    const float* z    = (const float*)d_in[0];
    const float* mask = (const float*)d_in[1];
    const float* lniw = (const float*)d_in[2];
    const float* lnib = (const float*)d_in[3];
    const float* lnow = (const float*)d_in[4];
    const float* lnob = (const float*)d_in[5];
    const float* Wpa  = (const float*)d_in[6];
    const float* bpa  = (const float*)d_in[7];
    const float* Wga  = (const float*)d_in[8];
    const float* bga  = (const float*)d_in[9];
    const float* Wpb  = (const float*)d_in[10];
    const float* bpb  = (const float*)d_in[11];
    const float* Wgb  = (const float*)d_in[12];
    const float* bgb  = (const float*)d_in[13];
    const float* Wgo  = (const float*)d_in[14];
    const float* bgo  = (const float*)d_in[15];
    const float* Wpo  = (const float*)d_in[16];
    const float* bpo  = (const float*)d_in[17];
    float* out = (float*)d_out;

    cudaFuncSetAttribute(k_lin5, cudaFuncAttributeMaxDynamicSharedMemorySize, SMB_TOT);
    cudaFuncSetAttribute(k_contract, cudaFuncAttributeMaxDynamicSharedMemorySize, CSM_TOT);
    cudaFuncSetAttribute(k_out, cudaFuncAttributeMaxDynamicSharedMemorySize, KO_TOT);

    k_prep<<<384, 256>>>(Wpa, Wga, Wpb, Wgb, Wgo, Wpo);
    k_lin5<<<NN / 128, 512, SMB_TOT>>>(z, mask, lniw, lnib, bpa, bga, bpb, bgb, bgo);
    k_contract<<<9 * C, 256, CSM_TOT>>>(mask);
    k_out<<<NN / 64, 256, KO_TOT>>>(lnow, lnob, bpo, out);
}

// round 7
// speedup vs baseline: 2.3141x; 1.2742x over previous
#include <cuda_runtime.h>
#include <cuda_bf16.h>
#include <math.h>
#include <stdint.h>

#define NDIM 384
#define C 128
#define NN (NDIM*NDIM)
#define EPS 1e-5f

// Scratch (allocation-free rule: __device__ globals)
__device__ uint32_t g_a[(size_t)C * NN];   // a packed bf16 (hi|lo<<16): [c][k][j]
__device__ uint32_t g_b[(size_t)C * NN];   // b packed bf16: [c][k][i]
__device__ float    g_ct[(size_t)C * NN];  // contracted fp32: [c][i][j]
__device__ float    g_gate[(size_t)NN * C];// sigmoid(gate_o): [r][c]
// Weights as m16n8k16 B-fragments: [wsel][ks(8)][g(16)][lane(32)] -> (b0h,b1h,b0l,b1l)
__device__ uint4 g_wfrag[6 * 8 * 16 * 32];

__device__ __forceinline__ float sigmf(float x) { return 1.f / (1.f + __expf(-x)); }

__device__ __forceinline__ uint32_t smem_u32(const void* p) {
    uint32_t a;
    asm("{ .reg .u64 t; cvta.to.shared.u64 t, %1; cvt.u32.u64 %0, t; }" : "=r"(a) : "l"(p));
    return a;
}
__device__ __forceinline__ void ldsm4(uint32_t (&r)[4], uint32_t a) {
    asm volatile("ldmatrix.sync.aligned.m8n8.x4.shared.b16 {%0,%1,%2,%3}, [%4];"
                 : "=r"(r[0]), "=r"(r[1]), "=r"(r[2]), "=r"(r[3]) : "r"(a));
}
__device__ __forceinline__ void ldsm4t(uint32_t (&r)[4], uint32_t a) {
    asm volatile("ldmatrix.sync.aligned.m8n8.x4.trans.shared.b16 {%0,%1,%2,%3}, [%4];"
                 : "=r"(r[0]), "=r"(r[1]), "=r"(r[2]), "=r"(r[3]) : "r"(a));
}
__device__ __forceinline__ void mma16816(float (&c)[4], const uint32_t (&a)[4],
                                         uint32_t b0, uint32_t b1) {
    asm volatile("mma.sync.aligned.m16n8k16.row.col.f32.bf16.bf16.f32 "
                 "{%0,%1,%2,%3}, {%4,%5,%6,%7}, {%8,%9}, {%0,%1,%2,%3};"
                 : "+f"(c[0]), "+f"(c[1]), "+f"(c[2]), "+f"(c[3])
                 : "r"(a[0]), "r"(a[1]), "r"(a[2]), "r"(a[3]), "r"(b0), "r"(b1));
}

__device__ __forceinline__ uint32_t bfbits(float x) {
    __nv_bfloat16 h = __float2bfloat16(x);
    return (uint32_t)*(unsigned short*)&h;
}
__device__ __forceinline__ float bff(uint32_t b) {
    unsigned short s = (unsigned short)b;
    __nv_bfloat16 h = *(__nv_bfloat16*)&s;
    return __bfloat162float(h);
}
__device__ __forceinline__ float lopart(float x) { return x - bff(bfbits(x)); }
__device__ __forceinline__ uint32_t pack2h(float a, float b) {
    return bfbits(a) | (bfbits(b) << 16);
}
__device__ __forceinline__ uint32_t pack_hl(float v) {
    uint32_t hb = bfbits(v);
    return hb | (bfbits(v - bff(hb)) << 16);
}

// ===================== k_prep: weights -> MMA B-fragment layout =====================
// m16n8k16 B frag: lane l holds b0 = (B[k0][n], B[k0+1][n]), b1 = (B[k0+8][n], B[k0+9][n])
// with n = g*8 + l/4, k0 = ks*16 + (l%4)*2, and B[k][n] = W[n][k].
__global__ void __launch_bounds__(256) k_prep(
    const float* __restrict__ W0, const float* __restrict__ W1,
    const float* __restrict__ W2, const float* __restrict__ W3,
    const float* __restrict__ W4, const float* __restrict__ W5)
{
    int gid = blockIdx.x * 256 + threadIdx.x;  // 24576 total
    int lane = gid & 31;
    int g = (gid >> 5) & 15;
    int ks = (gid >> 9) & 7;
    int wsel = gid >> 12;
    const float* W;
    switch (wsel) {
        case 0: W = W0; break;
        case 1: W = W1; break;
        case 2: W = W2; break;
        case 3: W = W3; break;
        case 4: W = W4; break;
        default: W = W5; break;
    }
    int n = g * 8 + (lane >> 2);
    int k0 = ks * 16 + (lane & 3) * 2;
    float w0 = W[n * 128 + k0],     w1 = W[n * 128 + k0 + 1];
    float w2 = W[n * 128 + k0 + 8], w3 = W[n * 128 + k0 + 9];
    g_wfrag[gid] = make_uint4(pack2h(w0, w1), pack2h(w2, w3),
                              pack2h(lopart(w0), lopart(w1)),
                              pack2h(lopart(w2), lopart(w3)));
}

// merged 3-combo gemm; A-hi preloaded; B fragments from global (L2-resident)
// warp tile 16 rows x 64 cols, K=128
__device__ __forceinline__ void wg_glob(const uint32_t (&aH)[8][4], uint32_t Zl, uint32_t aoff,
                                        const uint4* __restrict__ Wf, float (&acc)[8][4]) {
#pragma unroll
    for (int t = 0; t < 8; t++)
#pragma unroll
        for (int e = 0; e < 4; e++) acc[t][e] = 0.f;
#pragma unroll 2
    for (int ks = 0; ks < 8; ks++) {
        uint32_t aL[4];
        ldsm4(aL, Zl + aoff + ks * 32);
#pragma unroll
        for (int g = 0; g < 8; g++) {
            uint4 f = __ldg(Wf + (ks * 16 + g) * 32);
            mma16816(acc[g], aH[ks], f.x, f.y);   // hi*hi
            mma16816(acc[g], aH[ks], f.z, f.w);   // hi*lo
            mma16816(acc[g], aL,     f.x, f.y);   // lo*hi
        }
    }
}

// ===================== Stage 2: LN + 5 linears =====================
#define L5_ZH  0
#define L5_ZL  17408
#define L5_TOT 34816

// combine + direct channel-major store (sector-full 32B segments)
__device__ __forceinline__ void store_ab_d(float (&P)[8][4], float (&G)[8][4],
                                           const float* __restrict__ bp,
                                           const float* __restrict__ bg,
                                           const float* __restrict__ mask,
                                           uint32_t* __restrict__ gout,
                                           int r0, int rg, int chalf, int lane)
{
    int q = lane >> 2, m = lane & 3;
    int r1 = r0 + rg * 16 + q, r2 = r1 + 8;
    float m1 = __ldg(mask + r1), m2 = __ldg(mask + r2);
#pragma unroll
    for (int t = 0; t < 8; t++) {
        int cc = chalf * 64 + t * 8 + 2 * m;
        float p0 = __ldg(bp + cc), p1 = __ldg(bp + cc + 1);
        float g0 = __ldg(bg + cc), g1 = __ldg(bg + cc + 1);
        gout[(size_t)cc * NN + r1]       = pack_hl((P[t][0] + p0) * sigmf(G[t][0] + g0) * m1);
        gout[(size_t)(cc + 1) * NN + r1] = pack_hl((P[t][1] + p1) * sigmf(G[t][1] + g1) * m1);
        gout[(size_t)cc * NN + r2]       = pack_hl((P[t][2] + p0) * sigmf(G[t][2] + g0) * m2);
        gout[(size_t)(cc + 1) * NN + r2] = pack_hl((P[t][3] + p1) * sigmf(G[t][3] + g1) * m2);
    }
}

__global__ void __launch_bounds__(256, 2) k_lin5(
    const float* __restrict__ z, const float* __restrict__ mask,
    const float* __restrict__ lnw, const float* __restrict__ lnb,
    const float* __restrict__ bpa, const float* __restrict__ bga,
    const float* __restrict__ bpb, const float* __restrict__ bgb,
    const float* __restrict__ bgo)
{
    extern __shared__ char sm[];
    uint32_t sb = smem_u32(sm);
    int tid = threadIdx.x, w = tid >> 5, lane = tid & 31;
    int rg = w & 3, chalf = w >> 2;
    int r0 = blockIdx.x * 64;

    // LayerNorm -> bf16 hi/lo planes (warp handles 8 rows)
    {
        float4 wv = ((const float4*)lnw)[lane];
        float4 bv = ((const float4*)lnb)[lane];
#pragma unroll
        for (int rr = 0; rr < 8; rr++) {
            int row = w * 8 + rr;
            float4 v = *(const float4*)(z + (size_t)(r0 + row) * C + lane * 4);
            float s1 = v.x + v.y + v.z + v.w;
            float s2 = v.x * v.x + v.y * v.y + v.z * v.z + v.w * v.w;
#pragma unroll
            for (int o = 16; o; o >>= 1) {
                s1 += __shfl_xor_sync(0xffffffffu, s1, o);
                s2 += __shfl_xor_sync(0xffffffffu, s2, o);
            }
            float mn = s1 * (1.f / 128.f);
            float var = fmaxf(s2 * (1.f / 128.f) - mn * mn, 0.f);
            float rs = rsqrtf(var + EPS);
            v.x = (v.x - mn) * rs * wv.x + bv.x;
            v.y = (v.y - mn) * rs * wv.y + bv.y;
            v.z = (v.z - mn) * rs * wv.z + bv.z;
            v.w = (v.w - mn) * rs * wv.w + bv.w;
            *(uint2*)(sm + L5_ZH + row * 272 + lane * 8) =
                make_uint2(pack2h(v.x, v.y), pack2h(v.z, v.w));
            *(uint2*)(sm + L5_ZL + row * 272 + lane * 8) =
                make_uint2(pack2h(lopart(v.x), lopart(v.y)),
                           pack2h(lopart(v.z), lopart(v.w)));
        }
    }
    __syncthreads();

    uint32_t aoff = (uint32_t)(((rg * 16 + (lane & 15)) * 136 + (lane >> 4) * 8) * 2);

    // preload A-hi fragments (reused across all 5 gemms)
    uint32_t aH[8][4];
#pragma unroll
    for (int ks = 0; ks < 8; ks++) ldsm4(aH[ks], sb + L5_ZH + aoff + ks * 32);

    const uint4* WfBase = g_wfrag + (chalf * 8) * 32 + lane;
    float P[8][4], G[8][4];

    // branch a
    wg_glob(aH, sb + L5_ZL, aoff, WfBase + 0 * 4096, P);
    wg_glob(aH, sb + L5_ZL, aoff, WfBase + 1 * 4096, G);
    store_ab_d(P, G, bpa, bga, mask, g_a, r0, rg, chalf, lane);

    // branch b
    wg_glob(aH, sb + L5_ZL, aoff, WfBase + 2 * 4096, P);
    wg_glob(aH, sb + L5_ZL, aoff, WfBase + 3 * 4096, G);
    store_ab_d(P, G, bpb, bgb, mask, g_b, r0, rg, chalf, lane);

    // gate_o -> g_gate [r][c] direct
    wg_glob(aH, sb + L5_ZL, aoff, WfBase + 4 * 4096, P);
    {
        int q = lane >> 2, m = lane & 3;
        int r1 = r0 + rg * 16 + q, r2 = r1 + 8;
#pragma unroll
        for (int t = 0; t < 8; t++) {
            int cc = chalf * 64 + t * 8 + 2 * m;
            float b0 = __ldg(bgo + cc), b1 = __ldg(bgo + cc + 1);
            g_gate[(size_t)r1 * C + cc]     = sigmf(P[t][0] + b0);
            g_gate[(size_t)r1 * C + cc + 1] = sigmf(P[t][1] + b1);
            g_gate[(size_t)r2 * C + cc]     = sigmf(P[t][2] + b0);
            g_gate[(size_t)r2 * C + cc + 1] = sigmf(P[t][3] + b1);
        }
    }
}

// ===================== Stage 3: contraction, 32x64 warp tiles ==========
#define CSM_TOT 69632

__global__ void __launch_bounds__(256, 2) k_contract(const float* __restrict__ mask) {
    extern __shared__ char sm[];
    uint32_t sb = smem_u32(sm);
    int tid = threadIdx.x, w = tid >> 5, lane = tid & 31;
    int blk = blockIdx.x;
    int bj = blk % 3, bi = (blk / 3) % 3, ch = blk / 9;
    const uint32_t* __restrict__ Ag = g_b + (size_t)ch * NN;  // [k][i]
    const uint32_t* __restrict__ Bg = g_a + (size_t)ch * NN;  // [k][j]
    int ibase = bi * 128, jbase = bj * 128;
    int ig = w & 3, jg = w >> 2;   // 4 i-groups x 2 j-groups

    float acc[2][8][4];
#pragma unroll
    for (int r = 0; r < 2; r++)
#pragma unroll
        for (int t = 0; t < 8; t++)
#pragma unroll
            for (int e = 0; e < 4; e++) acc[r][t][e] = 0.f;

    int kl = (lane & 7) + (lane >> 4) * 8;
    int cbit = ((lane >> 3) & 1) * 8;
    uint32_t aoff0 = (uint32_t)((kl * 136 + ig * 32 + cbit) * 2);
    uint32_t aoff1 = aoff0 + 32;
    uint32_t boff = (uint32_t)((kl * 136 + jg * 64 + cbit) * 2);

    for (int k0 = 0; k0 < NDIM; k0 += 64) {
        __syncthreads();
#pragma unroll
        for (int it = 0; it < 16; it++) {
            int t2 = tid + it * 256;
            int row = t2 >> 6;
            int col2 = (t2 & 63) * 2;
            uint2 ua = *(const uint2*)(Ag + (size_t)(k0 + row) * NDIM + ibase + col2);
            uint2 ub = *(const uint2*)(Bg + (size_t)(k0 + row) * NDIM + jbase + col2);
            uint32_t off = row * 272 + col2 * 2;
            *(uint32_t*)(sm + 0     + off) = __byte_perm(ua.x, ua.y, 0x5410);
            *(uint32_t*)(sm + 17408 + off) = __byte_perm(ua.x, ua.y, 0x7632);
            *(uint32_t*)(sm + 34816 + off) = __byte_perm(ub.x, ub.y, 0x5410);
            *(uint32_t*)(sm + 52224 + off) = __byte_perm(ub.x, ub.y, 0x7632);
        }
        __syncthreads();
#pragma unroll
        for (int ks = 0; ks < 4; ks++) {
            uint32_t aH0[4], aH1[4], aL0[4], aL1[4];
            ldsm4t(aH0, sb + 0     + aoff0 + ks * 4352);
            ldsm4t(aH1, sb + 0     + aoff1 + ks * 4352);
            ldsm4t(aL0, sb + 17408 + aoff0 + ks * 4352);
            ldsm4t(aL1, sb + 17408 + aoff1 + ks * 4352);
#pragma unroll
            for (int g = 0; g < 4; g++) {
                uint32_t bH[4], bL[4];
                uint32_t bo = boff + g * 32 + ks * 4352;
                ldsm4t(bH, sb + 34816 + bo);
                ldsm4t(bL, sb + 52224 + bo);
                mma16816(acc[0][2 * g],     aH0, bH[0], bH[2]);
                mma16816(acc[0][2 * g + 1], aH0, bH[1], bH[3]);
                mma16816(acc[0][2 * g],     aH0, bL[0], bL[2]);
                mma16816(acc[0][2 * g + 1], aH0, bL[1], bL[3]);
                mma16816(acc[0][2 * g],     aL0, bH[0], bH[2]);
                mma16816(acc[0][2 * g + 1], aL0, bH[1], bH[3]);
                mma16816(acc[1][2 * g],     aH1, bH[0], bH[2]);
                mma16816(acc[1][2 * g + 1], aH1, bH[1], bH[3]);
                mma16816(acc[1][2 * g],     aH1, bL[0], bL[2]);
                mma16816(acc[1][2 * g + 1], aH1, bL[1], bL[3]);
                mma16816(acc[1][2 * g],     aL1, bH[0], bH[2]);
                mma16816(acc[1][2 * g + 1], aL1, bH[1], bH[3]);
            }
        }
    }

    __syncthreads();
    float* stg = (float*)sm;   // 128 x 132 floats
    {
        int q = lane >> 2, m = lane & 3;
#pragma unroll
        for (int r = 0; r < 2; r++)
#pragma unroll
            for (int t = 0; t < 8; t++) {
                int row1 = ig * 32 + r * 16 + q, row2 = row1 + 8;
                int col = jg * 64 + (t >> 1) * 16 + (t & 1) * 8 + 2 * m;
                stg[row1 * 132 + col]     = acc[r][t][0];
                stg[row1 * 132 + col + 1] = acc[r][t][1];
                stg[row2 * 132 + col]     = acc[r][t][2];
                stg[row2 * 132 + col + 1] = acc[r][t][3];
            }
    }
    __syncthreads();
#pragma unroll
    for (int it = 0; it < 16; it++) {
        int idx = (tid + it * 256) * 4;
        int row = idx >> 7, col = idx & 127;
        float4 v = *(float4*)(stg + row * 132 + col);
        int igl = ibase + row, jgl = jbase + col;
        float4 mk = *(const float4*)(mask + (size_t)igl * NDIM + jgl);
        v.x *= mk.x; v.y *= mk.y; v.z *= mk.z; v.w *= mk.w;
        *(float4*)(g_ct + (size_t)ch * NN + (size_t)igl * NDIM + jgl) = v;
    }
}

// ===================== Stage 4: transpose + LN + proj_o + gate =====================
#define KO_STG 0
#define KO_ZH  33792
#define KO_ZL  51200
#define KO_TOT 68608

__global__ void __launch_bounds__(256, 2) k_out(
    const float* __restrict__ lnw, const float* __restrict__ lnb,
    const float* __restrict__ bo, float* __restrict__ out)
{
    extern __shared__ char sm[];
    uint32_t sb = smem_u32(sm);
    int tid = threadIdx.x, w = tid >> 5, lane = tid & 31;
    int rg = w & 3, chalf = w >> 2;
    int r0 = blockIdx.x * 64;
    float* stg = (float*)(sm + KO_STG);   // 64 x 132 floats

    // transposed load of g_ct with per-row channel rotation (rot = r & 124)
#pragma unroll
    for (int it = 0; it < 8; it++) {
        int linear = tid + it * 256;
        int c = linear >> 4;
        int r = (linear & 15) * 4;
        float4 v = *(const float4*)(g_ct + (size_t)c * NN + r0 + r);
        stg[(r + 0) * 132 + ((c + ((r + 0) & 124)) & 127)] = v.x;
        stg[(r + 1) * 132 + ((c + ((r + 1) & 124)) & 127)] = v.y;
        stg[(r + 2) * 132 + ((c + ((r + 2) & 124)) & 127)] = v.z;
        stg[(r + 3) * 132 + ((c + ((r + 3) & 124)) & 127)] = v.w;
    }
    __syncthreads();

    // LayerNorm rows (8 per warp) -> bf16 hi/lo planes
    {
        float4 wv = ((const float4*)lnw)[lane];
        float4 bv = ((const float4*)lnb)[lane];
#pragma unroll
        for (int rr = 0; rr < 8; rr++) {
            int row = w * 8 + rr;
            int pos = (lane * 4 + (row & 124)) & 127;
            float4 v = *(float4*)(stg + row * 132 + pos);
            float s1 = v.x + v.y + v.z + v.w;
            float s2 = v.x * v.x + v.y * v.y + v.z * v.z + v.w * v.w;
#pragma unroll
            for (int o = 16; o; o >>= 1) {
                s1 += __shfl_xor_sync(0xffffffffu, s1, o);
                s2 += __shfl_xor_sync(0xffffffffu, s2, o);
            }
            float mn = s1 * (1.f / 128.f);
            float var = fmaxf(s2 * (1.f / 128.f) - mn * mn, 0.f);
            float rs = rsqrtf(var + EPS);
            v.x = (v.x - mn) * rs * wv.x + bv.x;
            v.y = (v.y - mn) * rs * wv.y + bv.y;
            v.z = (v.z - mn) * rs * wv.z + bv.z;
            v.w = (v.w - mn) * rs * wv.w + bv.w;
            *(uint2*)(sm + KO_ZH + row * 272 + lane * 8) =
                make_uint2(pack2h(v.x, v.y), pack2h(v.z, v.w));
            *(uint2*)(sm + KO_ZL + row * 272 + lane * 8) =
                make_uint2(pack2h(lopart(v.x), lopart(v.y)),
                           pack2h(lopart(v.z), lopart(v.w)));
        }
    }
    __syncthreads();

    uint32_t aoff = (uint32_t)(((rg * 16 + (lane & 15)) * 136 + (lane >> 4) * 8) * 2);
    uint32_t aH[8][4];
#pragma unroll
    for (int ks = 0; ks < 8; ks++) ldsm4(aH[ks], sb + KO_ZH + aoff + ks * 32);

    float P[8][4];
    wg_glob(aH, sb + KO_ZL, aoff, g_wfrag + 5 * 4096 + (chalf * 8) * 32 + lane, P);

    // epilogue: bias + gate, direct store
    {
        int q = lane >> 2, m = lane & 3;
        int r1 = r0 + rg * 16 + q, r2 = r1 + 8;
#pragma unroll
        for (int t = 0; t < 8; t++) {
            int cc = chalf * 64 + t * 8 + 2 * m;
            float b0 = __ldg(bo + cc), b1 = __ldg(bo + cc + 1);
            out[(size_t)r1 * C + cc]     = (P[t][0] + b0) * g_gate[(size_t)r1 * C + cc];
            out[(size_t)r1 * C + cc + 1] = (P[t][1] + b1) * g_gate[(size_t)r1 * C + cc + 1];
            out[(size_t)r2 * C + cc]     = (P[t][2] + b0) * g_gate[(size_t)r2 * C + cc];
            out[(size_t)r2 * C + cc + 1] = (P[t][3] + b1) * g_gate[(size_t)r2 * C + cc + 1];
        }
    }
}

extern "C" void kernel_launch(void* const* d_in, const int* in_sizes, int n_in,
                              void* d_out, int out_size) {
    const float* z    = (const float*)d_in[0];
    const float* mask = (const float*)d_in[1];
    const float* lniw = (const float*)d_in[2];
    const float* lnib = (const float*)d_in[3];
    const float* lnow = (const float*)d_in[4];
    const float* lnob = (const float*)d_in[5];
    const float* Wpa  = (const float*)d_in[6];
    const float* bpa  = (const float*)d_in[7];
    const float* Wga  = (const float*)d_in[8];
    const float* bga  = (const float*)d_in[9];
    const float* Wpb  = (const float*)d_in[10];
    const float* bpb  = (const float*)d_in[11];
    const float* Wgb  = (const float*)d_in[12];
    const float* bgb  = (const float*)d_in[13];
    const float* Wgo  = (const float*)d_in[14];
    const float* bgo  = (const float*)d_in[15];
    const float* Wpo  = (const float*)d_in[16];
    const float* bpo  = (const float*)d_in[17];
    float* out = (float*)d_out;

    cudaFuncSetAttribute(k_contract, cudaFuncAttributeMaxDynamicSharedMemorySize, CSM_TOT);
    cudaFuncSetAttribute(k_out, cudaFuncAttributeMaxDynamicSharedMemorySize, KO_TOT);

    k_prep<<<96, 256>>>(Wpa, Wga, Wpb, Wgb, Wgo, Wpo);
    k_lin5<<<NN / 64, 256, L5_TOT>>>(z, mask, lniw, lnib, bpa, bga, bpb, bgb, bgo);
    k_contract<<<9 * C, 256, CSM_TOT>>>(mask);
    k_out<<<NN / 64, 256, KO_TOT>>>(lnow, lnob, bpo, out);
}

// round 8
// speedup vs baseline: 2.3399x; 1.0112x over previous
#include <cuda_runtime.h>
#include <cuda_bf16.h>
#include <math.h>
#include <stdint.h>

#define NDIM 384
#define C 128
#define NN (NDIM*NDIM)
#define EPS 1e-5f

// Scratch (allocation-free rule: __device__ globals)
// a/b as separate bf16 hi/lo planes, channel-major [c][k][j]
__device__ __align__(16) unsigned short g_ah[(size_t)C * NN];
__device__ __align__(16) unsigned short g_al[(size_t)C * NN];
__device__ __align__(16) unsigned short g_bh[(size_t)C * NN];
__device__ __align__(16) unsigned short g_bl[(size_t)C * NN];
__device__ float g_ct[(size_t)C * NN];    // contracted fp32: [c][i][j]
__device__ float g_gate[(size_t)NN * C];  // sigmoid(gate_o): [r][c]
// Weights as m16n8k16 B-fragments: [wsel][ks(8)][g(16)][lane(32)] -> (b0h,b1h,b0l,b1l)
__device__ uint4 g_wfrag[6 * 8 * 16 * 32];

__device__ __forceinline__ float sigmf(float x) { return 1.f / (1.f + __expf(-x)); }

__device__ __forceinline__ uint32_t smem_u32(const void* p) {
    uint32_t a;
    asm("{ .reg .u64 t; cvta.to.shared.u64 t, %1; cvt.u32.u64 %0, t; }" : "=r"(a) : "l"(p));
    return a;
}
__device__ __forceinline__ void ldsm4(uint32_t (&r)[4], uint32_t a) {
    asm volatile("ldmatrix.sync.aligned.m8n8.x4.shared.b16 {%0,%1,%2,%3}, [%4];"
                 : "=r"(r[0]), "=r"(r[1]), "=r"(r[2]), "=r"(r[3]) : "r"(a));
}
__device__ __forceinline__ void ldsm4t(uint32_t (&r)[4], uint32_t a) {
    asm volatile("ldmatrix.sync.aligned.m8n8.x4.trans.shared.b16 {%0,%1,%2,%3}, [%4];"
                 : "=r"(r[0]), "=r"(r[1]), "=r"(r[2]), "=r"(r[3]) : "r"(a));
}
__device__ __forceinline__ void mma16816(float (&c)[4], const uint32_t (&a)[4],
                                         uint32_t b0, uint32_t b1) {
    asm volatile("mma.sync.aligned.m16n8k16.row.col.f32.bf16.bf16.f32 "
                 "{%0,%1,%2,%3}, {%4,%5,%6,%7}, {%8,%9}, {%0,%1,%2,%3};"
                 : "+f"(c[0]), "+f"(c[1]), "+f"(c[2]), "+f"(c[3])
                 : "r"(a[0]), "r"(a[1]), "r"(a[2]), "r"(a[3]), "r"(b0), "r"(b1));
}
__device__ __forceinline__ void cp16(uint32_t dst, const void* src) {
    asm volatile("cp.async.cg.shared.global [%0], [%1], 16;" :: "r"(dst), "l"(src));
}
#define CP_COMMIT() asm volatile("cp.async.commit_group;" ::: "memory")

__device__ __forceinline__ uint32_t bfbits(float x) {
    __nv_bfloat16 h = __float2bfloat16(x);
    return (uint32_t)*(unsigned short*)&h;
}
__device__ __forceinline__ float bff(uint32_t b) {
    unsigned short s = (unsigned short)b;
    __nv_bfloat16 h = *(__nv_bfloat16*)&s;
    return __bfloat162float(h);
}
__device__ __forceinline__ float lopart(float x) { return x - bff(bfbits(x)); }
__device__ __forceinline__ uint32_t pack2h(float a, float b) {
    return bfbits(a) | (bfbits(b) << 16);
}

// ===================== k_prep: weights -> MMA B-fragment layout =====================
__global__ void __launch_bounds__(256) k_prep(
    const float* __restrict__ W0, const float* __restrict__ W1,
    const float* __restrict__ W2, const float* __restrict__ W3,
    const float* __restrict__ W4, const float* __restrict__ W5)
{
    int gid = blockIdx.x * 256 + threadIdx.x;  // 24576 total
    int lane = gid & 31;
    int g = (gid >> 5) & 15;
    int ks = (gid >> 9) & 7;
    int wsel = gid >> 12;
    const float* W;
    switch (wsel) {
        case 0: W = W0; break;
        case 1: W = W1; break;
        case 2: W = W2; break;
        case 3: W = W3; break;
        case 4: W = W4; break;
        default: W = W5; break;
    }
    int n = g * 8 + (lane >> 2);
    int k0 = ks * 16 + (lane & 3) * 2;
    float w0 = W[n * 128 + k0],     w1 = W[n * 128 + k0 + 1];
    float w2 = W[n * 128 + k0 + 8], w3 = W[n * 128 + k0 + 9];
    g_wfrag[gid] = make_uint4(pack2h(w0, w1), pack2h(w2, w3),
                              pack2h(lopart(w0), lopart(w1)),
                              pack2h(lopart(w2), lopart(w3)));
}

// merged 3-combo gemm; A-hi preloaded; B fragments from global (L2-resident)
__device__ __forceinline__ void wg_glob(const uint32_t (&aH)[8][4], uint32_t Zl, uint32_t aoff,
                                        const uint4* __restrict__ Wf, float (&acc)[8][4]) {
#pragma unroll
    for (int t = 0; t < 8; t++)
#pragma unroll
        for (int e = 0; e < 4; e++) acc[t][e] = 0.f;
#pragma unroll 2
    for (int ks = 0; ks < 8; ks++) {
        uint32_t aL[4];
        ldsm4(aL, Zl + aoff + ks * 32);
#pragma unroll
        for (int g = 0; g < 8; g++) {
            uint4 f = __ldg(Wf + (ks * 16 + g) * 32);
            mma16816(acc[g], aH[ks], f.x, f.y);   // hi*hi
            mma16816(acc[g], aH[ks], f.z, f.w);   // hi*lo
            mma16816(acc[g], aL,     f.x, f.y);   // lo*hi
        }
    }
}

// ===================== Stage 2: LN + 5 linears =====================
#define L5_ZH  0
#define L5_ZL  17408
#define L5_TOT 34816

// combine + direct channel-major store into hi/lo planes
__device__ __forceinline__ void store_ab_d(float (&P)[8][4], float (&G)[8][4],
                                           const float* __restrict__ bp,
                                           const float* __restrict__ bg,
                                           const float* __restrict__ mask,
                                           unsigned short* __restrict__ gh,
                                           unsigned short* __restrict__ gl,
                                           int r0, int rg, int chalf, int lane)
{
    int q = lane >> 2, m = lane & 3;
    int r1 = r0 + rg * 16 + q, r2 = r1 + 8;
    float m1 = __ldg(mask + r1), m2 = __ldg(mask + r2);
#pragma unroll
    for (int t = 0; t < 8; t++) {
        int cc = chalf * 64 + t * 8 + 2 * m;
        float p0 = __ldg(bp + cc), p1 = __ldg(bp + cc + 1);
        float g0 = __ldg(bg + cc), g1 = __ldg(bg + cc + 1);
        float v0 = (P[t][0] + p0) * sigmf(G[t][0] + g0) * m1;
        float v1 = (P[t][1] + p1) * sigmf(G[t][1] + g1) * m1;
        float v2 = (P[t][2] + p0) * sigmf(G[t][2] + g0) * m2;
        float v3 = (P[t][3] + p1) * sigmf(G[t][3] + g1) * m2;
        uint32_t h0 = bfbits(v0), h1 = bfbits(v1), h2 = bfbits(v2), h3 = bfbits(v3);
        size_t o0 = (size_t)cc * NN + r1, o1 = (size_t)(cc + 1) * NN + r1;
        size_t o2 = (size_t)cc * NN + r2, o3 = (size_t)(cc + 1) * NN + r2;
        gh[o0] = (unsigned short)h0; gl[o0] = (unsigned short)bfbits(v0 - bff(h0));
        gh[o1] = (unsigned short)h1; gl[o1] = (unsigned short)bfbits(v1 - bff(h1));
        gh[o2] = (unsigned short)h2; gl[o2] = (unsigned short)bfbits(v2 - bff(h2));
        gh[o3] = (unsigned short)h3; gl[o3] = (unsigned short)bfbits(v3 - bff(h3));
    }
}

__global__ void __launch_bounds__(256, 2) k_lin5(
    const float* __restrict__ z, const float* __restrict__ mask,
    const float* __restrict__ lnw, const float* __restrict__ lnb,
    const float* __restrict__ bpa, const float* __restrict__ bga,
    const float* __restrict__ bpb, const float* __restrict__ bgb,
    const float* __restrict__ bgo)
{
    extern __shared__ char sm[];
    uint32_t sb = smem_u32(sm);
    int tid = threadIdx.x, w = tid >> 5, lane = tid & 31;
    int rg = w & 3, chalf = w >> 2;
    int r0 = blockIdx.x * 64;

    // LayerNorm -> bf16 hi/lo planes (warp handles 8 rows)
    {
        float4 wv = ((const float4*)lnw)[lane];
        float4 bv = ((const float4*)lnb)[lane];
#pragma unroll
        for (int rr = 0; rr < 8; rr++) {
            int row = w * 8 + rr;
            float4 v = *(const float4*)(z + (size_t)(r0 + row) * C + lane * 4);
            float s1 = v.x + v.y + v.z + v.w;
            float s2 = v.x * v.x + v.y * v.y + v.z * v.z + v.w * v.w;
#pragma unroll
            for (int o = 16; o; o >>= 1) {
                s1 += __shfl_xor_sync(0xffffffffu, s1, o);
                s2 += __shfl_xor_sync(0xffffffffu, s2, o);
            }
            float mn = s1 * (1.f / 128.f);
            float var = fmaxf(s2 * (1.f / 128.f) - mn * mn, 0.f);
            float rs = rsqrtf(var + EPS);
            v.x = (v.x - mn) * rs * wv.x + bv.x;
            v.y = (v.y - mn) * rs * wv.y + bv.y;
            v.z = (v.z - mn) * rs * wv.z + bv.z;
            v.w = (v.w - mn) * rs * wv.w + bv.w;
            *(uint2*)(sm + L5_ZH + row * 272 + lane * 8) =
                make_uint2(pack2h(v.x, v.y), pack2h(v.z, v.w));
            *(uint2*)(sm + L5_ZL + row * 272 + lane * 8) =
                make_uint2(pack2h(lopart(v.x), lopart(v.y)),
                           pack2h(lopart(v.z), lopart(v.w)));
        }
    }
    __syncthreads();

    uint32_t aoff = (uint32_t)(((rg * 16 + (lane & 15)) * 136 + (lane >> 4) * 8) * 2);

    // preload A-hi fragments (reused across all 5 gemms)
    uint32_t aH[8][4];
#pragma unroll
    for (int ks = 0; ks < 8; ks++) ldsm4(aH[ks], sb + L5_ZH + aoff + ks * 32);

    const uint4* WfBase = g_wfrag + (chalf * 8) * 32 + lane;
    float P[8][4], G[8][4];

    // branch a
    wg_glob(aH, sb + L5_ZL, aoff, WfBase + 0 * 4096, P);
    wg_glob(aH, sb + L5_ZL, aoff, WfBase + 1 * 4096, G);
    store_ab_d(P, G, bpa, bga, mask, g_ah, g_al, r0, rg, chalf, lane);

    // branch b
    wg_glob(aH, sb + L5_ZL, aoff, WfBase + 2 * 4096, P);
    wg_glob(aH, sb + L5_ZL, aoff, WfBase + 3 * 4096, G);
    store_ab_d(P, G, bpb, bgb, mask, g_bh, g_bl, r0, rg, chalf, lane);

    // gate_o -> g_gate [r][c] direct
    wg_glob(aH, sb + L5_ZL, aoff, WfBase + 4 * 4096, P);
    {
        int q = lane >> 2, m = lane & 3;
        int r1 = r0 + rg * 16 + q, r2 = r1 + 8;
#pragma unroll
        for (int t = 0; t < 8; t++) {
            int cc = chalf * 64 + t * 8 + 2 * m;
            float b0 = __ldg(bgo + cc), b1 = __ldg(bgo + cc + 1);
            g_gate[(size_t)r1 * C + cc]     = sigmf(P[t][0] + b0);
            g_gate[(size_t)r1 * C + cc + 1] = sigmf(P[t][1] + b1);
            g_gate[(size_t)r2 * C + cc]     = sigmf(P[t][2] + b0);
            g_gate[(size_t)r2 * C + cc + 1] = sigmf(P[t][3] + b1);
        }
    }
}

// ===================== Stage 3: contraction, cp.async double-buffered ==========
// Chunk = 32 k-rows. Planes per chunk: aH,aL,bH,bL at 8704 B each (32 rows x 272 B).
#define CH_BUF 34816
#define CSM_TOT 69632

__global__ void __launch_bounds__(256, 2) k_contract(const float* __restrict__ mask) {
    extern __shared__ char sm[];
    uint32_t sb = smem_u32(sm);
    int tid = threadIdx.x, w = tid >> 5, lane = tid & 31;
    int blk = blockIdx.x;
    int bj = blk % 3, bi = (blk / 3) % 3, ch = blk / 9;
    int ibase = bi * 128, jbase = bj * 128;
    // A operand = b (i-axis), B operand = a (j-axis)
    const unsigned short* s0 = g_bh + (size_t)ch * NN + ibase;
    const unsigned short* s1 = g_bl + (size_t)ch * NN + ibase;
    const unsigned short* s2 = g_ah + (size_t)ch * NN + jbase;
    const unsigned short* s3 = g_al + (size_t)ch * NN + jbase;
    int ig = w & 3, jg = w >> 2;   // 4 i-groups x 2 j-groups

    float acc[2][8][4];
#pragma unroll
    for (int r = 0; r < 2; r++)
#pragma unroll
        for (int t = 0; t < 8; t++)
#pragma unroll
            for (int e = 0; e < 4; e++) acc[r][t][e] = 0.f;

    int kl = (lane & 7) + (lane >> 4) * 8;
    int cbit = ((lane >> 3) & 1) * 8;
    uint32_t aoff0 = (uint32_t)((kl * 136 + ig * 32 + cbit) * 2);
    uint32_t aoff1 = aoff0 + 32;
    uint32_t boff = (uint32_t)((kl * 136 + jg * 64 + cbit) * 2);

    // issue chunk loads: 2048 x 16B per chunk, 8 per thread
#define LOAD_CHUNK(k0, bufb) do {                                              \
        _Pragma("unroll")                                                      \
        for (int it = 0; it < 8; it++) {                                       \
            int t2 = tid + it * 256;                                           \
            int p = t2 >> 9, rem = t2 & 511;                                   \
            int r = rem >> 4, s = rem & 15;                                    \
            const unsigned short* sp = (p == 0) ? s0 : (p == 1) ? s1           \
                                      : (p == 2) ? s2 : s3;                    \
            cp16((bufb) + p * 8704 + r * 272 + s * 16,                         \
                 sp + (size_t)((k0) + r) * NDIM + s * 8);                      \
        }                                                                      \
        CP_COMMIT();                                                           \
    } while (0)

    LOAD_CHUNK(0, sb);
    LOAD_CHUNK(32, sb + CH_BUF);

    for (int c = 0; c < 12; c++) {
        if (c < 11) asm volatile("cp.async.wait_group 1;" ::: "memory");
        else        asm volatile("cp.async.wait_group 0;" ::: "memory");
        __syncthreads();
        uint32_t bufb = sb + (c & 1) * CH_BUF;
#pragma unroll
        for (int ks = 0; ks < 2; ks++) {
            uint32_t aH0[4], aH1[4], aL0[4], aL1[4];
            ldsm4t(aH0, bufb + 0     + aoff0 + ks * 4352);
            ldsm4t(aH1, bufb + 0     + aoff1 + ks * 4352);
            ldsm4t(aL0, bufb + 8704  + aoff0 + ks * 4352);
            ldsm4t(aL1, bufb + 8704  + aoff1 + ks * 4352);
#pragma unroll
            for (int g = 0; g < 4; g++) {
                uint32_t bH[4], bL[4];
                uint32_t bo = boff + g * 32 + ks * 4352;
                ldsm4t(bH, bufb + 17408 + bo);
                ldsm4t(bL, bufb + 26112 + bo);
                mma16816(acc[0][2 * g],     aH0, bH[0], bH[2]);
                mma16816(acc[0][2 * g + 1], aH0, bH[1], bH[3]);
                mma16816(acc[0][2 * g],     aH0, bL[0], bL[2]);
                mma16816(acc[0][2 * g + 1], aH0, bL[1], bL[3]);
                mma16816(acc[0][2 * g],     aL0, bH[0], bH[2]);
                mma16816(acc[0][2 * g + 1], aL0, bH[1], bH[3]);
                mma16816(acc[1][2 * g],     aH1, bH[0], bH[2]);
                mma16816(acc[1][2 * g + 1], aH1, bH[1], bH[3]);
                mma16816(acc[1][2 * g],     aH1, bL[0], bL[2]);
                mma16816(acc[1][2 * g + 1], aH1, bL[1], bL[3]);
                mma16816(acc[1][2 * g],     aL1, bH[0], bH[2]);
                mma16816(acc[1][2 * g + 1], aL1, bH[1], bH[3]);
            }
        }
        __syncthreads();
        if (c + 2 < 12) LOAD_CHUNK((c + 2) * 32, sb + (c & 1) * CH_BUF);
    }
#undef LOAD_CHUNK

    float* stg = (float*)sm;   // 128 x 132 floats
    {
        int q = lane >> 2, m = lane & 3;
#pragma unroll
        for (int r = 0; r < 2; r++)
#pragma unroll
            for (int t = 0; t < 8; t++) {
                int row1 = ig * 32 + r * 16 + q, row2 = row1 + 8;
                int col = jg * 64 + (t >> 1) * 16 + (t & 1) * 8 + 2 * m;
                stg[row1 * 132 + col]     = acc[r][t][0];
                stg[row1 * 132 + col + 1] = acc[r][t][1];
                stg[row2 * 132 + col]     = acc[r][t][2];
                stg[row2 * 132 + col + 1] = acc[r][t][3];
            }
    }
    __syncthreads();
#pragma unroll
    for (int it = 0; it < 16; it++) {
        int idx = (tid + it * 256) * 4;
        int row = idx >> 7, col = idx & 127;
        float4 v = *(float4*)(stg + row * 132 + col);
        int igl = ibase + row, jgl = jbase + col;
        float4 mk = *(const float4*)(mask + (size_t)igl * NDIM + jgl);
        v.x *= mk.x; v.y *= mk.y; v.z *= mk.z; v.w *= mk.w;
        *(float4*)(g_ct + (size_t)ch * NN + (size_t)igl * NDIM + jgl) = v;
    }
}

// ===================== Stage 4: transpose + LN + proj_o + gate =====================
#define KO_STG 0
#define KO_ZH  33792
#define KO_ZL  51200
#define KO_TOT 68608

__global__ void __launch_bounds__(256, 2) k_out(
    const float* __restrict__ lnw, const float* __restrict__ lnb,
    const float* __restrict__ bo, float* __restrict__ out)
{
    extern __shared__ char sm[];
    uint32_t sb = smem_u32(sm);
    int tid = threadIdx.x, w = tid >> 5, lane = tid & 31;
    int rg = w & 3, chalf = w >> 2;
    int r0 = blockIdx.x * 64;
    float* stg = (float*)(sm + KO_STG);   // 64 x 132 floats

    // transposed load of g_ct with per-row channel rotation (rot = r & 124)
#pragma unroll
    for (int it = 0; it < 8; it++) {
        int linear = tid + it * 256;
        int c = linear >> 4;
        int r = (linear & 15) * 4;
        float4 v = *(const float4*)(g_ct + (size_t)c * NN + r0 + r);
        stg[(r + 0) * 132 + ((c + ((r + 0) & 124)) & 127)] = v.x;
        stg[(r + 1) * 132 + ((c + ((r + 1) & 124)) & 127)] = v.y;
        stg[(r + 2) * 132 + ((c + ((r + 2) & 124)) & 127)] = v.z;
        stg[(r + 3) * 132 + ((c + ((r + 3) & 124)) & 127)] = v.w;
    }
    __syncthreads();

    // LayerNorm rows (8 per warp) -> bf16 hi/lo planes
    {
        float4 wv = ((const float4*)lnw)[lane];
        float4 bv = ((const float4*)lnb)[lane];
#pragma unroll
        for (int rr = 0; rr < 8; rr++) {
            int row = w * 8 + rr;
            int pos = (lane * 4 + (row & 124)) & 127;
            float4 v = *(float4*)(stg + row * 132 + pos);
            float s1 = v.x + v.y + v.z + v.w;
            float s2 = v.x * v.x + v.y * v.y + v.z * v.z + v.w * v.w;
#pragma unroll
            for (int o = 16; o; o >>= 1) {
                s1 += __shfl_xor_sync(0xffffffffu, s1, o);
                s2 += __shfl_xor_sync(0xffffffffu, s2, o);
            }
            float mn = s1 * (1.f / 128.f);
            float var = fmaxf(s2 * (1.f / 128.f) - mn * mn, 0.f);
            float rs = rsqrtf(var + EPS);
            v.x = (v.x - mn) * rs * wv.x + bv.x;
            v.y = (v.y - mn) * rs * wv.y + bv.y;
            v.z = (v.z - mn) * rs * wv.z + bv.z;
            v.w = (v.w - mn) * rs * wv.w + bv.w;
            *(uint2*)(sm + KO_ZH + row * 272 + lane * 8) =
                make_uint2(pack2h(v.x, v.y), pack2h(v.z, v.w));
            *(uint2*)(sm + KO_ZL + row * 272 + lane * 8) =
                make_uint2(pack2h(lopart(v.x), lopart(v.y)),
                           pack2h(lopart(v.z), lopart(v.w)));
        }
    }
    __syncthreads();

    uint32_t aoff = (uint32_t)(((rg * 16 + (lane & 15)) * 136 + (lane >> 4) * 8) * 2);
    uint32_t aH[8][4];
#pragma unroll
    for (int ks = 0; ks < 8; ks++) ldsm4(aH[ks], sb + KO_ZH + aoff + ks * 32);

    float P[8][4];
    wg_glob(aH, sb + KO_ZL, aoff, g_wfrag + 5 * 4096 + (chalf * 8) * 32 + lane, P);

    // epilogue: bias + gate, direct store
    {
        int q = lane >> 2, m = lane & 3;
        int r1 = r0 + rg * 16 + q, r2 = r1 + 8;
#pragma unroll
        for (int t = 0; t < 8; t++) {
            int cc = chalf * 64 + t * 8 + 2 * m;
            float b0 = __ldg(bo + cc), b1 = __ldg(bo + cc + 1);
            out[(size_t)r1 * C + cc]     = (P[t][0] + b0) * g_gate[(size_t)r1 * C + cc];
            out[(size_t)r1 * C + cc + 1] = (P[t][1] + b1) * g_gate[(size_t)r1 * C + cc + 1];
            out[(size_t)r2 * C + cc]     = (P[t][2] + b0) * g_gate[(size_t)r2 * C + cc];
            out[(size_t)r2 * C + cc + 1] = (P[t][3] + b1) * g_gate[(size_t)r2 * C + cc + 1];
        }
    }
}

extern "C" void kernel_launch(void* const* d_in, const int* in_sizes, int n_in,
                              void* d_out, int out_size) {
    const float* z    = (const float*)d_in[0];
    const float* mask = (const float*)d_in[1];
    const float* lniw = (const float*)d_in[2];
    const float* lnib = (const float*)d_in[3];
    const float* lnow = (const float*)d_in[4];
    const float* lnob = (const float*)d_in[5];
    const float* Wpa  = (const float*)d_in[6];
    const float* bpa  = (const float*)d_in[7];
    const float* Wga  = (const float*)d_in[8];
    const float* bga  = (const float*)d_in[9];
    const float* Wpb  = (const float*)d_in[10];
    const float* bpb  = (const float*)d_in[11];
    const float* Wgb  = (const float*)d_in[12];
    const float* bgb  = (const float*)d_in[13];
    const float* Wgo  = (const float*)d_in[14];
    const float* bgo  = (const float*)d_in[15];
    const float* Wpo  = (const float*)d_in[16];
    const float* bpo  = (const float*)d_in[17];
    float* out = (float*)d_out;

    cudaFuncSetAttribute(k_contract, cudaFuncAttributeMaxDynamicSharedMemorySize, CSM_TOT);
    cudaFuncSetAttribute(k_out, cudaFuncAttributeMaxDynamicSharedMemorySize, KO_TOT);

    k_prep<<<96, 256>>>(Wpa, Wga, Wpb, Wgb, Wgo, Wpo);
    k_lin5<<<NN / 64, 256, L5_TOT>>>(z, mask, lniw, lnib, bpa, bga, bpb, bgb, bgo);
    k_contract<<<9 * C, 256, CSM_TOT>>>(mask);
    k_out<<<NN / 64, 256, KO_TOT>>>(lnow, lnob, bpo, out);
}

// round 9
// speedup vs baseline: 2.8651x; 1.2245x over previous
#include <cuda_runtime.h>
#include <cuda_fp16.h>
#include <math.h>
#include <stdint.h>

#define NDIM 384
#define C 128
#define NN (NDIM*NDIM)
#define EPS 1e-5f

// Scratch (allocation-free rule: __device__ globals)
// a (contract B operand): fp16 hi+lo planes; b (contract A operand): fp16 hi only.
__device__ __align__(16) unsigned short g_ah[(size_t)C * NN];
__device__ __align__(16) unsigned short g_al[(size_t)C * NN];
__device__ __align__(16) unsigned short g_bh[(size_t)C * NN];
__device__ float g_ct[(size_t)C * NN];    // contracted fp32: [c][i][j]
__device__ float g_gate[(size_t)NN * C];  // sigmoid(gate_o): [r][c]
// Weights as m16n8k16 B-fragments (fp16): [wsel][ks(8)][g(16)][lane(32)] -> (b0h,b1h,b0l,b1l)
__device__ uint4 g_wfrag[6 * 8 * 16 * 32];

__device__ __forceinline__ float sigmf(float x) { return 1.f / (1.f + __expf(-x)); }

__device__ __forceinline__ uint32_t smem_u32(const void* p) {
    uint32_t a;
    asm("{ .reg .u64 t; cvta.to.shared.u64 t, %1; cvt.u32.u64 %0, t; }" : "=r"(a) : "l"(p));
    return a;
}
__device__ __forceinline__ void ldsm4(uint32_t (&r)[4], uint32_t a) {
    asm volatile("ldmatrix.sync.aligned.m8n8.x4.shared.b16 {%0,%1,%2,%3}, [%4];"
                 : "=r"(r[0]), "=r"(r[1]), "=r"(r[2]), "=r"(r[3]) : "r"(a));
}
__device__ __forceinline__ void ldsm4t(uint32_t (&r)[4], uint32_t a) {
    asm volatile("ldmatrix.sync.aligned.m8n8.x4.trans.shared.b16 {%0,%1,%2,%3}, [%4];"
                 : "=r"(r[0]), "=r"(r[1]), "=r"(r[2]), "=r"(r[3]) : "r"(a));
}
__device__ __forceinline__ void mma16816(float (&c)[4], const uint32_t (&a)[4],
                                         uint32_t b0, uint32_t b1) {
    asm volatile("mma.sync.aligned.m16n8k16.row.col.f32.f16.f16.f32 "
                 "{%0,%1,%2,%3}, {%4,%5,%6,%7}, {%8,%9}, {%0,%1,%2,%3};"
                 : "+f"(c[0]), "+f"(c[1]), "+f"(c[2]), "+f"(c[3])
                 : "r"(a[0]), "r"(a[1]), "r"(a[2]), "r"(a[3]), "r"(b0), "r"(b1));
}
__device__ __forceinline__ void cp16(uint32_t dst, const void* src) {
    asm volatile("cp.async.cg.shared.global [%0], [%1], 16;" :: "r"(dst), "l"(src));
}
#define CP_COMMIT() asm volatile("cp.async.commit_group;" ::: "memory")

__device__ __forceinline__ uint32_t hfbits(float x) {
    __half h = __float2half_rn(x);
    return (uint32_t)*(unsigned short*)&h;
}
__device__ __forceinline__ float hff(uint32_t b) {
    unsigned short s = (unsigned short)b;
    __half h = *(__half*)&s;
    return __half2float(h);
}
__device__ __forceinline__ float hlopart(float x) { return x - hff(hfbits(x)); }
__device__ __forceinline__ uint32_t pack2hf(float a, float b) {
    return hfbits(a) | (hfbits(b) << 16);
}

// ===================== k_prep: weights -> fp16 MMA B-fragment layout =====================
__global__ void __launch_bounds__(256) k_prep(
    const float* __restrict__ W0, const float* __restrict__ W1,
    const float* __restrict__ W2, const float* __restrict__ W3,
    const float* __restrict__ W4, const float* __restrict__ W5)
{
    int gid = blockIdx.x * 256 + threadIdx.x;  // 24576 total
    int lane = gid & 31;
    int g = (gid >> 5) & 15;
    int ks = (gid >> 9) & 7;
    int wsel = gid >> 12;
    const float* W;
    switch (wsel) {
        case 0: W = W0; break;
        case 1: W = W1; break;
        case 2: W = W2; break;
        case 3: W = W3; break;
        case 4: W = W4; break;
        default: W = W5; break;
    }
    int n = g * 8 + (lane >> 2);
    int k0 = ks * 16 + (lane & 3) * 2;
    float w0 = W[n * 128 + k0],     w1 = W[n * 128 + k0 + 1];
    float w2 = W[n * 128 + k0 + 8], w3 = W[n * 128 + k0 + 9];
    g_wfrag[gid] = make_uint4(pack2hf(w0, w1), pack2hf(w2, w3),
                              pack2hf(hlopart(w0), hlopart(w1)),
                              pack2hf(hlopart(w2), hlopart(w3)));
}

// 2-combo gemm: A-hi in regs, W fragments (hi+lo) streamed from global (L2-resident)
__device__ __forceinline__ void wg_glob(const uint32_t (&aH)[8][4],
                                        const uint4* __restrict__ Wf, float (&acc)[8][4]) {
#pragma unroll
    for (int t = 0; t < 8; t++)
#pragma unroll
        for (int e = 0; e < 4; e++) acc[t][e] = 0.f;
#pragma unroll 2
    for (int ks = 0; ks < 8; ks++) {
#pragma unroll
        for (int g = 0; g < 8; g++) {
            uint4 f = __ldg(Wf + (ks * 16 + g) * 32);
            mma16816(acc[g], aH[ks], f.x, f.y);   // hi * W-hi
            mma16816(acc[g], aH[ks], f.z, f.w);   // hi * W-lo
        }
    }
}

// ===================== Stage 2: LN + 5 linears =====================
#define L5_TOT 17408

// combine + store a (fp16 hi+lo planes), channel-major
__device__ __forceinline__ void store_a2(float (&P)[8][4], float (&G)[8][4],
                                         const float* __restrict__ bp,
                                         const float* __restrict__ bg,
                                         const float* __restrict__ mask,
                                         int r0, int rg, int chalf, int lane)
{
    int q = lane >> 2, m = lane & 3;
    int r1 = r0 + rg * 16 + q, r2 = r1 + 8;
    float m1 = __ldg(mask + r1), m2 = __ldg(mask + r2);
#pragma unroll
    for (int t = 0; t < 8; t++) {
        int cc = chalf * 64 + t * 8 + 2 * m;
        float p0 = __ldg(bp + cc), p1 = __ldg(bp + cc + 1);
        float g0 = __ldg(bg + cc), g1 = __ldg(bg + cc + 1);
        float v0 = (P[t][0] + p0) * sigmf(G[t][0] + g0) * m1;
        float v1 = (P[t][1] + p1) * sigmf(G[t][1] + g1) * m1;
        float v2 = (P[t][2] + p0) * sigmf(G[t][2] + g0) * m2;
        float v3 = (P[t][3] + p1) * sigmf(G[t][3] + g1) * m2;
        uint32_t h0 = hfbits(v0), h1 = hfbits(v1), h2 = hfbits(v2), h3 = hfbits(v3);
        size_t o0 = (size_t)cc * NN + r1, o1 = (size_t)(cc + 1) * NN + r1;
        size_t o2 = (size_t)cc * NN + r2, o3 = (size_t)(cc + 1) * NN + r2;
        g_ah[o0] = (unsigned short)h0; g_al[o0] = (unsigned short)hfbits(v0 - hff(h0));
        g_ah[o1] = (unsigned short)h1; g_al[o1] = (unsigned short)hfbits(v1 - hff(h1));
        g_ah[o2] = (unsigned short)h2; g_al[o2] = (unsigned short)hfbits(v2 - hff(h2));
        g_ah[o3] = (unsigned short)h3; g_al[o3] = (unsigned short)hfbits(v3 - hff(h3));
    }
}

// combine + store b (fp16 hi only), channel-major
__device__ __forceinline__ void store_b1(float (&P)[8][4], float (&G)[8][4],
                                         const float* __restrict__ bp,
                                         const float* __restrict__ bg,
                                         const float* __restrict__ mask,
                                         int r0, int rg, int chalf, int lane)
{
    int q = lane >> 2, m = lane & 3;
    int r1 = r0 + rg * 16 + q, r2 = r1 + 8;
    float m1 = __ldg(mask + r1), m2 = __ldg(mask + r2);
#pragma unroll
    for (int t = 0; t < 8; t++) {
        int cc = chalf * 64 + t * 8 + 2 * m;
        float p0 = __ldg(bp + cc), p1 = __ldg(bp + cc + 1);
        float g0 = __ldg(bg + cc), g1 = __ldg(bg + cc + 1);
        g_bh[(size_t)cc * NN + r1]       = (unsigned short)hfbits((P[t][0] + p0) * sigmf(G[t][0] + g0) * m1);
        g_bh[(size_t)(cc + 1) * NN + r1] = (unsigned short)hfbits((P[t][1] + p1) * sigmf(G[t][1] + g1) * m1);
        g_bh[(size_t)cc * NN + r2]       = (unsigned short)hfbits((P[t][2] + p0) * sigmf(G[t][2] + g0) * m2);
        g_bh[(size_t)(cc + 1) * NN + r2] = (unsigned short)hfbits((P[t][3] + p1) * sigmf(G[t][3] + g1) * m2);
    }
}

__global__ void __launch_bounds__(256, 2) k_lin5(
    const float* __restrict__ z, const float* __restrict__ mask,
    const float* __restrict__ lnw, const float* __restrict__ lnb,
    const float* __restrict__ bpa, const float* __restrict__ bga,
    const float* __restrict__ bpb, const float* __restrict__ bgb,
    const float* __restrict__ bgo)
{
    extern __shared__ char sm[];
    uint32_t sb = smem_u32(sm);
    int tid = threadIdx.x, w = tid >> 5, lane = tid & 31;
    int rg = w & 3, chalf = w >> 2;
    int r0 = blockIdx.x * 64;

    // LayerNorm -> fp16 hi plane (warp handles 8 rows)
    {
        float4 wv = ((const float4*)lnw)[lane];
        float4 bv = ((const float4*)lnb)[lane];
#pragma unroll
        for (int rr = 0; rr < 8; rr++) {
            int row = w * 8 + rr;
            float4 v = *(const float4*)(z + (size_t)(r0 + row) * C + lane * 4);
            float s1 = v.x + v.y + v.z + v.w;
            float s2 = v.x * v.x + v.y * v.y + v.z * v.z + v.w * v.w;
#pragma unroll
            for (int o = 16; o; o >>= 1) {
                s1 += __shfl_xor_sync(0xffffffffu, s1, o);
                s2 += __shfl_xor_sync(0xffffffffu, s2, o);
            }
            float mn = s1 * (1.f / 128.f);
            float var = fmaxf(s2 * (1.f / 128.f) - mn * mn, 0.f);
            float rs = rsqrtf(var + EPS);
            v.x = (v.x - mn) * rs * wv.x + bv.x;
            v.y = (v.y - mn) * rs * wv.y + bv.y;
            v.z = (v.z - mn) * rs * wv.z + bv.z;
            v.w = (v.w - mn) * rs * wv.w + bv.w;
            *(uint2*)(sm + row * 272 + lane * 8) =
                make_uint2(pack2hf(v.x, v.y), pack2hf(v.z, v.w));
        }
    }
    __syncthreads();

    uint32_t aoff = (uint32_t)(((rg * 16 + (lane & 15)) * 136 + (lane >> 4) * 8) * 2);

    // preload A-hi fragments (reused across all 5 gemms)
    uint32_t aH[8][4];
#pragma unroll
    for (int ks = 0; ks < 8; ks++) ldsm4(aH[ks], sb + aoff + ks * 32);

    const uint4* WfBase = g_wfrag + (chalf * 8) * 32 + lane;
    float P[8][4], G[8][4];

    // branch a (hi+lo planes)
    wg_glob(aH, WfBase + 0 * 4096, P);
    wg_glob(aH, WfBase + 1 * 4096, G);
    store_a2(P, G, bpa, bga, mask, r0, rg, chalf, lane);

    // branch b (hi only)
    wg_glob(aH, WfBase + 2 * 4096, P);
    wg_glob(aH, WfBase + 3 * 4096, G);
    store_b1(P, G, bpb, bgb, mask, r0, rg, chalf, lane);

    // gate_o -> g_gate [r][c] fp32 direct
    wg_glob(aH, WfBase + 4 * 4096, P);
    {
        int q = lane >> 2, m = lane & 3;
        int r1 = r0 + rg * 16 + q, r2 = r1 + 8;
#pragma unroll
        for (int t = 0; t < 8; t++) {
            int cc = chalf * 64 + t * 8 + 2 * m;
            float b0 = __ldg(bgo + cc), b1 = __ldg(bgo + cc + 1);
            g_gate[(size_t)r1 * C + cc]     = sigmf(P[t][0] + b0);
            g_gate[(size_t)r1 * C + cc + 1] = sigmf(P[t][1] + b1);
            g_gate[(size_t)r2 * C + cc]     = sigmf(P[t][2] + b0);
            g_gate[(size_t)r2 * C + cc + 1] = sigmf(P[t][3] + b1);
        }
    }
}

// ===================== Stage 3: contraction, cp.async pipelined, fp16x2 ==========
// Chunk = 32 k-rows. Planes per chunk: A(bh), Bh(ah), Bl(al), 8704 B each.
#define CH_BUF 26112
#define CSM_TOT 69632

__global__ void __launch_bounds__(256, 2) k_contract(const float* __restrict__ mask) {
    extern __shared__ char sm[];
    uint32_t sb = smem_u32(sm);
    int tid = threadIdx.x, w = tid >> 5, lane = tid & 31;
    int blk = blockIdx.x;
    int bj = blk % 3, bi = (blk / 3) % 3, ch = blk / 9;
    int ibase = bi * 128, jbase = bj * 128;
    // A operand = b-hi (i-axis), B operand = a hi+lo (j-axis)
    const unsigned short* s0 = g_bh + (size_t)ch * NN + ibase;
    const unsigned short* s1 = g_ah + (size_t)ch * NN + jbase;
    const unsigned short* s2 = g_al + (size_t)ch * NN + jbase;
    int ig = w & 3, jg = w >> 2;   // 4 i-groups x 2 j-groups

    float acc[2][8][4];
#pragma unroll
    for (int r = 0; r < 2; r++)
#pragma unroll
        for (int t = 0; t < 8; t++)
#pragma unroll
            for (int e = 0; e < 4; e++) acc[r][t][e] = 0.f;

    int kl = (lane & 7) + (lane >> 4) * 8;
    int cbit = ((lane >> 3) & 1) * 8;
    uint32_t aoff0 = (uint32_t)((kl * 136 + ig * 32 + cbit) * 2);
    uint32_t aoff1 = aoff0 + 32;
    uint32_t boff = (uint32_t)((kl * 136 + jg * 64 + cbit) * 2);

    // issue chunk loads: 1536 x 16B per chunk, 6 per thread
#define LOAD_CHUNK(k0, bufb) do {                                              \
        _Pragma("unroll")                                                      \
        for (int it = 0; it < 6; it++) {                                       \
            int t2 = tid + it * 256;                                           \
            int p = t2 >> 9, rem = t2 & 511;                                   \
            int r = rem >> 4, s = rem & 15;                                    \
            const unsigned short* sp = (p == 0) ? s0 : (p == 1) ? s1 : s2;     \
            cp16((bufb) + p * 8704 + r * 272 + s * 16,                         \
                 sp + (size_t)((k0) + r) * NDIM + s * 8);                      \
        }                                                                      \
        CP_COMMIT();                                                           \
    } while (0)

    LOAD_CHUNK(0, sb);
    LOAD_CHUNK(32, sb + CH_BUF);

    for (int c = 0; c < 12; c++) {
        if (c < 11) asm volatile("cp.async.wait_group 1;" ::: "memory");
        else        asm volatile("cp.async.wait_group 0;" ::: "memory");
        __syncthreads();
        uint32_t bufb = sb + (c & 1) * CH_BUF;
#pragma unroll
        for (int ks = 0; ks < 2; ks++) {
            uint32_t A0[4], A1[4];
            ldsm4t(A0, bufb + aoff0 + ks * 4352);
            ldsm4t(A1, bufb + aoff1 + ks * 4352);
#pragma unroll
            for (int g = 0; g < 4; g++) {
                uint32_t bH[4], bL[4];
                uint32_t bo = boff + g * 32 + ks * 4352;
                ldsm4t(bH, bufb + 8704  + bo);
                ldsm4t(bL, bufb + 17408 + bo);
                mma16816(acc[0][2 * g],     A0, bH[0], bH[2]);
                mma16816(acc[0][2 * g + 1], A0, bH[1], bH[3]);
                mma16816(acc[0][2 * g],     A0, bL[0], bL[2]);
                mma16816(acc[0][2 * g + 1], A0, bL[1], bL[3]);
                mma16816(acc[1][2 * g],     A1, bH[0], bH[2]);
                mma16816(acc[1][2 * g + 1], A1, bH[1], bH[3]);
                mma16816(acc[1][2 * g],     A1, bL[0], bL[2]);
                mma16816(acc[1][2 * g + 1], A1, bL[1], bL[3]);
            }
        }
        __syncthreads();
        if (c + 2 < 12) LOAD_CHUNK((c + 2) * 32, sb + (c & 1) * CH_BUF);
    }
#undef LOAD_CHUNK

    float* stg = (float*)sm;   // 128 x 132 floats
    {
        int q = lane >> 2, m = lane & 3;
#pragma unroll
        for (int r = 0; r < 2; r++)
#pragma unroll
            for (int t = 0; t < 8; t++) {
                int row1 = ig * 32 + r * 16 + q, row2 = row1 + 8;
                int col = jg * 64 + (t >> 1) * 16 + (t & 1) * 8 + 2 * m;
                stg[row1 * 132 + col]     = acc[r][t][0];
                stg[row1 * 132 + col + 1] = acc[r][t][1];
                stg[row2 * 132 + col]     = acc[r][t][2];
                stg[row2 * 132 + col + 1] = acc[r][t][3];
            }
    }
    __syncthreads();
#pragma unroll
    for (int it = 0; it < 16; it++) {
        int idx = (tid + it * 256) * 4;
        int row = idx >> 7, col = idx & 127;
        float4 v = *(float4*)(stg + row * 132 + col);
        int igl = ibase + row, jgl = jbase + col;
        float4 mk = *(const float4*)(mask + (size_t)igl * NDIM + jgl);
        v.x *= mk.x; v.y *= mk.y; v.z *= mk.z; v.w *= mk.w;
        *(float4*)(g_ct + (size_t)ch * NN + (size_t)igl * NDIM + jgl) = v;
    }
}

// ===================== Stage 4: transpose + LN + proj_o + gate =====================
#define KO_STG 0
#define KO_ZH  33792
#define KO_TOT 51200

__global__ void __launch_bounds__(256, 2) k_out(
    const float* __restrict__ lnw, const float* __restrict__ lnb,
    const float* __restrict__ bo, float* __restrict__ out)
{
    extern __shared__ char sm[];
    uint32_t sb = smem_u32(sm);
    int tid = threadIdx.x, w = tid >> 5, lane = tid & 31;
    int rg = w & 3, chalf = w >> 2;
    int r0 = blockIdx.x * 64;
    float* stg = (float*)(sm + KO_STG);   // 64 x 132 floats

    // transposed load of g_ct with per-row channel rotation (rot = r & 124)
#pragma unroll
    for (int it = 0; it < 8; it++) {
        int linear = tid + it * 256;
        int c = linear >> 4;
        int r = (linear & 15) * 4;
        float4 v = *(const float4*)(g_ct + (size_t)c * NN + r0 + r);
        stg[(r + 0) * 132 + ((c + ((r + 0) & 124)) & 127)] = v.x;
        stg[(r + 1) * 132 + ((c + ((r + 1) & 124)) & 127)] = v.y;
        stg[(r + 2) * 132 + ((c + ((r + 2) & 124)) & 127)] = v.z;
        stg[(r + 3) * 132 + ((c + ((r + 3) & 124)) & 127)] = v.w;
    }
    __syncthreads();

    // LayerNorm rows (8 per warp) -> fp16 hi plane
    {
        float4 wv = ((const float4*)lnw)[lane];
        float4 bv = ((const float4*)lnb)[lane];
#pragma unroll
        for (int rr = 0; rr < 8; rr++) {
            int row = w * 8 + rr;
            int pos = (lane * 4 + (row & 124)) & 127;
            float4 v = *(float4*)(stg + row * 132 + pos);
            float s1 = v.x + v.y + v.z + v.w;
            float s2 = v.x * v.x + v.y * v.y + v.z * v.z + v.w * v.w;
#pragma unroll
            for (int o = 16; o; o >>= 1) {
                s1 += __shfl_xor_sync(0xffffffffu, s1, o);
                s2 += __shfl_xor_sync(0xffffffffu, s2, o);
            }
            float mn = s1 * (1.f / 128.f);
            float var = fmaxf(s2 * (1.f / 128.f) - mn * mn, 0.f);
            float rs = rsqrtf(var + EPS);
            v.x = (v.x - mn) * rs * wv.x + bv.x;
            v.y = (v.y - mn) * rs * wv.y + bv.y;
            v.z = (v.z - mn) * rs * wv.z + bv.z;
            v.w = (v.w - mn) * rs * wv.w + bv.w;
            *(uint2*)(sm + KO_ZH + row * 272 + lane * 8) =
                make_uint2(pack2hf(v.x, v.y), pack2hf(v.z, v.w));
        }
    }
    __syncthreads();

    uint32_t aoff = (uint32_t)(((rg * 16 + (lane & 15)) * 136 + (lane >> 4) * 8) * 2);
    uint32_t aH[8][4];
#pragma unroll
    for (int ks = 0; ks < 8; ks++) ldsm4(aH[ks], sb + KO_ZH + aoff + ks * 32);

    float P[8][4];
    wg_glob(aH, g_wfrag + 5 * 4096 + (chalf * 8) * 32 + lane, P);

    // epilogue: bias + gate, direct store
    {
        int q = lane >> 2, m = lane & 3;
        int r1 = r0 + rg * 16 + q, r2 = r1 + 8;
#pragma unroll
        for (int t = 0; t < 8; t++) {
            int cc = chalf * 64 + t * 8 + 2 * m;
            float b0 = __ldg(bo + cc), b1 = __ldg(bo + cc + 1);
            out[(size_t)r1 * C + cc]     = (P[t][0] + b0) * g_gate[(size_t)r1 * C + cc];
            out[(size_t)r1 * C + cc + 1] = (P[t][1] + b1) * g_gate[(size_t)r1 * C + cc + 1];
            out[(size_t)r2 * C + cc]     = (P[t][2] + b0) * g_gate[(size_t)r2 * C + cc];
            out[(size_t)r2 * C + cc + 1] = (P[t][3] + b1) * g_gate[(size_t)r2 * C + cc + 1];
        }
    }
}

extern "C" void kernel_launch(void* const* d_in, const int* in_sizes, int n_in,
                              void* d_out, int out_size) {
    const float* z    = (const float*)d_in[0];
    const float* mask = (const float*)d_in[1];
    const float* lniw = (const float*)d_in[2];
    const float* lnib = (const float*)d_in[3];
    const float* lnow = (const float*)d_in[4];
    const float* lnob = (const float*)d_in[5];
    const float* Wpa  = (const float*)d_in[6];
    const float* bpa  = (const float*)d_in[7];
    const float* Wga  = (const float*)d_in[8];
    const float* bga  = (const float*)d_in[9];
    const float* Wpb  = (const float*)d_in[10];
    const float* bpb  = (const float*)d_in[11];
    const float* Wgb  = (const float*)d_in[12];
    const float* bgb  = (const float*)d_in[13];
    const float* Wgo  = (const float*)d_in[14];
    const float* bgo  = (const float*)d_in[15];
    const float* Wpo  = (const float*)d_in[16];
    const float* bpo  = (const float*)d_in[17];
    float* out = (float*)d_out;

    cudaFuncSetAttribute(k_contract, cudaFuncAttributeMaxDynamicSharedMemorySize, CSM_TOT);
    cudaFuncSetAttribute(k_out, cudaFuncAttributeMaxDynamicSharedMemorySize, KO_TOT);

    k_prep<<<96, 256>>>(Wpa, Wga, Wpb, Wgb, Wgo, Wpo);
    k_lin5<<<NN / 64, 256, L5_TOT>>>(z, mask, lniw, lnib, bpa, bga, bpb, bgb, bgo);
    k_contract<<<9 * C, 256, CSM_TOT>>>(mask);
    k_out<<<NN / 64, 256, KO_TOT>>>(lnow, lnob, bpo, out);
}

// round 10
// speedup vs baseline: 2.9840x; 1.0415x over previous
#include <cuda_runtime.h>
#include <cuda_fp16.h>
#include <math.h>
#include <stdint.h>

#define NDIM 384
#define C 128
#define NN (NDIM*NDIM)
#define EPS 1e-5f

// Scratch (allocation-free rule: __device__ globals)
// a (contract B operand): fp16 hi+lo planes; b (contract A operand): fp16 hi only.
__device__ __align__(16) unsigned short g_ah[(size_t)C * NN];
__device__ __align__(16) unsigned short g_al[(size_t)C * NN];
__device__ __align__(16) unsigned short g_bh[(size_t)C * NN];
__device__ __align__(16) unsigned short g_ct[(size_t)C * NN];   // contracted fp16: [c][i][j]
__device__ __align__(16) unsigned short g_gate[(size_t)NN * C]; // sigmoid(gate_o) fp16: [r][c]
// Weights as m16n8k16 B-fragments (fp16): [wsel][ks(8)][g(16)][lane(32)] -> (b0h,b1h,b0l,b1l)
__device__ uint4 g_wfrag[6 * 8 * 16 * 32];

__device__ __forceinline__ float sigmf(float x) { return 1.f / (1.f + __expf(-x)); }

__device__ __forceinline__ uint32_t smem_u32(const void* p) {
    uint32_t a;
    asm("{ .reg .u64 t; cvta.to.shared.u64 t, %1; cvt.u32.u64 %0, t; }" : "=r"(a) : "l"(p));
    return a;
}
__device__ __forceinline__ void ldsm4(uint32_t (&r)[4], uint32_t a) {
    asm volatile("ldmatrix.sync.aligned.m8n8.x4.shared.b16 {%0,%1,%2,%3}, [%4];"
                 : "=r"(r[0]), "=r"(r[1]), "=r"(r[2]), "=r"(r[3]) : "r"(a));
}
__device__ __forceinline__ void ldsm4t(uint32_t (&r)[4], uint32_t a) {
    asm volatile("ldmatrix.sync.aligned.m8n8.x4.trans.shared.b16 {%0,%1,%2,%3}, [%4];"
                 : "=r"(r[0]), "=r"(r[1]), "=r"(r[2]), "=r"(r[3]) : "r"(a));
}
__device__ __forceinline__ void mma16816(float (&c)[4], const uint32_t (&a)[4],
                                         uint32_t b0, uint32_t b1) {
    asm volatile("mma.sync.aligned.m16n8k16.row.col.f32.f16.f16.f32 "
                 "{%0,%1,%2,%3}, {%4,%5,%6,%7}, {%8,%9}, {%0,%1,%2,%3};"
                 : "+f"(c[0]), "+f"(c[1]), "+f"(c[2]), "+f"(c[3])
                 : "r"(a[0]), "r"(a[1]), "r"(a[2]), "r"(a[3]), "r"(b0), "r"(b1));
}
__device__ __forceinline__ void cp16(uint32_t dst, const void* src) {
    asm volatile("cp.async.cg.shared.global [%0], [%1], 16;" :: "r"(dst), "l"(src));
}
#define CP_COMMIT() asm volatile("cp.async.commit_group;" ::: "memory")

__device__ __forceinline__ uint32_t hfbits(float x) {
    __half h = __float2half_rn(x);
    return (uint32_t)*(unsigned short*)&h;
}
__device__ __forceinline__ float hff(uint32_t b) {
    unsigned short s = (unsigned short)b;
    __half h = *(__half*)&s;
    return __half2float(h);
}
__device__ __forceinline__ float hlopart(float x) { return x - hff(hfbits(x)); }
__device__ __forceinline__ uint32_t pack2hf(float a, float b) {
    return hfbits(a) | (hfbits(b) << 16);
}

// ===================== k_prep: weights -> fp16 MMA B-fragment layout =====================
__global__ void __launch_bounds__(256) k_prep(
    const float* __restrict__ W0, const float* __restrict__ W1,
    const float* __restrict__ W2, const float* __restrict__ W3,
    const float* __restrict__ W4, const float* __restrict__ W5)
{
    int gid = blockIdx.x * 256 + threadIdx.x;  // 24576 total
    int lane = gid & 31;
    int g = (gid >> 5) & 15;
    int ks = (gid >> 9) & 7;
    int wsel = gid >> 12;
    const float* W;
    switch (wsel) {
        case 0: W = W0; break;
        case 1: W = W1; break;
        case 2: W = W2; break;
        case 3: W = W3; break;
        case 4: W = W4; break;
        default: W = W5; break;
    }
    int n = g * 8 + (lane >> 2);
    int k0 = ks * 16 + (lane & 3) * 2;
    float w0 = W[n * 128 + k0],     w1 = W[n * 128 + k0 + 1];
    float w2 = W[n * 128 + k0 + 8], w3 = W[n * 128 + k0 + 9];
    g_wfrag[gid] = make_uint4(pack2hf(w0, w1), pack2hf(w2, w3),
                              pack2hf(hlopart(w0), hlopart(w1)),
                              pack2hf(hlopart(w2), hlopart(w3)));
}

// 2-combo gemm: A-hi in regs, W fragments (hi+lo) streamed from global (L2-resident)
__device__ __forceinline__ void wg_glob(const uint32_t (&aH)[8][4],
                                        const uint4* __restrict__ Wf, float (&acc)[8][4]) {
#pragma unroll
    for (int t = 0; t < 8; t++)
#pragma unroll
        for (int e = 0; e < 4; e++) acc[t][e] = 0.f;
#pragma unroll 2
    for (int ks = 0; ks < 8; ks++) {
#pragma unroll
        for (int g = 0; g < 8; g++) {
            uint4 f = __ldg(Wf + (ks * 16 + g) * 32);
            mma16816(acc[g], aH[ks], f.x, f.y);   // hi * W-hi
            mma16816(acc[g], aH[ks], f.z, f.w);   // hi * W-lo
        }
    }
}

// ===================== Stage 2: LN + 5 linears =====================
#define L5_TOT 17408

// combine + store a (fp16 hi+lo planes), channel-major
__device__ __forceinline__ void store_a2(float (&P)[8][4], float (&G)[8][4],
                                         const float* __restrict__ bp,
                                         const float* __restrict__ bg,
                                         const float* __restrict__ mask,
                                         int r0, int rg, int chalf, int lane)
{
    int q = lane >> 2, m = lane & 3;
    int r1 = r0 + rg * 16 + q, r2 = r1 + 8;
    float m1 = __ldg(mask + r1), m2 = __ldg(mask + r2);
#pragma unroll
    for (int t = 0; t < 8; t++) {
        int cc = chalf * 64 + t * 8 + 2 * m;
        float p0 = __ldg(bp + cc), p1 = __ldg(bp + cc + 1);
        float g0 = __ldg(bg + cc), g1 = __ldg(bg + cc + 1);
        float v0 = (P[t][0] + p0) * sigmf(G[t][0] + g0) * m1;
        float v1 = (P[t][1] + p1) * sigmf(G[t][1] + g1) * m1;
        float v2 = (P[t][2] + p0) * sigmf(G[t][2] + g0) * m2;
        float v3 = (P[t][3] + p1) * sigmf(G[t][3] + g1) * m2;
        uint32_t h0 = hfbits(v0), h1 = hfbits(v1), h2 = hfbits(v2), h3 = hfbits(v3);
        size_t o0 = (size_t)cc * NN + r1, o1 = (size_t)(cc + 1) * NN + r1;
        size_t o2 = (size_t)cc * NN + r2, o3 = (size_t)(cc + 1) * NN + r2;
        g_ah[o0] = (unsigned short)h0; g_al[o0] = (unsigned short)hfbits(v0 - hff(h0));
        g_ah[o1] = (unsigned short)h1; g_al[o1] = (unsigned short)hfbits(v1 - hff(h1));
        g_ah[o2] = (unsigned short)h2; g_al[o2] = (unsigned short)hfbits(v2 - hff(h2));
        g_ah[o3] = (unsigned short)h3; g_al[o3] = (unsigned short)hfbits(v3 - hff(h3));
    }
}

// combine + store b (fp16 hi only), channel-major
__device__ __forceinline__ void store_b1(float (&P)[8][4], float (&G)[8][4],
                                         const float* __restrict__ bp,
                                         const float* __restrict__ bg,
                                         const float* __restrict__ mask,
                                         int r0, int rg, int chalf, int lane)
{
    int q = lane >> 2, m = lane & 3;
    int r1 = r0 + rg * 16 + q, r2 = r1 + 8;
    float m1 = __ldg(mask + r1), m2 = __ldg(mask + r2);
#pragma unroll
    for (int t = 0; t < 8; t++) {
        int cc = chalf * 64 + t * 8 + 2 * m;
        float p0 = __ldg(bp + cc), p1 = __ldg(bp + cc + 1);
        float g0 = __ldg(bg + cc), g1 = __ldg(bg + cc + 1);
        g_bh[(size_t)cc * NN + r1]       = (unsigned short)hfbits((P[t][0] + p0) * sigmf(G[t][0] + g0) * m1);
        g_bh[(size_t)(cc + 1) * NN + r1] = (unsigned short)hfbits((P[t][1] + p1) * sigmf(G[t][1] + g1) * m1);
        g_bh[(size_t)cc * NN + r2]       = (unsigned short)hfbits((P[t][2] + p0) * sigmf(G[t][2] + g0) * m2);
        g_bh[(size_t)(cc + 1) * NN + r2] = (unsigned short)hfbits((P[t][3] + p1) * sigmf(G[t][3] + g1) * m2);
    }
}

__global__ void __launch_bounds__(256, 2) k_lin5(
    const float* __restrict__ z, const float* __restrict__ mask,
    const float* __restrict__ lnw, const float* __restrict__ lnb,
    const float* __restrict__ bpa, const float* __restrict__ bga,
    const float* __restrict__ bpb, const float* __restrict__ bgb,
    const float* __restrict__ bgo)
{
    extern __shared__ char sm[];
    uint32_t sb = smem_u32(sm);
    int tid = threadIdx.x, w = tid >> 5, lane = tid & 31;
    int rg = w & 3, chalf = w >> 2;
    int r0 = blockIdx.x * 64;

    // LayerNorm -> fp16 hi plane (warp handles 8 rows)
    {
        float4 wv = ((const float4*)lnw)[lane];
        float4 bv = ((const float4*)lnb)[lane];
#pragma unroll
        for (int rr = 0; rr < 8; rr++) {
            int row = w * 8 + rr;
            float4 v = *(const float4*)(z + (size_t)(r0 + row) * C + lane * 4);
            float s1 = v.x + v.y + v.z + v.w;
            float s2 = v.x * v.x + v.y * v.y + v.z * v.z + v.w * v.w;
#pragma unroll
            for (int o = 16; o; o >>= 1) {
                s1 += __shfl_xor_sync(0xffffffffu, s1, o);
                s2 += __shfl_xor_sync(0xffffffffu, s2, o);
            }
            float mn = s1 * (1.f / 128.f);
            float var = fmaxf(s2 * (1.f / 128.f) - mn * mn, 0.f);
            float rs = rsqrtf(var + EPS);
            v.x = (v.x - mn) * rs * wv.x + bv.x;
            v.y = (v.y - mn) * rs * wv.y + bv.y;
            v.z = (v.z - mn) * rs * wv.z + bv.z;
            v.w = (v.w - mn) * rs * wv.w + bv.w;
            *(uint2*)(sm + row * 272 + lane * 8) =
                make_uint2(pack2hf(v.x, v.y), pack2hf(v.z, v.w));
        }
    }
    __syncthreads();

    uint32_t aoff = (uint32_t)(((rg * 16 + (lane & 15)) * 136 + (lane >> 4) * 8) * 2);

    // preload A-hi fragments (reused across all 5 gemms)
    uint32_t aH[8][4];
#pragma unroll
    for (int ks = 0; ks < 8; ks++) ldsm4(aH[ks], sb + aoff + ks * 32);

    const uint4* WfBase = g_wfrag + (chalf * 8) * 32 + lane;
    float P[8][4], G[8][4];

    // branch a (hi+lo planes)
    wg_glob(aH, WfBase + 0 * 4096, P);
    wg_glob(aH, WfBase + 1 * 4096, G);
    store_a2(P, G, bpa, bga, mask, r0, rg, chalf, lane);

    // branch b (hi only)
    wg_glob(aH, WfBase + 2 * 4096, P);
    wg_glob(aH, WfBase + 3 * 4096, G);
    store_b1(P, G, bpb, bgb, mask, r0, rg, chalf, lane);

    // gate_o -> g_gate [r][c] fp16 direct (pairwise half2 stores)
    wg_glob(aH, WfBase + 4 * 4096, P);
    {
        int q = lane >> 2, m = lane & 3;
        int r1 = r0 + rg * 16 + q, r2 = r1 + 8;
#pragma unroll
        for (int t = 0; t < 8; t++) {
            int cc = chalf * 64 + t * 8 + 2 * m;
            float b0 = __ldg(bgo + cc), b1 = __ldg(bgo + cc + 1);
            *(uint32_t*)(g_gate + (size_t)r1 * C + cc) =
                pack2hf(sigmf(P[t][0] + b0), sigmf(P[t][1] + b1));
            *(uint32_t*)(g_gate + (size_t)r2 * C + cc) =
                pack2hf(sigmf(P[t][2] + b0), sigmf(P[t][3] + b1));
        }
    }
}

// ===================== Stage 3: contraction, cp.async pipelined, fp16x2 ==========
// Chunk = 32 k-rows. Planes per chunk: A(bh), Bh(ah), Bl(al), 8704 B each.
#define CH_BUF 26112
#define CSM_TOT 69632

__global__ void __launch_bounds__(256, 2) k_contract(const float* __restrict__ mask) {
    extern __shared__ char sm[];
    uint32_t sb = smem_u32(sm);
    int tid = threadIdx.x, w = tid >> 5, lane = tid & 31;
    int blk = blockIdx.x;
    int bj = blk % 3, bi = (blk / 3) % 3, ch = blk / 9;
    int ibase = bi * 128, jbase = bj * 128;
    // A operand = b-hi (i-axis), B operand = a hi+lo (j-axis)
    const unsigned short* s0 = g_bh + (size_t)ch * NN + ibase;
    const unsigned short* s1 = g_ah + (size_t)ch * NN + jbase;
    const unsigned short* s2 = g_al + (size_t)ch * NN + jbase;
    int ig = w & 3, jg = w >> 2;   // 4 i-groups x 2 j-groups

    float acc[2][8][4];
#pragma unroll
    for (int r = 0; r < 2; r++)
#pragma unroll
        for (int t = 0; t < 8; t++)
#pragma unroll
            for (int e = 0; e < 4; e++) acc[r][t][e] = 0.f;

    int kl = (lane & 7) + (lane >> 4) * 8;
    int cbit = ((lane >> 3) & 1) * 8;
    uint32_t aoff0 = (uint32_t)((kl * 136 + ig * 32 + cbit) * 2);
    uint32_t aoff1 = aoff0 + 32;
    uint32_t boff = (uint32_t)((kl * 136 + jg * 64 + cbit) * 2);

    // issue chunk loads: 1536 x 16B per chunk, 6 per thread
#define LOAD_CHUNK(k0, bufb) do {                                              \
        _Pragma("unroll")                                                      \
        for (int it = 0; it < 6; it++) {                                       \
            int t2 = tid + it * 256;                                           \
            int p = t2 >> 9, rem = t2 & 511;                                   \
            int r = rem >> 4, s = rem & 15;                                    \
            const unsigned short* sp = (p == 0) ? s0 : (p == 1) ? s1 : s2;     \
            cp16((bufb) + p * 8704 + r * 272 + s * 16,                         \
                 sp + (size_t)((k0) + r) * NDIM + s * 8);                      \
        }                                                                      \
        CP_COMMIT();                                                           \
    } while (0)

    LOAD_CHUNK(0, sb);
    LOAD_CHUNK(32, sb + CH_BUF);

    for (int c = 0; c < 12; c++) {
        if (c < 11) asm volatile("cp.async.wait_group 1;" ::: "memory");
        else        asm volatile("cp.async.wait_group 0;" ::: "memory");
        __syncthreads();
        uint32_t bufb = sb + (c & 1) * CH_BUF;
#pragma unroll
        for (int ks = 0; ks < 2; ks++) {
            uint32_t A0[4], A1[4];
            ldsm4t(A0, bufb + aoff0 + ks * 4352);
            ldsm4t(A1, bufb + aoff1 + ks * 4352);
#pragma unroll
            for (int g = 0; g < 4; g++) {
                uint32_t bH[4], bL[4];
                uint32_t bo = boff + g * 32 + ks * 4352;
                ldsm4t(bH, bufb + 8704  + bo);
                ldsm4t(bL, bufb + 17408 + bo);
                mma16816(acc[0][2 * g],     A0, bH[0], bH[2]);
                mma16816(acc[0][2 * g + 1], A0, bH[1], bH[3]);
                mma16816(acc[0][2 * g],     A0, bL[0], bL[2]);
                mma16816(acc[0][2 * g + 1], A0, bL[1], bL[3]);
                mma16816(acc[1][2 * g],     A1, bH[0], bH[2]);
                mma16816(acc[1][2 * g + 1], A1, bH[1], bH[3]);
                mma16816(acc[1][2 * g],     A1, bL[0], bL[2]);
                mma16816(acc[1][2 * g + 1], A1, bL[1], bL[3]);
            }
        }
        __syncthreads();
        if (c + 2 < 12) LOAD_CHUNK((c + 2) * 32, sb + (c & 1) * CH_BUF);
    }
#undef LOAD_CHUNK

    float* stg = (float*)sm;   // 128 x 132 floats
    {
        int q = lane >> 2, m = lane & 3;
#pragma unroll
        for (int r = 0; r < 2; r++)
#pragma unroll
            for (int t = 0; t < 8; t++) {
                int row1 = ig * 32 + r * 16 + q, row2 = row1 + 8;
                int col = jg * 64 + (t >> 1) * 16 + (t & 1) * 8 + 2 * m;
                stg[row1 * 132 + col]     = acc[r][t][0];
                stg[row1 * 132 + col + 1] = acc[r][t][1];
                stg[row2 * 132 + col]     = acc[r][t][2];
                stg[row2 * 132 + col + 1] = acc[r][t][3];
            }
    }
    __syncthreads();
    // masked fp16 store: 8 cols per thread-iter
#pragma unroll
    for (int it = 0; it < 8; it++) {
        int idx = (tid + it * 256) * 8;
        int row = idx >> 7, col = idx & 127;
        float4 v0 = *(float4*)(stg + row * 132 + col);
        float4 v1 = *(float4*)(stg + row * 132 + col + 4);
        int igl = ibase + row, jgl = jbase + col;
        const float* mrow = mask + (size_t)igl * NDIM + jgl;
        float4 m0 = *(const float4*)mrow;
        float4 m1 = *(const float4*)(mrow + 4);
        uint4 o;
        o.x = pack2hf(v0.x * m0.x, v0.y * m0.y);
        o.y = pack2hf(v0.z * m0.z, v0.w * m0.w);
        o.z = pack2hf(v1.x * m1.x, v1.y * m1.y);
        o.w = pack2hf(v1.z * m1.z, v1.w * m1.w);
        *(uint4*)(g_ct + (size_t)ch * NN + (size_t)igl * NDIM + jgl) = o;
    }
}

// ===================== Stage 4: transpose + LN + proj_o + gate =====================
#define KO_STG 0
#define KO_ZH  33792
#define KO_TOT 51200

__global__ void __launch_bounds__(256, 2) k_out(
    const float* __restrict__ lnw, const float* __restrict__ lnb,
    const float* __restrict__ bo, float* __restrict__ out)
{
    extern __shared__ char sm[];
    uint32_t sb = smem_u32(sm);
    int tid = threadIdx.x, w = tid >> 5, lane = tid & 31;
    int rg = w & 3, chalf = w >> 2;
    int r0 = blockIdx.x * 64;
    float* stg = (float*)(sm + KO_STG);   // 64 x 132 floats

    // transposed fp16 load of g_ct with per-row channel rotation (rot = r & 124)
#pragma unroll
    for (int it = 0; it < 8; it++) {
        int linear = tid + it * 256;
        int c = linear >> 4;
        int r = (linear & 15) * 4;
        uint2 v = *(const uint2*)(g_ct + (size_t)c * NN + r0 + r);
        __half2 h0 = *(__half2*)&v.x;
        __half2 h1 = *(__half2*)&v.y;
        stg[(r + 0) * 132 + ((c + ((r + 0) & 124)) & 127)] = __low2float(h0);
        stg[(r + 1) * 132 + ((c + ((r + 1) & 124)) & 127)] = __high2float(h0);
        stg[(r + 2) * 132 + ((c + ((r + 2) & 124)) & 127)] = __low2float(h1);
        stg[(r + 3) * 132 + ((c + ((r + 3) & 124)) & 127)] = __high2float(h1);
    }
    __syncthreads();

    // LayerNorm rows (8 per warp) -> fp16 hi plane
    {
        float4 wv = ((const float4*)lnw)[lane];
        float4 bv = ((const float4*)lnb)[lane];
#pragma unroll
        for (int rr = 0; rr < 8; rr++) {
            int row = w * 8 + rr;
            int pos = (lane * 4 + (row & 124)) & 127;
            float4 v = *(float4*)(stg + row * 132 + pos);
            float s1 = v.x + v.y + v.z + v.w;
            float s2 = v.x * v.x + v.y * v.y + v.z * v.z + v.w * v.w;
#pragma unroll
            for (int o = 16; o; o >>= 1) {
                s1 += __shfl_xor_sync(0xffffffffu, s1, o);
                s2 += __shfl_xor_sync(0xffffffffu, s2, o);
            }
            float mn = s1 * (1.f / 128.f);
            float var = fmaxf(s2 * (1.f / 128.f) - mn * mn, 0.f);
            float rs = rsqrtf(var + EPS);
            v.x = (v.x - mn) * rs * wv.x + bv.x;
            v.y = (v.y - mn) * rs * wv.y + bv.y;
            v.z = (v.z - mn) * rs * wv.z + bv.z;
            v.w = (v.w - mn) * rs * wv.w + bv.w;
            *(uint2*)(sm + KO_ZH + row * 272 + lane * 8) =
                make_uint2(pack2hf(v.x, v.y), pack2hf(v.z, v.w));
        }
    }
    __syncthreads();

    uint32_t aoff = (uint32_t)(((rg * 16 + (lane & 15)) * 136 + (lane >> 4) * 8) * 2);
    uint32_t aH[8][4];
#pragma unroll
    for (int ks = 0; ks < 8; ks++) ldsm4(aH[ks], sb + KO_ZH + aoff + ks * 32);

    float P[8][4];
    wg_glob(aH, g_wfrag + 5 * 4096 + (chalf * 8) * 32 + lane, P);

    // epilogue: bias + fp16 gate, direct store
    {
        int q = lane >> 2, m = lane & 3;
        int r1 = r0 + rg * 16 + q, r2 = r1 + 8;
#pragma unroll
        for (int t = 0; t < 8; t++) {
            int cc = chalf * 64 + t * 8 + 2 * m;
            float b0 = __ldg(bo + cc), b1 = __ldg(bo + cc + 1);
            uint32_t gb1 = *(const uint32_t*)(g_gate + (size_t)r1 * C + cc);
            uint32_t gb2 = *(const uint32_t*)(g_gate + (size_t)r2 * C + cc);
            __half2 gh1 = *(__half2*)&gb1;
            __half2 gh2 = *(__half2*)&gb2;
            out[(size_t)r1 * C + cc]     = (P[t][0] + b0) * __low2float(gh1);
            out[(size_t)r1 * C + cc + 1] = (P[t][1] + b1) * __high2float(gh1);
            out[(size_t)r2 * C + cc]     = (P[t][2] + b0) * __low2float(gh2);
            out[(size_t)r2 * C + cc + 1] = (P[t][3] + b1) * __high2float(gh2);
        }
    }
}

extern "C" void kernel_launch(void* const* d_in, const int* in_sizes, int n_in,
                              void* d_out, int out_size) {
    const float* z    = (const float*)d_in[0];
    const float* mask = (const float*)d_in[1];
    const float* lniw = (const float*)d_in[2];
    const float* lnib = (const float*)d_in[3];
    const float* lnow = (const float*)d_in[4];
    const float* lnob = (const float*)d_in[5];
    const float* Wpa  = (const float*)d_in[6];
    const float* bpa  = (const float*)d_in[7];
    const float* Wga  = (const float*)d_in[8];
    const float* bga  = (const float*)d_in[9];
    const float* Wpb  = (const float*)d_in[10];
    const float* bpb  = (const float*)d_in[11];
    const float* Wgb  = (const float*)d_in[12];
    const float* bgb  = (const float*)d_in[13];
    const float* Wgo  = (const float*)d_in[14];
    const float* bgo  = (const float*)d_in[15];
    const float* Wpo  = (const float*)d_in[16];
    const float* bpo  = (const float*)d_in[17];
    float* out = (float*)d_out;

    cudaFuncSetAttribute(k_contract, cudaFuncAttributeMaxDynamicSharedMemorySize, CSM_TOT);
    cudaFuncSetAttribute(k_out, cudaFuncAttributeMaxDynamicSharedMemorySize, KO_TOT);

    k_prep<<<96, 256>>>(Wpa, Wga, Wpb, Wgb, Wgo, Wpo);
    k_lin5<<<NN / 64, 256, L5_TOT>>>(z, mask, lniw, lnib, bpa, bga, bpb, bgb, bgo);
    k_contract<<<9 * C, 256, CSM_TOT>>>(mask);
    k_out<<<NN / 64, 256, KO_TOT>>>(lnow, lnob, bpo, out);
}

// round 11
// speedup vs baseline: 3.6387x; 1.2194x over previous
#include <cuda_runtime.h>
#include <cuda_fp16.h>
#include <math.h>
#include <stdint.h>

#define NDIM 384
#define C 128
#define NN (NDIM*NDIM)
#define EPS 1e-5f

// Scratch (allocation-free rule: __device__ globals)
// a, b: single fp16 hi planes, channel-major [c][k][r]
__device__ __align__(16) unsigned short g_ah[(size_t)C * NN];
__device__ __align__(16) unsigned short g_bh[(size_t)C * NN];
__device__ __align__(16) unsigned short g_ct[(size_t)C * NN];   // contracted fp16: [c][i][j]
__device__ __align__(16) unsigned short g_gate[(size_t)NN * C]; // sigmoid(gate_o) fp16: [r][c]
// Proj weights (Wpa,Wpb,Wpo) as hi+lo m16n8k16 B-fragments
__device__ uint4 g_wfrag[3 * 8 * 16 * 32];
// Gate weights (Wga,Wgb,Wgo) as hi-only fragments
__device__ uint2 g_wgate[3 * 8 * 16 * 32];

__device__ __forceinline__ float sigmf(float x) { return 1.f / (1.f + __expf(-x)); }

__device__ __forceinline__ uint32_t smem_u32(const void* p) {
    uint32_t a;
    asm("{ .reg .u64 t; cvta.to.shared.u64 t, %1; cvt.u32.u64 %0, t; }" : "=r"(a) : "l"(p));
    return a;
}
__device__ __forceinline__ void ldsm4(uint32_t (&r)[4], uint32_t a) {
    asm volatile("ldmatrix.sync.aligned.m8n8.x4.shared.b16 {%0,%1,%2,%3}, [%4];"
                 : "=r"(r[0]), "=r"(r[1]), "=r"(r[2]), "=r"(r[3]) : "r"(a));
}
__device__ __forceinline__ void ldsm4t(uint32_t (&r)[4], uint32_t a) {
    asm volatile("ldmatrix.sync.aligned.m8n8.x4.trans.shared.b16 {%0,%1,%2,%3}, [%4];"
                 : "=r"(r[0]), "=r"(r[1]), "=r"(r[2]), "=r"(r[3]) : "r"(a));
}
__device__ __forceinline__ void mma16816(float (&c)[4], const uint32_t (&a)[4],
                                         uint32_t b0, uint32_t b1) {
    asm volatile("mma.sync.aligned.m16n8k16.row.col.f32.f16.f16.f32 "
                 "{%0,%1,%2,%3}, {%4,%5,%6,%7}, {%8,%9}, {%0,%1,%2,%3};"
                 : "+f"(c[0]), "+f"(c[1]), "+f"(c[2]), "+f"(c[3])
                 : "r"(a[0]), "r"(a[1]), "r"(a[2]), "r"(a[3]), "r"(b0), "r"(b1));
}
__device__ __forceinline__ void cp16(uint32_t dst, const void* src) {
    asm volatile("cp.async.cg.shared.global [%0], [%1], 16;" :: "r"(dst), "l"(src));
}
#define CP_COMMIT() asm volatile("cp.async.commit_group;" ::: "memory")

__device__ __forceinline__ uint32_t hfbits(float x) {
    __half h = __float2half_rn(x);
    return (uint32_t)*(unsigned short*)&h;
}
__device__ __forceinline__ float hff(uint32_t b) {
    unsigned short s = (unsigned short)b;
    __half h = *(__half*)&s;
    return __half2float(h);
}
__device__ __forceinline__ float hlopart(float x) { return x - hff(hfbits(x)); }
__device__ __forceinline__ uint32_t pack2hf(float a, float b) {
    return hfbits(a) | (hfbits(b) << 16);
}

// ===================== k_prep: weights -> fp16 MMA B-fragment layout =====================
// Order: W0=Wpa, W1=Wpb, W2=Wpo (proj, hi+lo); W3=Wga, W4=Wgb, W5=Wgo (gate, hi only)
__global__ void __launch_bounds__(256) k_prep(
    const float* __restrict__ W0, const float* __restrict__ W1,
    const float* __restrict__ W2, const float* __restrict__ W3,
    const float* __restrict__ W4, const float* __restrict__ W5)
{
    int gid = blockIdx.x * 256 + threadIdx.x;  // 24576 total
    int lane = gid & 31;
    int g = (gid >> 5) & 15;
    int ks = (gid >> 9) & 7;
    int wsel = gid >> 12;
    const float* W;
    switch (wsel) {
        case 0: W = W0; break;
        case 1: W = W1; break;
        case 2: W = W2; break;
        case 3: W = W3; break;
        case 4: W = W4; break;
        default: W = W5; break;
    }
    int n = g * 8 + (lane >> 2);
    int k0 = ks * 16 + (lane & 3) * 2;
    float w0 = W[n * 128 + k0],     w1 = W[n * 128 + k0 + 1];
    float w2 = W[n * 128 + k0 + 8], w3 = W[n * 128 + k0 + 9];
    int idx = gid & 4095;
    if (wsel < 3) {
        g_wfrag[wsel * 4096 + idx] =
            make_uint4(pack2hf(w0, w1), pack2hf(w2, w3),
                       pack2hf(hlopart(w0), hlopart(w1)),
                       pack2hf(hlopart(w2), hlopart(w3)));
    } else {
        g_wgate[(wsel - 3) * 4096 + idx] = make_uint2(pack2hf(w0, w1), pack2hf(w2, w3));
    }
}

// 2-pass proj gemm: A-hi in regs, W hi+lo fragments streamed from global (L2-resident)
__device__ __forceinline__ void wg_glob2(const uint32_t (&aH)[8][4],
                                         const uint4* __restrict__ Wf, float (&acc)[8][4]) {
#pragma unroll
    for (int t = 0; t < 8; t++)
#pragma unroll
        for (int e = 0; e < 4; e++) acc[t][e] = 0.f;
#pragma unroll 2
    for (int ks = 0; ks < 8; ks++) {
#pragma unroll
        for (int g = 0; g < 8; g++) {
            uint4 f = __ldg(Wf + (ks * 16 + g) * 32);
            mma16816(acc[g], aH[ks], f.x, f.y);   // hi * W-hi
            mma16816(acc[g], aH[ks], f.z, f.w);   // hi * W-lo
        }
    }
}

// 1-pass gate gemm: hi-only fragments
__device__ __forceinline__ void wg_glob1(const uint32_t (&aH)[8][4],
                                         const uint2* __restrict__ Wf, float (&acc)[8][4]) {
#pragma unroll
    for (int t = 0; t < 8; t++)
#pragma unroll
        for (int e = 0; e < 4; e++) acc[t][e] = 0.f;
#pragma unroll 2
    for (int ks = 0; ks < 8; ks++) {
#pragma unroll
        for (int g = 0; g < 8; g++) {
            uint2 f = __ldg(Wf + (ks * 16 + g) * 32);
            mma16816(acc[g], aH[ks], f.x, f.y);
        }
    }
}

// ===================== Stage 2: LN + 5 linears =====================
#define L5_TOT 17408

// combine + store fp16 hi plane, channel-major
__device__ __forceinline__ void store_hi(float (&P)[8][4], float (&G)[8][4],
                                         const float* __restrict__ bp,
                                         const float* __restrict__ bg,
                                         const float* __restrict__ mask,
                                         unsigned short* __restrict__ gh,
                                         int r0, int rg, int chalf, int lane)
{
    int q = lane >> 2, m = lane & 3;
    int r1 = r0 + rg * 16 + q, r2 = r1 + 8;
    float m1 = __ldg(mask + r1), m2 = __ldg(mask + r2);
#pragma unroll
    for (int t = 0; t < 8; t++) {
        int cc = chalf * 64 + t * 8 + 2 * m;
        float p0 = __ldg(bp + cc), p1 = __ldg(bp + cc + 1);
        float g0 = __ldg(bg + cc), g1 = __ldg(bg + cc + 1);
        gh[(size_t)cc * NN + r1]       = (unsigned short)hfbits((P[t][0] + p0) * sigmf(G[t][0] + g0) * m1);
        gh[(size_t)(cc + 1) * NN + r1] = (unsigned short)hfbits((P[t][1] + p1) * sigmf(G[t][1] + g1) * m1);
        gh[(size_t)cc * NN + r2]       = (unsigned short)hfbits((P[t][2] + p0) * sigmf(G[t][2] + g0) * m2);
        gh[(size_t)(cc + 1) * NN + r2] = (unsigned short)hfbits((P[t][3] + p1) * sigmf(G[t][3] + g1) * m2);
    }
}

__global__ void __launch_bounds__(256, 2) k_lin5(
    const float* __restrict__ z, const float* __restrict__ mask,
    const float* __restrict__ lnw, const float* __restrict__ lnb,
    const float* __restrict__ bpa, const float* __restrict__ bga,
    const float* __restrict__ bpb, const float* __restrict__ bgb,
    const float* __restrict__ bgo)
{
    extern __shared__ char sm[];
    uint32_t sb = smem_u32(sm);
    int tid = threadIdx.x, w = tid >> 5, lane = tid & 31;
    int rg = w & 3, chalf = w >> 2;
    int r0 = blockIdx.x * 64;

    // LayerNorm -> fp16 hi plane (warp handles 8 rows)
    {
        float4 wv = ((const float4*)lnw)[lane];
        float4 bv = ((const float4*)lnb)[lane];
#pragma unroll
        for (int rr = 0; rr < 8; rr++) {
            int row = w * 8 + rr;
            float4 v = *(const float4*)(z + (size_t)(r0 + row) * C + lane * 4);
            float s1 = v.x + v.y + v.z + v.w;
            float s2 = v.x * v.x + v.y * v.y + v.z * v.z + v.w * v.w;
#pragma unroll
            for (int o = 16; o; o >>= 1) {
                s1 += __shfl_xor_sync(0xffffffffu, s1, o);
                s2 += __shfl_xor_sync(0xffffffffu, s2, o);
            }
            float mn = s1 * (1.f / 128.f);
            float var = fmaxf(s2 * (1.f / 128.f) - mn * mn, 0.f);
            float rs = rsqrtf(var + EPS);
            v.x = (v.x - mn) * rs * wv.x + bv.x;
            v.y = (v.y - mn) * rs * wv.y + bv.y;
            v.z = (v.z - mn) * rs * wv.z + bv.z;
            v.w = (v.w - mn) * rs * wv.w + bv.w;
            *(uint2*)(sm + row * 272 + lane * 8) =
                make_uint2(pack2hf(v.x, v.y), pack2hf(v.z, v.w));
        }
    }
    __syncthreads();

    uint32_t aoff = (uint32_t)(((rg * 16 + (lane & 15)) * 136 + (lane >> 4) * 8) * 2);

    // preload A-hi fragments (reused across all 5 gemms)
    uint32_t aH[8][4];
#pragma unroll
    for (int ks = 0; ks < 8; ks++) ldsm4(aH[ks], sb + aoff + ks * 32);

    const uint4* Wp = g_wfrag + (chalf * 8) * 32 + lane;
    const uint2* Wg = g_wgate + (chalf * 8) * 32 + lane;
    float P[8][4], G[8][4];

    // branch a
    wg_glob2(aH, Wp + 0 * 4096, P);
    wg_glob1(aH, Wg + 0 * 4096, G);
    store_hi(P, G, bpa, bga, mask, g_ah, r0, rg, chalf, lane);

    // branch b
    wg_glob2(aH, Wp + 1 * 4096, P);
    wg_glob1(aH, Wg + 1 * 4096, G);
    store_hi(P, G, bpb, bgb, mask, g_bh, r0, rg, chalf, lane);

    // gate_o -> g_gate [r][c] fp16 direct
    wg_glob1(aH, Wg + 2 * 4096, P);
    {
        int q = lane >> 2, m = lane & 3;
        int r1 = r0 + rg * 16 + q, r2 = r1 + 8;
#pragma unroll
        for (int t = 0; t < 8; t++) {
            int cc = chalf * 64 + t * 8 + 2 * m;
            float b0 = __ldg(bgo + cc), b1 = __ldg(bgo + cc + 1);
            *(uint32_t*)(g_gate + (size_t)r1 * C + cc) =
                pack2hf(sigmf(P[t][0] + b0), sigmf(P[t][1] + b1));
            *(uint32_t*)(g_gate + (size_t)r2 * C + cc) =
                pack2hf(sigmf(P[t][2] + b0), sigmf(P[t][3] + b1));
        }
    }
}

// ===================== Stage 3: contraction, 4-stage cp.async, fp16 single ==========
// Chunk = 32 k-rows. Planes per chunk: A(bh), B(ah), 8704 B each; chunk = 17408 B.
#define CH_BUF 17408
#define CSM_TOT 69632

__global__ void __launch_bounds__(256, 2) k_contract(const float* __restrict__ mask) {
    extern __shared__ char sm[];
    uint32_t sb = smem_u32(sm);
    int tid = threadIdx.x, w = tid >> 5, lane = tid & 31;
    int blk = blockIdx.x;
    int bj = blk % 3, bi = (blk / 3) % 3, ch = blk / 9;
    int ibase = bi * 128, jbase = bj * 128;
    const unsigned short* s0 = g_bh + (size_t)ch * NN + ibase;  // A operand (i-axis)
    const unsigned short* s1 = g_ah + (size_t)ch * NN + jbase;  // B operand (j-axis)
    int ig = w & 3, jg = w >> 2;   // 4 i-groups x 2 j-groups

    float acc[2][8][4];
#pragma unroll
    for (int r = 0; r < 2; r++)
#pragma unroll
        for (int t = 0; t < 8; t++)
#pragma unroll
            for (int e = 0; e < 4; e++) acc[r][t][e] = 0.f;

    int kl = (lane & 7) + (lane >> 4) * 8;
    int cbit = ((lane >> 3) & 1) * 8;
    uint32_t aoff0 = (uint32_t)((kl * 136 + ig * 32 + cbit) * 2);
    uint32_t aoff1 = aoff0 + 32;
    uint32_t boff = (uint32_t)((kl * 136 + jg * 64 + cbit) * 2);

    // issue chunk loads: 1024 x 16B per chunk, 4 per thread
#define LOAD_CHUNK(k0, bufb) do {                                              \
        _Pragma("unroll")                                                      \
        for (int it = 0; it < 4; it++) {                                       \
            int t2 = tid + it * 256;                                           \
            int p = t2 >> 9, rem = t2 & 511;                                   \
            int r = rem >> 4, s = rem & 15;                                    \
            const unsigned short* sp = (p == 0) ? s0 : s1;                     \
            cp16((bufb) + p * 8704 + r * 272 + s * 16,                         \
                 sp + (size_t)((k0) + r) * NDIM + s * 8);                      \
        }                                                                      \
        CP_COMMIT();                                                           \
    } while (0)

    LOAD_CHUNK(0,  sb);
    LOAD_CHUNK(32, sb + CH_BUF);
    LOAD_CHUNK(64, sb + 2 * CH_BUF);
    LOAD_CHUNK(96, sb + 3 * CH_BUF);

    for (int c = 0; c < 12; c++) {
        if (c < 9)       asm volatile("cp.async.wait_group 3;" ::: "memory");
        else if (c == 9) asm volatile("cp.async.wait_group 2;" ::: "memory");
        else if (c == 10) asm volatile("cp.async.wait_group 1;" ::: "memory");
        else             asm volatile("cp.async.wait_group 0;" ::: "memory");
        __syncthreads();
        uint32_t bufb = sb + (c & 3) * CH_BUF;
#pragma unroll
        for (int ks = 0; ks < 2; ks++) {
            uint32_t A0[4], A1[4];
            ldsm4t(A0, bufb + aoff0 + ks * 4352);
            ldsm4t(A1, bufb + aoff1 + ks * 4352);
#pragma unroll
            for (int g = 0; g < 4; g++) {
                uint32_t bH[4];
                ldsm4t(bH, bufb + 8704 + boff + g * 32 + ks * 4352);
                mma16816(acc[0][2 * g],     A0, bH[0], bH[2]);
                mma16816(acc[0][2 * g + 1], A0, bH[1], bH[3]);
                mma16816(acc[1][2 * g],     A1, bH[0], bH[2]);
                mma16816(acc[1][2 * g + 1], A1, bH[1], bH[3]);
            }
        }
        __syncthreads();
        if (c + 4 < 12) LOAD_CHUNK((c + 4) * 32, sb + (c & 3) * CH_BUF);
    }
#undef LOAD_CHUNK

    float* stg = (float*)sm;   // 128 x 132 floats = 67584 B (fits CSM_TOT)
    {
        int q = lane >> 2, m = lane & 3;
#pragma unroll
        for (int r = 0; r < 2; r++)
#pragma unroll
            for (int t = 0; t < 8; t++) {
                int row1 = ig * 32 + r * 16 + q, row2 = row1 + 8;
                int col = jg * 64 + (t >> 1) * 16 + (t & 1) * 8 + 2 * m;
                stg[row1 * 132 + col]     = acc[r][t][0];
                stg[row1 * 132 + col + 1] = acc[r][t][1];
                stg[row2 * 132 + col]     = acc[r][t][2];
                stg[row2 * 132 + col + 1] = acc[r][t][3];
            }
    }
    __syncthreads();
    // masked fp16 store: 8 cols per thread-iter
#pragma unroll
    for (int it = 0; it < 8; it++) {
        int idx = (tid + it * 256) * 8;
        int row = idx >> 7, col = idx & 127;
        float4 v0 = *(float4*)(stg + row * 132 + col);
        float4 v1 = *(float4*)(stg + row * 132 + col + 4);
        int igl = ibase + row, jgl = jbase + col;
        const float* mrow = mask + (size_t)igl * NDIM + jgl;
        float4 m0 = *(const float4*)mrow;
        float4 m1 = *(const float4*)(mrow + 4);
        uint4 o;
        o.x = pack2hf(v0.x * m0.x, v0.y * m0.y);
        o.y = pack2hf(v0.z * m0.z, v0.w * m0.w);
        o.z = pack2hf(v1.x * m1.x, v1.y * m1.y);
        o.w = pack2hf(v1.z * m1.z, v1.w * m1.w);
        *(uint4*)(g_ct + (size_t)ch * NN + (size_t)igl * NDIM + jgl) = o;
    }
}

// ===================== Stage 4: transpose + LN + proj_o + gate =====================
#define KO_STG 0
#define KO_ZH  33792
#define KO_TOT 51200

__global__ void __launch_bounds__(256, 2) k_out(
    const float* __restrict__ lnw, const float* __restrict__ lnb,
    const float* __restrict__ bo, float* __restrict__ out)
{
    extern __shared__ char sm[];
    uint32_t sb = smem_u32(sm);
    int tid = threadIdx.x, w = tid >> 5, lane = tid & 31;
    int rg = w & 3, chalf = w >> 2;
    int r0 = blockIdx.x * 64;
    float* stg = (float*)(sm + KO_STG);   // 64 x 132 floats

    // transposed fp16 load of g_ct with per-row channel rotation (rot = r & 124)
#pragma unroll
    for (int it = 0; it < 8; it++) {
        int linear = tid + it * 256;
        int c = linear >> 4;
        int r = (linear & 15) * 4;
        uint2 v = *(const uint2*)(g_ct + (size_t)c * NN + r0 + r);
        __half2 h0 = *(__half2*)&v.x;
        __half2 h1 = *(__half2*)&v.y;
        stg[(r + 0) * 132 + ((c + ((r + 0) & 124)) & 127)] = __low2float(h0);
        stg[(r + 1) * 132 + ((c + ((r + 1) & 124)) & 127)] = __high2float(h0);
        stg[(r + 2) * 132 + ((c + ((r + 2) & 124)) & 127)] = __low2float(h1);
        stg[(r + 3) * 132 + ((c + ((r + 3) & 124)) & 127)] = __high2float(h1);
    }
    __syncthreads();

    // LayerNorm rows (8 per warp) -> fp16 hi plane
    {
        float4 wv = ((const float4*)lnw)[lane];
        float4 bv = ((const float4*)lnb)[lane];
#pragma unroll
        for (int rr = 0; rr < 8; rr++) {
            int row = w * 8 + rr;
            int pos = (lane * 4 + (row & 124)) & 127;
            float4 v = *(float4*)(stg + row * 132 + pos);
            float s1 = v.x + v.y + v.z + v.w;
            float s2 = v.x * v.x + v.y * v.y + v.z * v.z + v.w * v.w;
#pragma unroll
            for (int o = 16; o; o >>= 1) {
                s1 += __shfl_xor_sync(0xffffffffu, s1, o);
                s2 += __shfl_xor_sync(0xffffffffu, s2, o);
            }
            float mn = s1 * (1.f / 128.f);
            float var = fmaxf(s2 * (1.f / 128.f) - mn * mn, 0.f);
            float rs = rsqrtf(var + EPS);
            v.x = (v.x - mn) * rs * wv.x + bv.x;
            v.y = (v.y - mn) * rs * wv.y + bv.y;
            v.z = (v.z - mn) * rs * wv.z + bv.z;
            v.w = (v.w - mn) * rs * wv.w + bv.w;
            *(uint2*)(sm + KO_ZH + row * 272 + lane * 8) =
                make_uint2(pack2hf(v.x, v.y), pack2hf(v.z, v.w));
        }
    }
    __syncthreads();

    uint32_t aoff = (uint32_t)(((rg * 16 + (lane & 15)) * 136 + (lane >> 4) * 8) * 2);
    uint32_t aH[8][4];
#pragma unroll
    for (int ks = 0; ks < 8; ks++) ldsm4(aH[ks], sb + KO_ZH + aoff + ks * 32);

    float P[8][4];
    wg_glob2(aH, g_wfrag + 2 * 4096 + (chalf * 8) * 32 + lane, P);

    // epilogue: bias + fp16 gate, direct store
    {
        int q = lane >> 2, m = lane & 3;
        int r1 = r0 + rg * 16 + q, r2 = r1 + 8;
#pragma unroll
        for (int t = 0; t < 8; t++) {
            int cc = chalf * 64 + t * 8 + 2 * m;
            float b0 = __ldg(bo + cc), b1 = __ldg(bo + cc + 1);
            uint32_t gb1 = *(const uint32_t*)(g_gate + (size_t)r1 * C + cc);
            uint32_t gb2 = *(const uint32_t*)(g_gate + (size_t)r2 * C + cc);
            __half2 gh1 = *(__half2*)&gb1;
            __half2 gh2 = *(__half2*)&gb2;
            out[(size_t)r1 * C + cc]     = (P[t][0] + b0) * __low2float(gh1);
            out[(size_t)r1 * C + cc + 1] = (P[t][1] + b1) * __high2float(gh1);
            out[(size_t)r2 * C + cc]     = (P[t][2] + b0) * __low2float(gh2);
            out[(size_t)r2 * C + cc + 1] = (P[t][3] + b1) * __high2float(gh2);
        }
    }
}

extern "C" void kernel_launch(void* const* d_in, const int* in_sizes, int n_in,
                              void* d_out, int out_size) {
    const float* z    = (const float*)d_in[0];
    const float* mask = (const float*)d_in[1];
    const float* lniw = (const float*)d_in[2];
    const float* lnib = (const float*)d_in[3];
    const float* lnow = (const float*)d_in[4];
    const float* lnob = (const float*)d_in[5];
    const float* Wpa  = (const float*)d_in[6];
    const float* bpa  = (const float*)d_in[7];
    const float* Wga  = (const float*)d_in[8];
    const float* bga  = (const float*)d_in[9];
    const float* Wpb  = (const float*)d_in[10];
    const float* bpb  = (const float*)d_in[11];
    const float* Wgb  = (const float*)d_in[12];
    const float* bgb  = (const float*)d_in[13];
    const float* Wgo  = (const float*)d_in[14];
    const float* bgo  = (const float*)d_in[15];
    const float* Wpo  = (const float*)d_in[16];
    const float* bpo  = (const float*)d_in[17];
    float* out = (float*)d_out;

    cudaFuncSetAttribute(k_contract, cudaFuncAttributeMaxDynamicSharedMemorySize, CSM_TOT);
    cudaFuncSetAttribute(k_out, cudaFuncAttributeMaxDynamicSharedMemorySize, KO_TOT);

    k_prep<<<96, 256>>>(Wpa, Wpb, Wpo, Wga, Wgb, Wgo);
    k_lin5<<<NN / 64, 256, L5_TOT>>>(z, mask, lniw, lnib, bpa, bga, bpb, bgb, bgo);
    k_contract<<<9 * C, 256, CSM_TOT>>>(mask);
    k_out<<<NN / 64, 256, KO_TOT>>>(lnow, lnob, bpo, out);
}

// round 12
// speedup vs baseline: 3.6631x; 1.0067x over previous
#include <cuda_runtime.h>
#include <cuda_fp16.h>
#include <math.h>
#include <stdint.h>

#define NDIM 384
#define C 128
#define NN (NDIM*NDIM)
#define EPS 1e-5f

// Scratch (allocation-free rule: __device__ globals)
__device__ __align__(16) unsigned short g_ah[(size_t)C * NN];
__device__ __align__(16) unsigned short g_bh[(size_t)C * NN];
__device__ __align__(16) unsigned short g_ct[(size_t)C * NN];   // contracted fp16: [c][i][j]
__device__ __align__(16) unsigned short g_gate[(size_t)NN * C]; // sigmoid(gate_o) fp16: [r][c]
__device__ uint4 g_wfrag[3 * 8 * 16 * 32];  // proj weights hi+lo fragments
__device__ uint2 g_wgate[3 * 8 * 16 * 32];  // gate weights hi-only fragments

__device__ __forceinline__ float sigmf(float x) { return 1.f / (1.f + __expf(-x)); }

__device__ __forceinline__ uint32_t smem_u32(const void* p) {
    uint32_t a;
    asm("{ .reg .u64 t; cvta.to.shared.u64 t, %1; cvt.u32.u64 %0, t; }" : "=r"(a) : "l"(p));
    return a;
}
__device__ __forceinline__ void ldsm4(uint32_t (&r)[4], uint32_t a) {
    asm volatile("ldmatrix.sync.aligned.m8n8.x4.shared.b16 {%0,%1,%2,%3}, [%4];"
                 : "=r"(r[0]), "=r"(r[1]), "=r"(r[2]), "=r"(r[3]) : "r"(a));
}
__device__ __forceinline__ void ldsm4t(uint32_t (&r)[4], uint32_t a) {
    asm volatile("ldmatrix.sync.aligned.m8n8.x4.trans.shared.b16 {%0,%1,%2,%3}, [%4];"
                 : "=r"(r[0]), "=r"(r[1]), "=r"(r[2]), "=r"(r[3]) : "r"(a));
}
__device__ __forceinline__ void mma16816(float (&c)[4], const uint32_t (&a)[4],
                                         uint32_t b0, uint32_t b1) {
    asm volatile("mma.sync.aligned.m16n8k16.row.col.f32.f16.f16.f32 "
                 "{%0,%1,%2,%3}, {%4,%5,%6,%7}, {%8,%9}, {%0,%1,%2,%3};"
                 : "+f"(c[0]), "+f"(c[1]), "+f"(c[2]), "+f"(c[3])
                 : "r"(a[0]), "r"(a[1]), "r"(a[2]), "r"(a[3]), "r"(b0), "r"(b1));
}
__device__ __forceinline__ void cp16(uint32_t dst, const void* src) {
    asm volatile("cp.async.cg.shared.global [%0], [%1], 16;" :: "r"(dst), "l"(src));
}
#define CP_COMMIT() asm volatile("cp.async.commit_group;" ::: "memory")

__device__ __forceinline__ uint32_t hfbits(float x) {
    __half h = __float2half_rn(x);
    return (uint32_t)*(unsigned short*)&h;
}
__device__ __forceinline__ float hff(uint32_t b) {
    unsigned short s = (unsigned short)b;
    __half h = *(__half*)&s;
    return __half2float(h);
}
__device__ __forceinline__ float hlopart(float x) { return x - hff(hfbits(x)); }
__device__ __forceinline__ uint32_t pack2hf(float a, float b) {
    return hfbits(a) | (hfbits(b) << 16);
}

// ===================== k_prep =====================
__global__ void __launch_bounds__(256) k_prep(
    const float* __restrict__ W0, const float* __restrict__ W1,
    const float* __restrict__ W2, const float* __restrict__ W3,
    const float* __restrict__ W4, const float* __restrict__ W5)
{
    int gid = blockIdx.x * 256 + threadIdx.x;
    int lane = gid & 31;
    int g = (gid >> 5) & 15;
    int ks = (gid >> 9) & 7;
    int wsel = gid >> 12;
    const float* W;
    switch (wsel) {
        case 0: W = W0; break;
        case 1: W = W1; break;
        case 2: W = W2; break;
        case 3: W = W3; break;
        case 4: W = W4; break;
        default: W = W5; break;
    }
    int n = g * 8 + (lane >> 2);
    int k0 = ks * 16 + (lane & 3) * 2;
    float w0 = W[n * 128 + k0],     w1 = W[n * 128 + k0 + 1];
    float w2 = W[n * 128 + k0 + 8], w3 = W[n * 128 + k0 + 9];
    int idx = gid & 4095;
    if (wsel < 3) {
        g_wfrag[wsel * 4096 + idx] =
            make_uint4(pack2hf(w0, w1), pack2hf(w2, w3),
                       pack2hf(hlopart(w0), hlopart(w1)),
                       pack2hf(hlopart(w2), hlopart(w3)));
    } else {
        g_wgate[(wsel - 3) * 4096 + idx] = make_uint2(pack2hf(w0, w1), pack2hf(w2, w3));
    }
}

// 2-pass proj gemm (hi+lo weights)
__device__ __forceinline__ void wg_glob2(const uint32_t (&aH)[8][4],
                                         const uint4* __restrict__ Wf, float (&acc)[8][4]) {
#pragma unroll
    for (int t = 0; t < 8; t++)
#pragma unroll
        for (int e = 0; e < 4; e++) acc[t][e] = 0.f;
#pragma unroll 2
    for (int ks = 0; ks < 8; ks++) {
#pragma unroll
        for (int g = 0; g < 8; g++) {
            uint4 f = __ldg(Wf + (ks * 16 + g) * 32);
            mma16816(acc[g], aH[ks], f.x, f.y);
            mma16816(acc[g], aH[ks], f.z, f.w);
        }
    }
}

// 1-pass gate gemm
__device__ __forceinline__ void wg_glob1(const uint32_t (&aH)[8][4],
                                         const uint2* __restrict__ Wf, float (&acc)[8][4]) {
#pragma unroll
    for (int t = 0; t < 8; t++)
#pragma unroll
        for (int e = 0; e < 4; e++) acc[t][e] = 0.f;
#pragma unroll 2
    for (int ks = 0; ks < 8; ks++) {
#pragma unroll
        for (int g = 0; g < 8; g++) {
            uint2 f = __ldg(Wf + (ks * 16 + g) * 32);
            mma16816(acc[g], aH[ks], f.x, f.y);
        }
    }
}

// ===================== Stage 2: LN + 5 linears =====================
// smem: single region, 18432 B. Used first as ZH (64 x 272B), then as store staging.
#define L5_TOT 18432

// combine + scatter to smem (half st[128ch][72]) + coalesced STG.128
__device__ __forceinline__ void store_hi_staged(
    float (&P)[8][4], float (&G)[8][4],
    const float* __restrict__ bp, const float* __restrict__ bg,
    const float* __restrict__ mask,
    unsigned short* st, unsigned short* __restrict__ gout,
    int r0, int rg, int chalf, int lane, int tid)
{
    int q = lane >> 2, m = lane & 3;
    int rl1 = rg * 16 + q, rl2 = rl1 + 8;
    float m1 = __ldg(mask + r0 + rl1), m2 = __ldg(mask + r0 + rl2);
#pragma unroll
    for (int t = 0; t < 8; t++) {
        int cc = chalf * 64 + t * 8 + 2 * m;
        float p0 = __ldg(bp + cc), p1 = __ldg(bp + cc + 1);
        float g0 = __ldg(bg + cc), g1 = __ldg(bg + cc + 1);
        st[cc * 72 + rl1]       = (unsigned short)hfbits((P[t][0] + p0) * sigmf(G[t][0] + g0) * m1);
        st[(cc + 1) * 72 + rl1] = (unsigned short)hfbits((P[t][1] + p1) * sigmf(G[t][1] + g1) * m1);
        st[cc * 72 + rl2]       = (unsigned short)hfbits((P[t][2] + p0) * sigmf(G[t][2] + g0) * m2);
        st[(cc + 1) * 72 + rl2] = (unsigned short)hfbits((P[t][3] + p1) * sigmf(G[t][3] + g1) * m2);
    }
    __syncthreads();
#pragma unroll
    for (int it = 0; it < 4; it++) {
        int f = tid + it * 256;
        int c = f >> 3, r8 = (f & 7) * 8;
        uint4 v = *(uint4*)&st[c * 72 + r8];
        *(uint4*)(gout + (size_t)c * NN + r0 + r8) = v;
    }
    __syncthreads();
}

__global__ void __launch_bounds__(256, 2) k_lin5(
    const float* __restrict__ z, const float* __restrict__ mask,
    const float* __restrict__ lnw, const float* __restrict__ lnb,
    const float* __restrict__ bpa, const float* __restrict__ bga,
    const float* __restrict__ bpb, const float* __restrict__ bgb,
    const float* __restrict__ bgo)
{
    extern __shared__ char sm[];
    uint32_t sb = smem_u32(sm);
    int tid = threadIdx.x, w = tid >> 5, lane = tid & 31;
    int rg = w & 3, chalf = w >> 2;
    int r0 = blockIdx.x * 64;

    // LayerNorm -> fp16 hi plane (64 rows x 272B, region start)
    {
        float4 wv = ((const float4*)lnw)[lane];
        float4 bv = ((const float4*)lnb)[lane];
#pragma unroll
        for (int rr = 0; rr < 8; rr++) {
            int row = w * 8 + rr;
            float4 v = *(const float4*)(z + (size_t)(r0 + row) * C + lane * 4);
            float s1 = v.x + v.y + v.z + v.w;
            float s2 = v.x * v.x + v.y * v.y + v.z * v.z + v.w * v.w;
#pragma unroll
            for (int o = 16; o; o >>= 1) {
                s1 += __shfl_xor_sync(0xffffffffu, s1, o);
                s2 += __shfl_xor_sync(0xffffffffu, s2, o);
            }
            float mn = s1 * (1.f / 128.f);
            float var = fmaxf(s2 * (1.f / 128.f) - mn * mn, 0.f);
            float rs = rsqrtf(var + EPS);
            v.x = (v.x - mn) * rs * wv.x + bv.x;
            v.y = (v.y - mn) * rs * wv.y + bv.y;
            v.z = (v.z - mn) * rs * wv.z + bv.z;
            v.w = (v.w - mn) * rs * wv.w + bv.w;
            *(uint2*)(sm + row * 272 + lane * 8) =
                make_uint2(pack2hf(v.x, v.y), pack2hf(v.z, v.w));
        }
    }
    __syncthreads();

    uint32_t aoff = (uint32_t)(((rg * 16 + (lane & 15)) * 136 + (lane >> 4) * 8) * 2);

    // preload A-hi fragments (reused across all 5 gemms)
    uint32_t aH[8][4];
#pragma unroll
    for (int ks = 0; ks < 8; ks++) ldsm4(aH[ks], sb + aoff + ks * 32);
    __syncthreads();   // ZH region now dead -> reusable as staging

    const uint4* Wp = g_wfrag + (chalf * 8) * 32 + lane;
    const uint2* Wg = g_wgate + (chalf * 8) * 32 + lane;
    unsigned short* st = (unsigned short*)sm;
    float P[8][4], G[8][4];

    // branch a
    wg_glob2(aH, Wp + 0 * 4096, P);
    wg_glob1(aH, Wg + 0 * 4096, G);
    store_hi_staged(P, G, bpa, bga, mask, st, g_ah, r0, rg, chalf, lane, tid);

    // branch b
    wg_glob2(aH, Wp + 1 * 4096, P);
    wg_glob1(aH, Wg + 1 * 4096, G);
    store_hi_staged(P, G, bpb, bgb, mask, st, g_bh, r0, rg, chalf, lane, tid);

    // gate_o -> stage row-major (half gt[64][136]) -> coalesced STG.128
    wg_glob1(aH, Wg + 2 * 4096, P);
    {
        int q = lane >> 2, m = lane & 3;
        int rl1 = rg * 16 + q, rl2 = rl1 + 8;
#pragma unroll
        for (int t = 0; t < 8; t++) {
            int cc = chalf * 64 + t * 8 + 2 * m;
            float b0 = __ldg(bgo + cc), b1 = __ldg(bgo + cc + 1);
            *(uint32_t*)(st + rl1 * 136 + cc) = pack2hf(sigmf(P[t][0] + b0), sigmf(P[t][1] + b1));
            *(uint32_t*)(st + rl2 * 136 + cc) = pack2hf(sigmf(P[t][2] + b0), sigmf(P[t][3] + b1));
        }
        __syncthreads();
#pragma unroll
        for (int it = 0; it < 4; it++) {
            int f = tid + it * 256;
            int r = f >> 4, u = (f & 15) * 8;
            uint4 v = *(uint4*)&st[r * 136 + u];
            *(uint4*)(g_gate + (size_t)(r0 + r) * C + u) = v;
        }
    }
}

// ===================== Stage 3: contraction, 4-stage cp.async (unchanged) ==========
#define CH_BUF 17408
#define CSM_TOT 69632

__global__ void __launch_bounds__(256, 2) k_contract(const float* __restrict__ mask) {
    extern __shared__ char sm[];
    uint32_t sb = smem_u32(sm);
    int tid = threadIdx.x, w = tid >> 5, lane = tid & 31;
    int blk = blockIdx.x;
    int bj = blk % 3, bi = (blk / 3) % 3, ch = blk / 9;
    int ibase = bi * 128, jbase = bj * 128;
    const unsigned short* s0 = g_bh + (size_t)ch * NN + ibase;
    const unsigned short* s1 = g_ah + (size_t)ch * NN + jbase;
    int ig = w & 3, jg = w >> 2;

    float acc[2][8][4];
#pragma unroll
    for (int r = 0; r < 2; r++)
#pragma unroll
        for (int t = 0; t < 8; t++)
#pragma unroll
            for (int e = 0; e < 4; e++) acc[r][t][e] = 0.f;

    int kl = (lane & 7) + (lane >> 4) * 8;
    int cbit = ((lane >> 3) & 1) * 8;
    uint32_t aoff0 = (uint32_t)((kl * 136 + ig * 32 + cbit) * 2);
    uint32_t aoff1 = aoff0 + 32;
    uint32_t boff = (uint32_t)((kl * 136 + jg * 64 + cbit) * 2);

#define LOAD_CHUNK(k0, bufb) do {                                              \
        _Pragma("unroll")                                                      \
        for (int it = 0; it < 4; it++) {                                       \
            int t2 = tid + it * 256;                                           \
            int p = t2 >> 9, rem = t2 & 511;                                   \
            int r = rem >> 4, s = rem & 15;                                    \
            const unsigned short* sp = (p == 0) ? s0 : s1;                     \
            cp16((bufb) + p * 8704 + r * 272 + s * 16,                         \
                 sp + (size_t)((k0) + r) * NDIM + s * 8);                      \
        }                                                                      \
        CP_COMMIT();                                                           \
    } while (0)

    LOAD_CHUNK(0,  sb);
    LOAD_CHUNK(32, sb + CH_BUF);
    LOAD_CHUNK(64, sb + 2 * CH_BUF);
    LOAD_CHUNK(96, sb + 3 * CH_BUF);

    for (int c = 0; c < 12; c++) {
        if (c < 9)        asm volatile("cp.async.wait_group 3;" ::: "memory");
        else if (c == 9)  asm volatile("cp.async.wait_group 2;" ::: "memory");
        else if (c == 10) asm volatile("cp.async.wait_group 1;" ::: "memory");
        else              asm volatile("cp.async.wait_group 0;" ::: "memory");
        __syncthreads();
        uint32_t bufb = sb + (c & 3) * CH_BUF;
#pragma unroll
        for (int ks = 0; ks < 2; ks++) {
            uint32_t A0[4], A1[4];
            ldsm4t(A0, bufb + aoff0 + ks * 4352);
            ldsm4t(A1, bufb + aoff1 + ks * 4352);
#pragma unroll
            for (int g = 0; g < 4; g++) {
                uint32_t bH[4];
                ldsm4t(bH, bufb + 8704 + boff + g * 32 + ks * 4352);
                mma16816(acc[0][2 * g],     A0, bH[0], bH[2]);
                mma16816(acc[0][2 * g + 1], A0, bH[1], bH[3]);
                mma16816(acc[1][2 * g],     A1, bH[0], bH[2]);
                mma16816(acc[1][2 * g + 1], A1, bH[1], bH[3]);
            }
        }
        __syncthreads();
        if (c + 4 < 12) LOAD_CHUNK((c + 4) * 32, sb + (c & 3) * CH_BUF);
    }
#undef LOAD_CHUNK

    float* stg = (float*)sm;
    {
        int q = lane >> 2, m = lane & 3;
#pragma unroll
        for (int r = 0; r < 2; r++)
#pragma unroll
            for (int t = 0; t < 8; t++) {
                int row1 = ig * 32 + r * 16 + q, row2 = row1 + 8;
                int col = jg * 64 + (t >> 1) * 16 + (t & 1) * 8 + 2 * m;
                stg[row1 * 132 + col]     = acc[r][t][0];
                stg[row1 * 132 + col + 1] = acc[r][t][1];
                stg[row2 * 132 + col]     = acc[r][t][2];
                stg[row2 * 132 + col + 1] = acc[r][t][3];
            }
    }
    __syncthreads();
#pragma unroll
    for (int it = 0; it < 8; it++) {
        int idx = (tid + it * 256) * 8;
        int row = idx >> 7, col = idx & 127;
        float4 v0 = *(float4*)(stg + row * 132 + col);
        float4 v1 = *(float4*)(stg + row * 132 + col + 4);
        int igl = ibase + row, jgl = jbase + col;
        const float* mrow = mask + (size_t)igl * NDIM + jgl;
        float4 m0 = *(const float4*)mrow;
        float4 m1 = *(const float4*)(mrow + 4);
        uint4 o;
        o.x = pack2hf(v0.x * m0.x, v0.y * m0.y);
        o.y = pack2hf(v0.z * m0.z, v0.w * m0.w);
        o.z = pack2hf(v1.x * m1.x, v1.y * m1.y);
        o.w = pack2hf(v1.z * m1.z, v1.w * m1.w);
        *(uint4*)(g_ct + (size_t)ch * NN + (size_t)igl * NDIM + jgl) = o;
    }
}

// ===================== Stage 4: 512 threads, 128 rows, half2 staging =====================
// smem: stg = uint32[128][68] (34816 B) | ZH at 34816 (128 x 272B = 34816)
#define KO_ZH  34816
#define KO_TOT 69632

__global__ void __launch_bounds__(512, 1) k_out(
    const float* __restrict__ lnw, const float* __restrict__ lnb,
    const float* __restrict__ bo, float* __restrict__ out)
{
    extern __shared__ char sm[];
    uint32_t sb = smem_u32(sm);
    int tid = threadIdx.x, w = tid >> 5, lane = tid & 31;
    int rg = w & 7, chalf = w >> 3;
    int r0 = blockIdx.x * 128;
    uint32_t* stg = (uint32_t*)sm;    // [row][slot] row stride 68 words

    // transposed fp16 load: warp = fixed channel pair, lanes = row quads
#pragma unroll
    for (int it = 0; it < 4; it++) {
        int cpair = w + it * 16;                 // 0..63
        const unsigned short* p0 = g_ct + (size_t)(2 * cpair) * NN + r0 + lane * 4;
        uint2 u0 = *(const uint2*)p0;
        uint2 u1 = *(const uint2*)(p0 + NN);
        int r = lane * 4;
        int slot = (cpair + lane) & 63;          // rotation: (cpair + r/4) & 63
        stg[(r + 0) * 68 + slot] = __byte_perm(u0.x, u1.x, 0x5410);
        stg[(r + 1) * 68 + slot] = __byte_perm(u0.x, u1.x, 0x7632);
        stg[(r + 2) * 68 + slot] = __byte_perm(u0.y, u1.y, 0x5410);
        stg[(r + 3) * 68 + slot] = __byte_perm(u0.y, u1.y, 0x7632);
    }
    __syncthreads();

    // LayerNorm: warp handles 8 rows; lane reads slots 2p, 2p+1 (LDS-64)
    {
        float2 lw0, lb0, lw1, lb1;
        int cp0 = 0, cp1 = 0;
#pragma unroll
        for (int rr = 0; rr < 8; rr++) {
            int row = w * 8 + rr;
            int k = row >> 2;
            if (rr == 0 || rr == 4) {
                cp0 = (2 * lane - k) & 63;
                cp1 = (2 * lane + 1 - k) & 63;
                lw0 = *(const float2*)(lnw + 2 * cp0); lb0 = *(const float2*)(lnb + 2 * cp0);
                lw1 = *(const float2*)(lnw + 2 * cp1); lb1 = *(const float2*)(lnb + 2 * cp1);
            }
            uint2 d = *(uint2*)&stg[row * 68 + 2 * lane];
            __half2 ha = *(__half2*)&d.x;
            __half2 hb = *(__half2*)&d.y;
            float f0 = __low2float(ha), f1 = __high2float(ha);
            float f2 = __low2float(hb), f3 = __high2float(hb);
            float s1 = f0 + f1 + f2 + f3;
            float s2 = f0 * f0 + f1 * f1 + f2 * f2 + f3 * f3;
#pragma unroll
            for (int o = 16; o; o >>= 1) {
                s1 += __shfl_xor_sync(0xffffffffu, s1, o);
                s2 += __shfl_xor_sync(0xffffffffu, s2, o);
            }
            float mn = s1 * (1.f / 128.f);
            float var = fmaxf(s2 * (1.f / 128.f) - mn * mn, 0.f);
            float rs = rsqrtf(var + EPS);
            float n0 = (f0 - mn) * rs * lw0.x + lb0.x;
            float n1 = (f1 - mn) * rs * lw0.y + lb0.y;
            float n2 = (f2 - mn) * rs * lw1.x + lb1.x;
            float n3 = (f3 - mn) * rs * lw1.y + lb1.y;
            *(uint32_t*)(sm + KO_ZH + row * 272 + 4 * cp0) = pack2hf(n0, n1);
            *(uint32_t*)(sm + KO_ZH + row * 272 + 4 * cp1) = pack2hf(n2, n3);
        }
    }
    __syncthreads();

    uint32_t aoff = (uint32_t)(((rg * 16 + (lane & 15)) * 136 + (lane >> 4) * 8) * 2);
    uint32_t aH[8][4];
#pragma unroll
    for (int ks = 0; ks < 8; ks++) ldsm4(aH[ks], sb + KO_ZH + aoff + ks * 32);

    float P[8][4];
    wg_glob2(aH, g_wfrag + 2 * 4096 + (chalf * 8) * 32 + lane, P);

    // epilogue: bias + fp16 gate, float2 stores
    {
        int q = lane >> 2, m = lane & 3;
        int r1 = r0 + rg * 16 + q, r2 = r1 + 8;
#pragma unroll
        for (int t = 0; t < 8; t++) {
            int cc = chalf * 64 + t * 8 + 2 * m;
            float b0 = __ldg(bo + cc), b1 = __ldg(bo + cc + 1);
            uint32_t gb1 = *(const uint32_t*)(g_gate + (size_t)r1 * C + cc);
            uint32_t gb2 = *(const uint32_t*)(g_gate + (size_t)r2 * C + cc);
            __half2 gh1 = *(__half2*)&gb1;
            __half2 gh2 = *(__half2*)&gb2;
            float2 o1, o2;
            o1.x = (P[t][0] + b0) * __low2float(gh1);
            o1.y = (P[t][1] + b1) * __high2float(gh1);
            o2.x = (P[t][2] + b0) * __low2float(gh2);
            o2.y = (P[t][3] + b1) * __high2float(gh2);
            *(float2*)(out + (size_t)r1 * C + cc) = o1;
            *(float2*)(out + (size_t)r2 * C + cc) = o2;
        }
    }
}

extern "C" void kernel_launch(void* const* d_in, const int* in_sizes, int n_in,
                              void* d_out, int out_size) {
    const float* z    = (const float*)d_in[0];
    const float* mask = (const float*)d_in[1];
    const float* lniw = (const float*)d_in[2];
    const float* lnib = (const float*)d_in[3];
    const float* lnow = (const float*)d_in[4];
    const float* lnob = (const float*)d_in[5];
    const float* Wpa  = (const float*)d_in[6];
    const float* bpa  = (const float*)d_in[7];
    const float* Wga  = (const float*)d_in[8];
    const float* bga  = (const float*)d_in[9];
    const float* Wpb  = (const float*)d_in[10];
    const float* bpb  = (const float*)d_in[11];
    const float* Wgb  = (const float*)d_in[12];
    const float* bgb  = (const float*)d_in[13];
    const float* Wgo  = (const float*)d_in[14];
    const float* bgo  = (const float*)d_in[15];
    const float* Wpo  = (const float*)d_in[16];
    const float* bpo  = (const float*)d_in[17];
    float* out = (float*)d_out;

    cudaFuncSetAttribute(k_contract, cudaFuncAttributeMaxDynamicSharedMemorySize, CSM_TOT);
    cudaFuncSetAttribute(k_out, cudaFuncAttributeMaxDynamicSharedMemorySize, KO_TOT);

    k_prep<<<96, 256>>>(Wpa, Wpb, Wpo, Wga, Wgb, Wgo);
    k_lin5<<<NN / 64, 256, L5_TOT>>>(z, mask, lniw, lnib, bpa, bga, bpb, bgb, bgo);
    k_contract<<<9 * C, 256, CSM_TOT>>>(mask);
    k_out<<<NN / 128, 512, KO_TOT>>>(lnow, lnob, bpo, out);
}

// round 13
// speedup vs baseline: 3.8262x; 1.0445x over previous
#include <cuda_runtime.h>
#include <cuda_fp16.h>
#include <math.h>
#include <stdint.h>

#define NDIM 384
#define C 128
#define NN (NDIM*NDIM)
#define EPS 1e-5f

// Scratch (allocation-free rule: __device__ globals)
__device__ __align__(16) unsigned short g_ah[(size_t)C * NN];
__device__ __align__(16) unsigned short g_bh[(size_t)C * NN];
__device__ __align__(16) unsigned short g_ct[(size_t)C * NN];   // contracted fp16: [c][i][j]
__device__ __align__(16) unsigned short g_gate[(size_t)NN * C]; // sigmoid(gate_o) fp16: [r][c]
__device__ uint4 g_wfrag[1 * 8 * 16 * 32];  // Wpo hi+lo fragments
__device__ uint2 g_wgate[5 * 8 * 16 * 32];  // Wpa,Wga,Wpb,Wgb,Wgo hi-only fragments

__device__ __forceinline__ float sigmf(float x) { return 1.f / (1.f + __expf(-x)); }

__device__ __forceinline__ uint32_t smem_u32(const void* p) {
    uint32_t a;
    asm("{ .reg .u64 t; cvta.to.shared.u64 t, %1; cvt.u32.u64 %0, t; }" : "=r"(a) : "l"(p));
    return a;
}
__device__ __forceinline__ void ldsm4(uint32_t (&r)[4], uint32_t a) {
    asm volatile("ldmatrix.sync.aligned.m8n8.x4.shared.b16 {%0,%1,%2,%3}, [%4];"
                 : "=r"(r[0]), "=r"(r[1]), "=r"(r[2]), "=r"(r[3]) : "r"(a));
}
__device__ __forceinline__ void ldsm4t(uint32_t (&r)[4], uint32_t a) {
    asm volatile("ldmatrix.sync.aligned.m8n8.x4.trans.shared.b16 {%0,%1,%2,%3}, [%4];"
                 : "=r"(r[0]), "=r"(r[1]), "=r"(r[2]), "=r"(r[3]) : "r"(a));
}
__device__ __forceinline__ void mma16816(float (&c)[4], const uint32_t (&a)[4],
                                         uint32_t b0, uint32_t b1) {
    asm volatile("mma.sync.aligned.m16n8k16.row.col.f32.f16.f16.f32 "
                 "{%0,%1,%2,%3}, {%4,%5,%6,%7}, {%8,%9}, {%0,%1,%2,%3};"
                 : "+f"(c[0]), "+f"(c[1]), "+f"(c[2]), "+f"(c[3])
                 : "r"(a[0]), "r"(a[1]), "r"(a[2]), "r"(a[3]), "r"(b0), "r"(b1));
}
__device__ __forceinline__ void cp16(uint32_t dst, const void* src) {
    asm volatile("cp.async.cg.shared.global [%0], [%1], 16;" :: "r"(dst), "l"(src));
}
#define CP_COMMIT() asm volatile("cp.async.commit_group;" ::: "memory")

__device__ __forceinline__ uint32_t hfbits(float x) {
    __half h = __float2half_rn(x);
    return (uint32_t)*(unsigned short*)&h;
}
__device__ __forceinline__ float hff(uint32_t b) {
    unsigned short s = (unsigned short)b;
    __half h = *(__half*)&s;
    return __half2float(h);
}
__device__ __forceinline__ float hlopart(float x) { return x - hff(hfbits(x)); }
__device__ __forceinline__ uint32_t pack2hf(float a, float b) {
    return hfbits(a) | (hfbits(b) << 16);
}

// ===================== k_prep =====================
// W0=Wpo (hi+lo, uint4); W1..W5 = Wpa,Wga,Wpb,Wgb,Wgo (hi only, uint2)
__global__ void __launch_bounds__(256) k_prep(
    const float* __restrict__ W0, const float* __restrict__ W1,
    const float* __restrict__ W2, const float* __restrict__ W3,
    const float* __restrict__ W4, const float* __restrict__ W5)
{
    int gid = blockIdx.x * 256 + threadIdx.x;
    int lane = gid & 31;
    int g = (gid >> 5) & 15;
    int ks = (gid >> 9) & 7;
    int wsel = gid >> 12;
    const float* W;
    switch (wsel) {
        case 0: W = W0; break;
        case 1: W = W1; break;
        case 2: W = W2; break;
        case 3: W = W3; break;
        case 4: W = W4; break;
        default: W = W5; break;
    }
    int n = g * 8 + (lane >> 2);
    int k0 = ks * 16 + (lane & 3) * 2;
    float w0 = W[n * 128 + k0],     w1 = W[n * 128 + k0 + 1];
    float w2 = W[n * 128 + k0 + 8], w3 = W[n * 128 + k0 + 9];
    int idx = gid & 4095;
    if (wsel == 0) {
        g_wfrag[idx] = make_uint4(pack2hf(w0, w1), pack2hf(w2, w3),
                                  pack2hf(hlopart(w0), hlopart(w1)),
                                  pack2hf(hlopart(w2), hlopart(w3)));
    } else {
        g_wgate[(wsel - 1) * 4096 + idx] = make_uint2(pack2hf(w0, w1), pack2hf(w2, w3));
    }
}

// 2-pass proj gemm (hi+lo weights) — used only for Wpo in k_out
__device__ __forceinline__ void wg_glob2(const uint32_t (&aH)[8][4],
                                         const uint4* __restrict__ Wf, float (&acc)[8][4]) {
#pragma unroll
    for (int t = 0; t < 8; t++)
#pragma unroll
        for (int e = 0; e < 4; e++) acc[t][e] = 0.f;
#pragma unroll 2
    for (int ks = 0; ks < 8; ks++) {
#pragma unroll
        for (int g = 0; g < 8; g++) {
            uint4 f = __ldg(Wf + (ks * 16 + g) * 32);
            mma16816(acc[g], aH[ks], f.x, f.y);
            mma16816(acc[g], aH[ks], f.z, f.w);
        }
    }
}

// 1-pass gemm (hi-only weights)
__device__ __forceinline__ void wg_glob1(const uint32_t (&aH)[8][4],
                                         const uint2* __restrict__ Wf, float (&acc)[8][4]) {
#pragma unroll
    for (int t = 0; t < 8; t++)
#pragma unroll
        for (int e = 0; e < 4; e++) acc[t][e] = 0.f;
#pragma unroll 2
    for (int ks = 0; ks < 8; ks++) {
#pragma unroll
        for (int g = 0; g < 8; g++) {
            uint2 f = __ldg(Wf + (ks * 16 + g) * 32);
            mma16816(acc[g], aH[ks], f.x, f.y);
        }
    }
}

// ===================== Stage 2: LN + 5 linears (all 1-pass) =====================
#define L5_TOT 18432

__device__ __forceinline__ void store_hi_staged(
    float (&P)[8][4], float (&G)[8][4],
    const float* __restrict__ bp, const float* __restrict__ bg,
    const float* __restrict__ mask,
    unsigned short* st, unsigned short* __restrict__ gout,
    int r0, int rg, int chalf, int lane, int tid)
{
    int q = lane >> 2, m = lane & 3;
    int rl1 = rg * 16 + q, rl2 = rl1 + 8;
    float m1 = __ldg(mask + r0 + rl1), m2 = __ldg(mask + r0 + rl2);
#pragma unroll
    for (int t = 0; t < 8; t++) {
        int cc = chalf * 64 + t * 8 + 2 * m;
        float p0 = __ldg(bp + cc), p1 = __ldg(bp + cc + 1);
        float g0 = __ldg(bg + cc), g1 = __ldg(bg + cc + 1);
        st[cc * 72 + rl1]       = (unsigned short)hfbits((P[t][0] + p0) * sigmf(G[t][0] + g0) * m1);
        st[(cc + 1) * 72 + rl1] = (unsigned short)hfbits((P[t][1] + p1) * sigmf(G[t][1] + g1) * m1);
        st[cc * 72 + rl2]       = (unsigned short)hfbits((P[t][2] + p0) * sigmf(G[t][2] + g0) * m2);
        st[(cc + 1) * 72 + rl2] = (unsigned short)hfbits((P[t][3] + p1) * sigmf(G[t][3] + g1) * m2);
    }
    __syncthreads();
#pragma unroll
    for (int it = 0; it < 4; it++) {
        int f = tid + it * 256;
        int c = f >> 3, r8 = (f & 7) * 8;
        uint4 v = *(uint4*)&st[c * 72 + r8];
        *(uint4*)(gout + (size_t)c * NN + r0 + r8) = v;
    }
    __syncthreads();
}

__global__ void __launch_bounds__(256, 2) k_lin5(
    const float* __restrict__ z, const float* __restrict__ mask,
    const float* __restrict__ lnw, const float* __restrict__ lnb,
    const float* __restrict__ bpa, const float* __restrict__ bga,
    const float* __restrict__ bpb, const float* __restrict__ bgb,
    const float* __restrict__ bgo)
{
    extern __shared__ char sm[];
    uint32_t sb = smem_u32(sm);
    int tid = threadIdx.x, w = tid >> 5, lane = tid & 31;
    int rg = w & 3, chalf = w >> 2;
    int r0 = blockIdx.x * 64;

    // LayerNorm -> fp16 hi plane (64 rows x 272B)
    {
        float4 wv = ((const float4*)lnw)[lane];
        float4 bv = ((const float4*)lnb)[lane];
#pragma unroll
        for (int rr = 0; rr < 8; rr++) {
            int row = w * 8 + rr;
            float4 v = *(const float4*)(z + (size_t)(r0 + row) * C + lane * 4);
            float s1 = v.x + v.y + v.z + v.w;
            float s2 = v.x * v.x + v.y * v.y + v.z * v.z + v.w * v.w;
#pragma unroll
            for (int o = 16; o; o >>= 1) {
                s1 += __shfl_xor_sync(0xffffffffu, s1, o);
                s2 += __shfl_xor_sync(0xffffffffu, s2, o);
            }
            float mn = s1 * (1.f / 128.f);
            float var = fmaxf(s2 * (1.f / 128.f) - mn * mn, 0.f);
            float rs = rsqrtf(var + EPS);
            v.x = (v.x - mn) * rs * wv.x + bv.x;
            v.y = (v.y - mn) * rs * wv.y + bv.y;
            v.z = (v.z - mn) * rs * wv.z + bv.z;
            v.w = (v.w - mn) * rs * wv.w + bv.w;
            *(uint2*)(sm + row * 272 + lane * 8) =
                make_uint2(pack2hf(v.x, v.y), pack2hf(v.z, v.w));
        }
    }
    __syncthreads();

    uint32_t aoff = (uint32_t)(((rg * 16 + (lane & 15)) * 136 + (lane >> 4) * 8) * 2);

    uint32_t aH[8][4];
#pragma unroll
    for (int ks = 0; ks < 8; ks++) ldsm4(aH[ks], sb + aoff + ks * 32);
    __syncthreads();   // ZH region now dead -> reusable as staging

    const uint2* Wg = g_wgate + (chalf * 8) * 32 + lane;
    unsigned short* st = (unsigned short*)sm;
    float P[8][4], G[8][4];

    // branch a (Wpa=0, Wga=1)
    wg_glob1(aH, Wg + 0 * 4096, P);
    wg_glob1(aH, Wg + 1 * 4096, G);
    store_hi_staged(P, G, bpa, bga, mask, st, g_ah, r0, rg, chalf, lane, tid);

    // branch b (Wpb=2, Wgb=3)
    wg_glob1(aH, Wg + 2 * 4096, P);
    wg_glob1(aH, Wg + 3 * 4096, G);
    store_hi_staged(P, G, bpb, bgb, mask, st, g_bh, r0, rg, chalf, lane, tid);

    // gate_o (Wgo=4) -> stage row-major (half gt[64][136]) -> coalesced STG.128
    wg_glob1(aH, Wg + 4 * 4096, P);
    {
        int q = lane >> 2, m = lane & 3;
        int rl1 = rg * 16 + q, rl2 = rl1 + 8;
#pragma unroll
        for (int t = 0; t < 8; t++) {
            int cc = chalf * 64 + t * 8 + 2 * m;
            float b0 = __ldg(bgo + cc), b1 = __ldg(bgo + cc + 1);
            *(uint32_t*)(st + rl1 * 136 + cc) = pack2hf(sigmf(P[t][0] + b0), sigmf(P[t][1] + b1));
            *(uint32_t*)(st + rl2 * 136 + cc) = pack2hf(sigmf(P[t][2] + b0), sigmf(P[t][3] + b1));
        }
        __syncthreads();
#pragma unroll
        for (int it = 0; it < 4; it++) {
            int f = tid + it * 256;
            int r = f >> 4, u = (f & 15) * 8;
            uint4 v = *(uint4*)&st[r * 136 + u];
            *(uint4*)(g_gate + (size_t)(r0 + r) * C + u) = v;
        }
    }
}

// ===================== Stage 3: contraction, 64-row chunks, double-buffered ==========
// Chunk = 64 k-rows. Planes per chunk: A(bh) 17408 B, B(ah) 17408 B; chunk = 34816 B.
#define CH_BUF 34816
#define CSM_TOT 69632

__global__ void __launch_bounds__(256, 2) k_contract(const float* __restrict__ mask) {
    extern __shared__ char sm[];
    uint32_t sb = smem_u32(sm);
    int tid = threadIdx.x, w = tid >> 5, lane = tid & 31;
    int blk = blockIdx.x;
    int bj = blk % 3, bi = (blk / 3) % 3, ch = blk / 9;
    int ibase = bi * 128, jbase = bj * 128;
    const unsigned short* s0 = g_bh + (size_t)ch * NN + ibase;  // A operand (i-axis)
    const unsigned short* s1 = g_ah + (size_t)ch * NN + jbase;  // B operand (j-axis)
    int ig = w & 3, jg = w >> 2;

    float acc[2][8][4];
#pragma unroll
    for (int r = 0; r < 2; r++)
#pragma unroll
        for (int t = 0; t < 8; t++)
#pragma unroll
            for (int e = 0; e < 4; e++) acc[r][t][e] = 0.f;

    int kl = (lane & 7) + (lane >> 4) * 8;
    int cbit = ((lane >> 3) & 1) * 8;
    uint32_t aoff0 = (uint32_t)((kl * 136 + ig * 32 + cbit) * 2);
    uint32_t aoff1 = aoff0 + 32;
    uint32_t boff = (uint32_t)((kl * 136 + jg * 64 + cbit) * 2);

    // chunk loads: 2048 x 16B, 8 per thread
#define LOAD_CHUNK(k0, bufb) do {                                              \
        _Pragma("unroll")                                                      \
        for (int it = 0; it < 8; it++) {                                       \
            int t2 = tid + it * 256;                                           \
            int p = t2 >> 10, rem = t2 & 1023;                                 \
            int r = rem >> 4, s = rem & 15;                                    \
            const unsigned short* sp = (p == 0) ? s0 : s1;                     \
            cp16((bufb) + p * 17408 + r * 272 + s * 16,                        \
                 sp + (size_t)((k0) + r) * NDIM + s * 8);                      \
        }                                                                      \
        CP_COMMIT();                                                           \
    } while (0)

    LOAD_CHUNK(0,  sb);
    LOAD_CHUNK(64, sb + CH_BUF);

    for (int c = 0; c < 6; c++) {
        if (c < 5) asm volatile("cp.async.wait_group 1;" ::: "memory");
        else       asm volatile("cp.async.wait_group 0;" ::: "memory");
        __syncthreads();
        uint32_t bufb = sb + (c & 1) * CH_BUF;
#pragma unroll
        for (int ks = 0; ks < 4; ks++) {
            uint32_t A0[4], A1[4];
            ldsm4t(A0, bufb + aoff0 + ks * 4352);
            ldsm4t(A1, bufb + aoff1 + ks * 4352);
#pragma unroll
            for (int g = 0; g < 4; g++) {
                uint32_t bH[4];
                ldsm4t(bH, bufb + 17408 + boff + g * 32 + ks * 4352);
                mma16816(acc[0][2 * g],     A0, bH[0], bH[2]);
                mma16816(acc[0][2 * g + 1], A0, bH[1], bH[3]);
                mma16816(acc[1][2 * g],     A1, bH[0], bH[2]);
                mma16816(acc[1][2 * g + 1], A1, bH[1], bH[3]);
            }
        }
        __syncthreads();
        if (c + 2 < 6) LOAD_CHUNK((c + 2) * 64, sb + (c & 1) * CH_BUF);
    }
#undef LOAD_CHUNK

    float* stg = (float*)sm;
    {
        int q = lane >> 2, m = lane & 3;
#pragma unroll
        for (int r = 0; r < 2; r++)
#pragma unroll
            for (int t = 0; t < 8; t++) {
                int row1 = ig * 32 + r * 16 + q, row2 = row1 + 8;
                int col = jg * 64 + (t >> 1) * 16 + (t & 1) * 8 + 2 * m;
                stg[row1 * 132 + col]     = acc[r][t][0];
                stg[row1 * 132 + col + 1] = acc[r][t][1];
                stg[row2 * 132 + col]     = acc[r][t][2];
                stg[row2 * 132 + col + 1] = acc[r][t][3];
            }
    }
    __syncthreads();
#pragma unroll
    for (int it = 0; it < 8; it++) {
        int idx = (tid + it * 256) * 8;
        int row = idx >> 7, col = idx & 127;
        float4 v0 = *(float4*)(stg + row * 132 + col);
        float4 v1 = *(float4*)(stg + row * 132 + col + 4);
        int igl = ibase + row, jgl = jbase + col;
        const float* mrow = mask + (size_t)igl * NDIM + jgl;
        float4 m0 = *(const float4*)mrow;
        float4 m1 = *(const float4*)(mrow + 4);
        uint4 o;
        o.x = pack2hf(v0.x * m0.x, v0.y * m0.y);
        o.y = pack2hf(v0.z * m0.z, v0.w * m0.w);
        o.z = pack2hf(v1.x * m1.x, v1.y * m1.y);
        o.w = pack2hf(v1.z * m1.z, v1.w * m1.w);
        *(uint4*)(g_ct + (size_t)ch * NN + (size_t)igl * NDIM + jgl) = o;
    }
}

// ===================== Stage 4: 512 threads, 128 rows, half2 staging =====================
#define KO_ZH  34816
#define KO_TOT 69632

__global__ void __launch_bounds__(512, 1) k_out(
    const float* __restrict__ lnw, const float* __restrict__ lnb,
    const float* __restrict__ bo, float* __restrict__ out)
{
    extern __shared__ char sm[];
    uint32_t sb = smem_u32(sm);
    int tid = threadIdx.x, w = tid >> 5, lane = tid & 31;
    int rg = w & 7, chalf = w >> 3;
    int r0 = blockIdx.x * 128;
    uint32_t* stg = (uint32_t*)sm;    // [row][slot] row stride 68 words

    // transposed fp16 load: warp = channel pair, lanes = row quads
#pragma unroll
    for (int it = 0; it < 4; it++) {
        int cpair = w + it * 16;
        const unsigned short* p0 = g_ct + (size_t)(2 * cpair) * NN + r0 + lane * 4;
        uint2 u0 = *(const uint2*)p0;
        uint2 u1 = *(const uint2*)(p0 + NN);
        int r = lane * 4;
        int slot = (cpair + lane) & 63;
        stg[(r + 0) * 68 + slot] = __byte_perm(u0.x, u1.x, 0x5410);
        stg[(r + 1) * 68 + slot] = __byte_perm(u0.x, u1.x, 0x7632);
        stg[(r + 2) * 68 + slot] = __byte_perm(u0.y, u1.y, 0x5410);
        stg[(r + 3) * 68 + slot] = __byte_perm(u0.y, u1.y, 0x7632);
    }
    __syncthreads();

    // LayerNorm: warp handles 8 rows; lane reads slots 2p, 2p+1
    {
        float2 lw0, lb0, lw1, lb1;
        int cp0 = 0, cp1 = 0;
#pragma unroll
        for (int rr = 0; rr < 8; rr++) {
            int row = w * 8 + rr;
            int k = row >> 2;
            if (rr == 0 || rr == 4) {
                cp0 = (2 * lane - k) & 63;
                cp1 = (2 * lane + 1 - k) & 63;
                lw0 = *(const float2*)(lnw + 2 * cp0); lb0 = *(const float2*)(lnb + 2 * cp0);
                lw1 = *(const float2*)(lnw + 2 * cp1); lb1 = *(const float2*)(lnb + 2 * cp1);
            }
            uint2 d = *(uint2*)&stg[row * 68 + 2 * lane];
            __half2 ha = *(__half2*)&d.x;
            __half2 hb = *(__half2*)&d.y;
            float f0 = __low2float(ha), f1 = __high2float(ha);
            float f2 = __low2float(hb), f3 = __high2float(hb);
            float s1 = f0 + f1 + f2 + f3;
            float s2 = f0 * f0 + f1 * f1 + f2 * f2 + f3 * f3;
#pragma unroll
            for (int o = 16; o; o >>= 1) {
                s1 += __shfl_xor_sync(0xffffffffu, s1, o);
                s2 += __shfl_xor_sync(0xffffffffu, s2, o);
            }
            float mn = s1 * (1.f / 128.f);
            float var = fmaxf(s2 * (1.f / 128.f) - mn * mn, 0.f);
            float rs = rsqrtf(var + EPS);
            float n0 = (f0 - mn) * rs * lw0.x + lb0.x;
            float n1 = (f1 - mn) * rs * lw0.y + lb0.y;
            float n2 = (f2 - mn) * rs * lw1.x + lb1.x;
            float n3 = (f3 - mn) * rs * lw1.y + lb1.y;
            *(uint32_t*)(sm + KO_ZH + row * 272 + 4 * cp0) = pack2hf(n0, n1);
            *(uint32_t*)(sm + KO_ZH + row * 272 + 4 * cp1) = pack2hf(n2, n3);
        }
    }
    __syncthreads();

    uint32_t aoff = (uint32_t)(((rg * 16 + (lane & 15)) * 136 + (lane >> 4) * 8) * 2);
    uint32_t aH[8][4];
#pragma unroll
    for (int ks = 0; ks < 8; ks++) ldsm4(aH[ks], sb + KO_ZH + aoff + ks * 32);

    float P[8][4];
    wg_glob2(aH, g_wfrag + (chalf * 8) * 32 + lane, P);

    // epilogue: bias + fp16 gate, float2 stores
    {
        int q = lane >> 2, m = lane & 3;
        int r1 = r0 + rg * 16 + q, r2 = r1 + 8;
#pragma unroll
        for (int t = 0; t < 8; t++) {
            int cc = chalf * 64 + t * 8 + 2 * m;
            float b0 = __ldg(bo + cc), b1 = __ldg(bo + cc + 1);
            uint32_t gb1 = *(const uint32_t*)(g_gate + (size_t)r1 * C + cc);
            uint32_t gb2 = *(const uint32_t*)(g_gate + (size_t)r2 * C + cc);
            __half2 gh1 = *(__half2*)&gb1;
            __half2 gh2 = *(__half2*)&gb2;
            float2 o1, o2;
            o1.x = (P[t][0] + b0) * __low2float(gh1);
            o1.y = (P[t][1] + b1) * __high2float(gh1);
            o2.x = (P[t][2] + b0) * __low2float(gh2);
            o2.y = (P[t][3] + b1) * __high2float(gh2);
            *(float2*)(out + (size_t)r1 * C + cc) = o1;
            *(float2*)(out + (size_t)r2 * C + cc) = o2;
        }
    }
}

extern "C" void kernel_launch(void* const* d_in, const int* in_sizes, int n_in,
                              void* d_out, int out_size) {
    const float* z    = (const float*)d_in[0];
    const float* mask = (const float*)d_in[1];
    const float* lniw = (const float*)d_in[2];
    const float* lnib = (const float*)d_in[3];
    const float* lnow = (const float*)d_in[4];
    const float* lnob = (const float*)d_in[5];
    const float* Wpa  = (const float*)d_in[6];
    const float* bpa  = (const float*)d_in[7];
    const float* Wga  = (const float*)d_in[8];
    const float* bga  = (const float*)d_in[9];
    const float* Wpb  = (const float*)d_in[10];
    const float* bpb  = (const float*)d_in[11];
    const float* Wgb  = (const float*)d_in[12];
    const float* bgb  = (const float*)d_in[13];
    const float* Wgo  = (const float*)d_in[14];
    const float* bgo  = (const float*)d_in[15];
    const float* Wpo  = (const float*)d_in[16];
    const float* bpo  = (const float*)d_in[17];
    float* out = (float*)d_out;

    cudaFuncSetAttribute(k_contract, cudaFuncAttributeMaxDynamicSharedMemorySize, CSM_TOT);
    cudaFuncSetAttribute(k_out, cudaFuncAttributeMaxDynamicSharedMemorySize, KO_TOT);

    k_prep<<<96, 256>>>(Wpo, Wpa, Wga, Wpb, Wgb, Wgo);
    k_lin5<<<NN / 64, 256, L5_TOT>>>(z, mask, lniw, lnib, bpa, bga, bpb, bgb, bgo);
    k_contract<<<9 * C, 256, CSM_TOT>>>(mask);
    k_out<<<NN / 128, 512, KO_TOT>>>(lnow, lnob, bpo, out);
}

// round 14
// speedup vs baseline: 3.9301x; 1.0272x over previous
#include <cuda_runtime.h>
#include <cuda_fp16.h>
#include <math.h>
#include <stdint.h>

#define NDIM 384
#define C 128
#define NN (NDIM*NDIM)
#define EPS 1e-5f

// Scratch (allocation-free rule: __device__ globals)
__device__ __align__(16) unsigned short g_ah[(size_t)C * NN];
__device__ __align__(16) unsigned short g_bh[(size_t)C * NN];
__device__ __align__(16) unsigned short g_ct[(size_t)C * NN];   // contracted fp16: [c][i][j]
__device__ __align__(16) unsigned short g_gate[(size_t)NN * C]; // sigmoid(gate_o) fp16: [r][c]
// All 6 weights as hi-only m16n8k16 B-fragments: Wpa,Wga,Wpb,Wgb,Wgo,Wpo
__device__ uint2 g_wgate[6 * 8 * 16 * 32];

__device__ __forceinline__ float sigmf(float x) { return 1.f / (1.f + __expf(-x)); }

__device__ __forceinline__ uint32_t smem_u32(const void* p) {
    uint32_t a;
    asm("{ .reg .u64 t; cvta.to.shared.u64 t, %1; cvt.u32.u64 %0, t; }" : "=r"(a) : "l"(p));
    return a;
}
__device__ __forceinline__ void ldsm4(uint32_t (&r)[4], uint32_t a) {
    asm volatile("ldmatrix.sync.aligned.m8n8.x4.shared.b16 {%0,%1,%2,%3}, [%4];"
                 : "=r"(r[0]), "=r"(r[1]), "=r"(r[2]), "=r"(r[3]) : "r"(a));
}
__device__ __forceinline__ void ldsm4t(uint32_t (&r)[4], uint32_t a) {
    asm volatile("ldmatrix.sync.aligned.m8n8.x4.trans.shared.b16 {%0,%1,%2,%3}, [%4];"
                 : "=r"(r[0]), "=r"(r[1]), "=r"(r[2]), "=r"(r[3]) : "r"(a));
}
__device__ __forceinline__ void mma16816(float (&c)[4], const uint32_t (&a)[4],
                                         uint32_t b0, uint32_t b1) {
    asm volatile("mma.sync.aligned.m16n8k16.row.col.f32.f16.f16.f32 "
                 "{%0,%1,%2,%3}, {%4,%5,%6,%7}, {%8,%9}, {%0,%1,%2,%3};"
                 : "+f"(c[0]), "+f"(c[1]), "+f"(c[2]), "+f"(c[3])
                 : "r"(a[0]), "r"(a[1]), "r"(a[2]), "r"(a[3]), "r"(b0), "r"(b1));
}
__device__ __forceinline__ void cp16(uint32_t dst, const void* src) {
    asm volatile("cp.async.cg.shared.global [%0], [%1], 16;" :: "r"(dst), "l"(src));
}
#define CP_COMMIT() asm volatile("cp.async.commit_group;" ::: "memory")

__device__ __forceinline__ uint32_t hfbits(float x) {
    __half h = __float2half_rn(x);
    return (uint32_t)*(unsigned short*)&h;
}
__device__ __forceinline__ uint32_t pack2hf(float a, float b) {
    return hfbits(a) | (hfbits(b) << 16);
}

// ===================== k_prep: 6 weights -> hi-only fp16 fragments =====================
__global__ void __launch_bounds__(256) k_prep(
    const float* __restrict__ W0, const float* __restrict__ W1,
    const float* __restrict__ W2, const float* __restrict__ W3,
    const float* __restrict__ W4, const float* __restrict__ W5)
{
    int gid = blockIdx.x * 256 + threadIdx.x;   // 24576 total
    int lane = gid & 31;
    int g = (gid >> 5) & 15;
    int ks = (gid >> 9) & 7;
    int wsel = gid >> 12;
    const float* W;
    switch (wsel) {
        case 0: W = W0; break;
        case 1: W = W1; break;
        case 2: W = W2; break;
        case 3: W = W3; break;
        case 4: W = W4; break;
        default: W = W5; break;
    }
    int n = g * 8 + (lane >> 2);
    int k0 = ks * 16 + (lane & 3) * 2;
    float w0 = W[n * 128 + k0],     w1 = W[n * 128 + k0 + 1];
    float w2 = W[n * 128 + k0 + 8], w3 = W[n * 128 + k0 + 9];
    g_wgate[gid] = make_uint2(pack2hf(w0, w1), pack2hf(w2, w3));
}

// 1-pass gemm (hi-only weights streamed from global, L2/L1-resident)
__device__ __forceinline__ void wg_glob1(const uint32_t (&aH)[8][4],
                                         const uint2* __restrict__ Wf, float (&acc)[8][4]) {
#pragma unroll
    for (int t = 0; t < 8; t++)
#pragma unroll
        for (int e = 0; e < 4; e++) acc[t][e] = 0.f;
#pragma unroll 2
    for (int ks = 0; ks < 8; ks++) {
#pragma unroll
        for (int g = 0; g < 8; g++) {
            uint2 f = __ldg(Wf + (ks * 16 + g) * 32);
            mma16816(acc[g], aH[ks], f.x, f.y);
        }
    }
}

// ===================== Stage 2: LN + 5 linears (all 1-pass) =====================
#define L5_TOT 18432

__device__ __forceinline__ void store_hi_staged(
    float (&P)[8][4], float (&G)[8][4],
    const float* __restrict__ bp, const float* __restrict__ bg,
    const float* __restrict__ mask,
    unsigned short* st, unsigned short* __restrict__ gout,
    int r0, int rg, int chalf, int lane, int tid)
{
    int q = lane >> 2, m = lane & 3;
    int rl1 = rg * 16 + q, rl2 = rl1 + 8;
    float m1 = __ldg(mask + r0 + rl1), m2 = __ldg(mask + r0 + rl2);
#pragma unroll
    for (int t = 0; t < 8; t++) {
        int cc = chalf * 64 + t * 8 + 2 * m;
        float p0 = __ldg(bp + cc), p1 = __ldg(bp + cc + 1);
        float g0 = __ldg(bg + cc), g1 = __ldg(bg + cc + 1);
        st[cc * 72 + rl1]       = (unsigned short)hfbits((P[t][0] + p0) * sigmf(G[t][0] + g0) * m1);
        st[(cc + 1) * 72 + rl1] = (unsigned short)hfbits((P[t][1] + p1) * sigmf(G[t][1] + g1) * m1);
        st[cc * 72 + rl2]       = (unsigned short)hfbits((P[t][2] + p0) * sigmf(G[t][2] + g0) * m2);
        st[(cc + 1) * 72 + rl2] = (unsigned short)hfbits((P[t][3] + p1) * sigmf(G[t][3] + g1) * m2);
    }
    __syncthreads();
#pragma unroll
    for (int it = 0; it < 4; it++) {
        int f = tid + it * 256;
        int c = f >> 3, r8 = (f & 7) * 8;
        uint4 v = *(uint4*)&st[c * 72 + r8];
        *(uint4*)(gout + (size_t)c * NN + r0 + r8) = v;
    }
    __syncthreads();
}

__global__ void __launch_bounds__(256, 2) k_lin5(
    const float* __restrict__ z, const float* __restrict__ mask,
    const float* __restrict__ lnw, const float* __restrict__ lnb,
    const float* __restrict__ bpa, const float* __restrict__ bga,
    const float* __restrict__ bpb, const float* __restrict__ bgb,
    const float* __restrict__ bgo)
{
    extern __shared__ char sm[];
    uint32_t sb = smem_u32(sm);
    int tid = threadIdx.x, w = tid >> 5, lane = tid & 31;
    int rg = w & 3, chalf = w >> 2;
    int r0 = blockIdx.x * 64;

    // LayerNorm -> fp16 hi plane (64 rows x 272B)
    {
        float4 wv = ((const float4*)lnw)[lane];
        float4 bv = ((const float4*)lnb)[lane];
#pragma unroll
        for (int rr = 0; rr < 8; rr++) {
            int row = w * 8 + rr;
            float4 v = *(const float4*)(z + (size_t)(r0 + row) * C + lane * 4);
            float s1 = v.x + v.y + v.z + v.w;
            float s2 = v.x * v.x + v.y * v.y + v.z * v.z + v.w * v.w;
#pragma unroll
            for (int o = 16; o; o >>= 1) {
                s1 += __shfl_xor_sync(0xffffffffu, s1, o);
                s2 += __shfl_xor_sync(0xffffffffu, s2, o);
            }
            float mn = s1 * (1.f / 128.f);
            float var = fmaxf(s2 * (1.f / 128.f) - mn * mn, 0.f);
            float rs = rsqrtf(var + EPS);
            v.x = (v.x - mn) * rs * wv.x + bv.x;
            v.y = (v.y - mn) * rs * wv.y + bv.y;
            v.z = (v.z - mn) * rs * wv.z + bv.z;
            v.w = (v.w - mn) * rs * wv.w + bv.w;
            *(uint2*)(sm + row * 272 + lane * 8) =
                make_uint2(pack2hf(v.x, v.y), pack2hf(v.z, v.w));
        }
    }
    __syncthreads();

    uint32_t aoff = (uint32_t)(((rg * 16 + (lane & 15)) * 136 + (lane >> 4) * 8) * 2);

    uint32_t aH[8][4];
#pragma unroll
    for (int ks = 0; ks < 8; ks++) ldsm4(aH[ks], sb + aoff + ks * 32);
    __syncthreads();   // ZH region now dead -> reusable as staging

    const uint2* Wg = g_wgate + (chalf * 8) * 32 + lane;
    unsigned short* st = (unsigned short*)sm;
    float P[8][4], G[8][4];

    // branch a (Wpa=0, Wga=1)
    wg_glob1(aH, Wg + 0 * 4096, P);
    wg_glob1(aH, Wg + 1 * 4096, G);
    store_hi_staged(P, G, bpa, bga, mask, st, g_ah, r0, rg, chalf, lane, tid);

    // branch b (Wpb=2, Wgb=3)
    wg_glob1(aH, Wg + 2 * 4096, P);
    wg_glob1(aH, Wg + 3 * 4096, G);
    store_hi_staged(P, G, bpb, bgb, mask, st, g_bh, r0, rg, chalf, lane, tid);

    // gate_o (Wgo=4) -> stage row-major -> coalesced STG.128
    wg_glob1(aH, Wg + 4 * 4096, P);
    {
        int q = lane >> 2, m = lane & 3;
        int rl1 = rg * 16 + q, rl2 = rl1 + 8;
#pragma unroll
        for (int t = 0; t < 8; t++) {
            int cc = chalf * 64 + t * 8 + 2 * m;
            float b0 = __ldg(bgo + cc), b1 = __ldg(bgo + cc + 1);
            *(uint32_t*)(st + rl1 * 136 + cc) = pack2hf(sigmf(P[t][0] + b0), sigmf(P[t][1] + b1));
            *(uint32_t*)(st + rl2 * 136 + cc) = pack2hf(sigmf(P[t][2] + b0), sigmf(P[t][3] + b1));
        }
        __syncthreads();
#pragma unroll
        for (int it = 0; it < 4; it++) {
            int f = tid + it * 256;
            int r = f >> 4, u = (f & 15) * 8;
            uint4 v = *(uint4*)&st[r * 136 + u];
            *(uint4*)(g_gate + (size_t)(r0 + r) * C + u) = v;
        }
    }
}

// ===================== Stage 3: contraction, 64-row chunks, double-buffered ==========
#define CH_BUF 34816
#define CSM_TOT 69632

__global__ void __launch_bounds__(256, 2) k_contract(const float* __restrict__ mask) {
    extern __shared__ char sm[];
    uint32_t sb = smem_u32(sm);
    int tid = threadIdx.x, w = tid >> 5, lane = tid & 31;
    int blk = blockIdx.x;
    int bj = blk % 3, bi = (blk / 3) % 3, ch = blk / 9;
    int ibase = bi * 128, jbase = bj * 128;
    const unsigned short* s0 = g_bh + (size_t)ch * NN + ibase;  // A operand (i-axis)
    const unsigned short* s1 = g_ah + (size_t)ch * NN + jbase;  // B operand (j-axis)
    int ig = w & 3, jg = w >> 2;

    float acc[2][8][4];
#pragma unroll
    for (int r = 0; r < 2; r++)
#pragma unroll
        for (int t = 0; t < 8; t++)
#pragma unroll
            for (int e = 0; e < 4; e++) acc[r][t][e] = 0.f;

    int kl = (lane & 7) + (lane >> 4) * 8;
    int cbit = ((lane >> 3) & 1) * 8;
    uint32_t aoff0 = (uint32_t)((kl * 136 + ig * 32 + cbit) * 2);
    uint32_t aoff1 = aoff0 + 32;
    uint32_t boff = (uint32_t)((kl * 136 + jg * 64 + cbit) * 2);

#define LOAD_CHUNK(k0, bufb) do {                                              \
        _Pragma("unroll")                                                      \
        for (int it = 0; it < 8; it++) {                                       \
            int t2 = tid + it * 256;                                           \
            int p = t2 >> 10, rem = t2 & 1023;                                 \
            int r = rem >> 4, s = rem & 15;                                    \
            const unsigned short* sp = (p == 0) ? s0 : s1;                     \
            cp16((bufb) + p * 17408 + r * 272 + s * 16,                        \
                 sp + (size_t)((k0) + r) * NDIM + s * 8);                      \
        }                                                                      \
        CP_COMMIT();                                                           \
    } while (0)

    LOAD_CHUNK(0,  sb);
    LOAD_CHUNK(64, sb + CH_BUF);

    for (int c = 0; c < 6; c++) {
        if (c < 5) asm volatile("cp.async.wait_group 1;" ::: "memory");
        else       asm volatile("cp.async.wait_group 0;" ::: "memory");
        __syncthreads();
        uint32_t bufb = sb + (c & 1) * CH_BUF;
#pragma unroll
        for (int ks = 0; ks < 4; ks++) {
            uint32_t A0[4], A1[4];
            ldsm4t(A0, bufb + aoff0 + ks * 4352);
            ldsm4t(A1, bufb + aoff1 + ks * 4352);
#pragma unroll
            for (int g = 0; g < 4; g++) {
                uint32_t bH[4];
                ldsm4t(bH, bufb + 17408 + boff + g * 32 + ks * 4352);
                mma16816(acc[0][2 * g],     A0, bH[0], bH[2]);
                mma16816(acc[0][2 * g + 1], A0, bH[1], bH[3]);
                mma16816(acc[1][2 * g],     A1, bH[0], bH[2]);
                mma16816(acc[1][2 * g + 1], A1, bH[1], bH[3]);
            }
        }
        __syncthreads();
        if (c + 2 < 6) LOAD_CHUNK((c + 2) * 64, sb + (c & 1) * CH_BUF);
    }
#undef LOAD_CHUNK

    float* stg = (float*)sm;
    {
        int q = lane >> 2, m = lane & 3;
#pragma unroll
        for (int r = 0; r < 2; r++)
#pragma unroll
            for (int t = 0; t < 8; t++) {
                int row1 = ig * 32 + r * 16 + q, row2 = row1 + 8;
                int col = jg * 64 + (t >> 1) * 16 + (t & 1) * 8 + 2 * m;
                stg[row1 * 132 + col]     = acc[r][t][0];
                stg[row1 * 132 + col + 1] = acc[r][t][1];
                stg[row2 * 132 + col]     = acc[r][t][2];
                stg[row2 * 132 + col + 1] = acc[r][t][3];
            }
    }
    __syncthreads();
#pragma unroll
    for (int it = 0; it < 8; it++) {
        int idx = (tid + it * 256) * 8;
        int row = idx >> 7, col = idx & 127;
        float4 v0 = *(float4*)(stg + row * 132 + col);
        float4 v1 = *(float4*)(stg + row * 132 + col + 4);
        int igl = ibase + row, jgl = jbase + col;
        const float* mrow = mask + (size_t)igl * NDIM + jgl;
        float4 m0 = *(const float4*)mrow;
        float4 m1 = *(const float4*)(mrow + 4);
        uint4 o;
        o.x = pack2hf(v0.x * m0.x, v0.y * m0.y);
        o.y = pack2hf(v0.z * m0.z, v0.w * m0.w);
        o.z = pack2hf(v1.x * m1.x, v1.y * m1.y);
        o.w = pack2hf(v1.z * m1.z, v1.w * m1.w);
        *(uint4*)(g_ct + (size_t)ch * NN + (size_t)igl * NDIM + jgl) = o;
    }
}

// ===================== Stage 4: 512 threads, 128 rows, 1-pass Wpo =====================
#define KO_ZH  34816
#define KO_TOT 69632

__global__ void __launch_bounds__(512, 1) k_out(
    const float* __restrict__ lnw, const float* __restrict__ lnb,
    const float* __restrict__ bo, float* __restrict__ out)
{
    extern __shared__ char sm[];
    uint32_t sb = smem_u32(sm);
    int tid = threadIdx.x, w = tid >> 5, lane = tid & 31;
    int rg = w & 7, chalf = w >> 3;
    int r0 = blockIdx.x * 128;
    uint32_t* stg = (uint32_t*)sm;    // [row][slot] row stride 68 words

    // transposed fp16 load: warp = channel pair, lanes = row quads
#pragma unroll
    for (int it = 0; it < 4; it++) {
        int cpair = w + it * 16;
        const unsigned short* p0 = g_ct + (size_t)(2 * cpair) * NN + r0 + lane * 4;
        uint2 u0 = *(const uint2*)p0;
        uint2 u1 = *(const uint2*)(p0 + NN);
        int r = lane * 4;
        int slot = (cpair + lane) & 63;
        stg[(r + 0) * 68 + slot] = __byte_perm(u0.x, u1.x, 0x5410);
        stg[(r + 1) * 68 + slot] = __byte_perm(u0.x, u1.x, 0x7632);
        stg[(r + 2) * 68 + slot] = __byte_perm(u0.y, u1.y, 0x5410);
        stg[(r + 3) * 68 + slot] = __byte_perm(u0.y, u1.y, 0x7632);
    }
    __syncthreads();

    // LayerNorm: warp handles 8 rows; lane reads slots 2p, 2p+1
    {
        float2 lw0, lb0, lw1, lb1;
        int cp0 = 0, cp1 = 0;
#pragma unroll
        for (int rr = 0; rr < 8; rr++) {
            int row = w * 8 + rr;
            int k = row >> 2;
            if (rr == 0 || rr == 4) {
                cp0 = (2 * lane - k) & 63;
                cp1 = (2 * lane + 1 - k) & 63;
                lw0 = *(const float2*)(lnw + 2 * cp0); lb0 = *(const float2*)(lnb + 2 * cp0);
                lw1 = *(const float2*)(lnw + 2 * cp1); lb1 = *(const float2*)(lnb + 2 * cp1);
            }
            uint2 d = *(uint2*)&stg[row * 68 + 2 * lane];
            __half2 ha = *(__half2*)&d.x;
            __half2 hb = *(__half2*)&d.y;
            float f0 = __low2float(ha), f1 = __high2float(ha);
            float f2 = __low2float(hb), f3 = __high2float(hb);
            float s1 = f0 + f1 + f2 + f3;
            float s2 = f0 * f0 + f1 * f1 + f2 * f2 + f3 * f3;
#pragma unroll
            for (int o = 16; o; o >>= 1) {
                s1 += __shfl_xor_sync(0xffffffffu, s1, o);
                s2 += __shfl_xor_sync(0xffffffffu, s2, o);
            }
            float mn = s1 * (1.f / 128.f);
            float var = fmaxf(s2 * (1.f / 128.f) - mn * mn, 0.f);
            float rs = rsqrtf(var + EPS);
            float n0 = (f0 - mn) * rs * lw0.x + lb0.x;
            float n1 = (f1 - mn) * rs * lw0.y + lb0.y;
            float n2 = (f2 - mn) * rs * lw1.x + lb1.x;
            float n3 = (f3 - mn) * rs * lw1.y + lb1.y;
            *(uint32_t*)(sm + KO_ZH + row * 272 + 4 * cp0) = pack2hf(n0, n1);
            *(uint32_t*)(sm + KO_ZH + row * 272 + 4 * cp1) = pack2hf(n2, n3);
        }
    }
    __syncthreads();

    uint32_t aoff = (uint32_t)(((rg * 16 + (lane & 15)) * 136 + (lane >> 4) * 8) * 2);
    uint32_t aH[8][4];
#pragma unroll
    for (int ks = 0; ks < 8; ks++) ldsm4(aH[ks], sb + KO_ZH + aoff + ks * 32);

    float P[8][4];
    wg_glob1(aH, g_wgate + 5 * 4096 + (chalf * 8) * 32 + lane, P);

    // epilogue: bias + fp16 gate, float2 stores
    {
        int q = lane >> 2, m = lane & 3;
        int r1 = r0 + rg * 16 + q, r2 = r1 + 8;
#pragma unroll
        for (int t = 0; t < 8; t++) {
            int cc = chalf * 64 + t * 8 + 2 * m;
            float b0 = __ldg(bo + cc), b1 = __ldg(bo + cc + 1);
            uint32_t gb1 = *(const uint32_t*)(g_gate + (size_t)r1 * C + cc);
            uint32_t gb2 = *(const uint32_t*)(g_gate + (size_t)r2 * C + cc);
            __half2 gh1 = *(__half2*)&gb1;
            __half2 gh2 = *(__half2*)&gb2;
            float2 o1, o2;
            o1.x = (P[t][0] + b0) * __low2float(gh1);
            o1.y = (P[t][1] + b1) * __high2float(gh1);
            o2.x = (P[t][2] + b0) * __low2float(gh2);
            o2.y = (P[t][3] + b1) * __high2float(gh2);
            *(float2*)(out + (size_t)r1 * C + cc) = o1;
            *(float2*)(out + (size_t)r2 * C + cc) = o2;
        }
    }
}

extern "C" void kernel_launch(void* const* d_in, const int* in_sizes, int n_in,
                              void* d_out, int out_size) {
    const float* z    = (const float*)d_in[0];
    const float* mask = (const float*)d_in[1];
    const float* lniw = (const float*)d_in[2];
    const float* lnib = (const float*)d_in[3];
    const float* lnow = (const float*)d_in[4];
    const float* lnob = (const float*)d_in[5];
    const float* Wpa  = (const float*)d_in[6];
    const float* bpa  = (const float*)d_in[7];
    const float* Wga  = (const float*)d_in[8];
    const float* bga  = (const float*)d_in[9];
    const float* Wpb  = (const float*)d_in[10];
    const float* bpb  = (const float*)d_in[11];
    const float* Wgb  = (const float*)d_in[12];
    const float* bgb  = (const float*)d_in[13];
    const float* Wgo  = (const float*)d_in[14];
    const float* bgo  = (const float*)d_in[15];
    const float* Wpo  = (const float*)d_in[16];
    const float* bpo  = (const float*)d_in[17];
    float* out = (float*)d_out;

    cudaFuncSetAttribute(k_contract, cudaFuncAttributeMaxDynamicSharedMemorySize, CSM_TOT);
    cudaFuncSetAttribute(k_out, cudaFuncAttributeMaxDynamicSharedMemorySize, KO_TOT);

    k_prep<<<96, 256>>>(Wpa, Wga, Wpb, Wgb, Wgo, Wpo);
    k_lin5<<<NN / 64, 256, L5_TOT>>>(z, mask, lniw, lnib, bpa, bga, bpb, bgb, bgo);
    k_contract<<<9 * C, 256, CSM_TOT>>>(mask);
    k_out<<<NN / 128, 512, KO_TOT>>>(lnow, lnob, bpo, out);
}